// round 4
// baseline (speedup 1.0000x reference)
#include <cuda_runtime.h>
#include <cuda_fp16.h>
#include <math.h>
#include <cstdint>

#define J 4
#define BATCH 8192
#define TIN 10
#define TOUT 10
#define HDIM 100
#define VDIM 11
#define JB (J*BATCH)

#define NWARP 12
#define NTHREADS (NWARP*32)

typedef unsigned long long u64;

// ---------------- global scratch (allocation-free) ----------------
__device__ float g_H [(size_t)JB*TIN*HDIM];   // [b][j][t][e]
__device__ float g_HA[(size_t)JB*TIN*HDIM];   // [b][j][t][f]

// ---------------- packed f32x2 helpers ----------------
__device__ __forceinline__ void fma2(u64 &d, u64 a, u64 b){
    asm("fma.rn.f32x2 %0, %1, %2, %0;" : "+l"(d) : "l"(a), "l"(b));
}
__device__ __forceinline__ u64 dup2(float x){
    u64 r; asm("mov.b64 %0, {%1, %1};" : "=l"(r) : "f"(x)); return r;
}
__device__ __forceinline__ u64 pack2(float x, float y){
    u64 r; asm("mov.b64 %0, {%1, %2};" : "=l"(r) : "f"(x), "f"(y)); return r;
}
__device__ __forceinline__ float2 unpack2(u64 v){
    float2 f; asm("mov.b64 {%0, %1}, %2;" : "=f"(f.x), "=f"(f.y) : "l"(v)); return f;
}
__device__ __forceinline__ float sigm(float x){ return __fdividef(1.f, 1.f+__expf(-x)); }
__device__ __forceinline__ float tanh_f(float x){
    return fmaf(2.f, __fdividef(1.f, 1.f+__expf(-2.f*x)), -1.f);
}

// ---------------- shared memory layout (float offsets) ----------------
// encoder phase
#define E_WHH 0        // WhhT [100][300]
#define E_WIH 30000    // WihT [11][300]
#define E_AW  33300    // A_w  [100][100]
#define E_BIH 43300
#define E_BHH 43600
#define E_H   43900    // h [12][4][100]
// decoder phase (reuses same smem after __syncthreads)
#define D_WHH 0        // WhhT [100][300]
#define D_WIH 30000    // WihT [11][300]
#define D_VW  33300    // V_w [11][100]
#define D_BIH 34400
#define D_BHH 34700
#define D_WB  35000
#define D_VB  35100    // 12 slots (pad)
#define D_PC  35112    // [12][4][200]  P|c
#define D_SC  44712    // [12][40]
#define D_WW2 45192    // half2 [200][50]
#define SM_FLOATS 55192  // 220768 bytes

// =================================================================
// packed decoder GRU: P[j] = GRU(onehot(tok), c[j]); c in pc[+100], P out pc[+0]
// =================================================================
__device__ __forceinline__ void dec_gru(const float* __restrict__ sm,
                                        float* __restrict__ pc,
                                        int lane, int tok)
{
    const int e0 = 2*lane, e1 = 64 + 2*lane;
    const bool m1 = (lane < 18);
    u64 gr[J][2], gz[J][2], gn[J][2];
    {
        u64 br0=*(const u64*)&sm[D_BHH+e0], bz0=*(const u64*)&sm[D_BHH+100+e0], bn0=*(const u64*)&sm[D_BHH+200+e0];
        u64 br1=0, bz1=0, bn1=0;
        if (m1){ br1=*(const u64*)&sm[D_BHH+e1]; bz1=*(const u64*)&sm[D_BHH+100+e1]; bn1=*(const u64*)&sm[D_BHH+200+e1]; }
        #pragma unroll
        for(int j=0;j<J;j++){ gr[j][0]=br0; gz[j][0]=bz0; gn[j][0]=bn0;
                              gr[j][1]=br1; gz[j][1]=bz1; gn[j][1]=bn1; }
    }
    #pragma unroll 2
    for (int k=0;k<HDIM;k+=2){
        float2 cc[J];
        #pragma unroll
        for(int j=0;j<J;j++) cc[j] = *(const float2*)&pc[j*200+100+k];
        #pragma unroll
        for (int s=0;s<2;s++){
            const float* wrow = &sm[D_WHH + (k+s)*300];
            u64 cb[J];
            #pragma unroll
            for(int j=0;j<J;j++) cb[j] = dup2(s? cc[j].y : cc[j].x);
            u64 wr0=*(const u64*)(wrow+e0), wz0=*(const u64*)(wrow+100+e0), wn0=*(const u64*)(wrow+200+e0);
            #pragma unroll
            for(int j=0;j<J;j++){ fma2(gr[j][0],wr0,cb[j]); fma2(gz[j][0],wz0,cb[j]); fma2(gn[j][0],wn0,cb[j]); }
            if (m1){
                u64 wr1=*(const u64*)(wrow+e1), wz1=*(const u64*)(wrow+100+e1), wn1=*(const u64*)(wrow+200+e1);
                #pragma unroll
                for(int j=0;j<J;j++){ fma2(gr[j][1],wr1,cb[j]); fma2(gz[j][1],wz1,cb[j]); fma2(gn[j][1],wn1,cb[j]); }
            }
        }
    }
    const float* wi = &sm[D_WIH + tok*300];
    #pragma unroll
    for (int m=0;m<2;m++){
        if (m==1 && !m1) break;
        const int e = m? e1 : e0;
        float2 b_r=*(const float2*)&sm[D_BIH+e];
        float2 b_z=*(const float2*)&sm[D_BIH+100+e];
        float2 b_n=*(const float2*)&sm[D_BIH+200+e];
        float2 wir=*(const float2*)&wi[e], wiz=*(const float2*)&wi[100+e], win=*(const float2*)&wi[200+e];
        float ir0=wir.x+b_r.x, ir1=wir.y+b_r.y;
        float iz0=wiz.x+b_z.x, iz1=wiz.y+b_z.y;
        float in0=win.x+b_n.x, in1=win.y+b_n.y;
        #pragma unroll
        for(int j=0;j<J;j++){
            float2 R=unpack2(gr[j][m]), Z=unpack2(gz[j][m]), N=unpack2(gn[j][m]);
            float2 cj=*(const float2*)&pc[j*200+100+e];
            float r0=sigm(ir0+R.x), z0=sigm(iz0+Z.x);
            float n0=tanh_f(in0 + r0*N.x);
            float r1=sigm(ir1+R.y), z1=sigm(iz1+Z.y);
            float n1=tanh_f(in1 + r1*N.y);
            float2 pn; pn.x=(1.f-z0)*n0 + z0*cj.x; pn.y=(1.f-z1)*n1 + z1*cj.y;
            *(float2*)&pc[j*200+e] = pn;
        }
    }
    __syncwarp();
}

// =================================================================
__global__ void __launch_bounds__(NTHREADS,1)
fused_kernel(const int* __restrict__ inputs, const int* __restrict__ target,
             const float* __restrict__ eWih, const float* __restrict__ eWhh,
             const float* __restrict__ ebih, const float* __restrict__ ebhh,
             const float* __restrict__ dWih, const float* __restrict__ dWhh,
             const float* __restrict__ dbih, const float* __restrict__ dbhh,
             const float* __restrict__ Ww,  const float* __restrict__ Wb,
             const float* __restrict__ Vw,  const float* __restrict__ Vb,
             const float* __restrict__ Aw,  float* __restrict__ out)
{
    extern __shared__ float sm[];
    const int tid = threadIdx.x;
    const int warp = tid>>5, lane = tid&31;
    const int b = min(blockIdx.x*NWARP + warp, BATCH-1);
    const int e0 = 2*lane, e1 = 64 + 2*lane;
    const bool m1 = (lane < 18);

    // ================= ENCODER PHASE =================
    for (int i=tid;i<300*100;i+=NTHREADS){ int g=i/100,k=i%100; sm[E_WHH+k*300+g]=eWhh[i]; }
    for (int i=tid;i<300*11; i+=NTHREADS){ int g=i/11, v=i%11;  sm[E_WIH+v*300+g]=eWih[i]; }
    for (int i=tid;i<100*100;i+=NTHREADS) sm[E_AW+i]=Aw[i];
    for (int i=tid;i<300;    i+=NTHREADS){ sm[E_BIH+i]=ebih[i]; sm[E_BHH+i]=ebhh[i]; }
    __syncthreads();

    {
        float* hrow[J];
        #pragma unroll
        for(int j=0;j<J;j++) hrow[j]=&sm[E_H + (warp*J+j)*HDIM];
        float2 z2; z2.x=0.f; z2.y=0.f;
        #pragma unroll
        for(int j=0;j<J;j++){ *(float2*)&hrow[j][e0]=z2; if(m1) *(float2*)&hrow[j][e1]=z2; }
        __syncwarp();

        #pragma unroll 1
        for (int t=0;t<TIN;t++){
            int tok[J];
            #pragma unroll
            for(int j=0;j<J;j++) tok[j]=inputs[(j*TIN+t)*BATCH + b];

            u64 ar[J][2], az[J][2], an[J][2];
            {
                u64 br0=*(const u64*)&sm[E_BHH+e0], bz0=*(const u64*)&sm[E_BHH+100+e0], bn0=*(const u64*)&sm[E_BHH+200+e0];
                u64 br1=0,bz1=0,bn1=0;
                if(m1){ br1=*(const u64*)&sm[E_BHH+e1]; bz1=*(const u64*)&sm[E_BHH+100+e1]; bn1=*(const u64*)&sm[E_BHH+200+e1]; }
                #pragma unroll
                for(int j=0;j<J;j++){ ar[j][0]=br0; az[j][0]=bz0; an[j][0]=bn0;
                                      ar[j][1]=br1; az[j][1]=bz1; an[j][1]=bn1; }
            }
            if (t>0){   // at t==0, h==0 -> Whh@h == 0
                #pragma unroll 2
                for (int k=0;k<HDIM;k+=2){
                    float2 hk[J];
                    #pragma unroll
                    for(int j=0;j<J;j++) hk[j]=*(const float2*)&hrow[j][k];
                    #pragma unroll
                    for (int s=0;s<2;s++){
                        const float* wrow=&sm[E_WHH+(k+s)*300];
                        u64 hb[J];
                        #pragma unroll
                        for(int j=0;j<J;j++) hb[j]=dup2(s?hk[j].y:hk[j].x);
                        u64 wr0=*(const u64*)(wrow+e0), wz0=*(const u64*)(wrow+100+e0), wn0=*(const u64*)(wrow+200+e0);
                        #pragma unroll
                        for(int j=0;j<J;j++){ fma2(ar[j][0],wr0,hb[j]); fma2(az[j][0],wz0,hb[j]); fma2(an[j][0],wn0,hb[j]); }
                        if(m1){
                            u64 wr1=*(const u64*)(wrow+e1), wz1=*(const u64*)(wrow+100+e1), wn1=*(const u64*)(wrow+200+e1);
                            #pragma unroll
                            for(int j=0;j<J;j++){ fma2(ar[j][1],wr1,hb[j]); fma2(az[j][1],wz1,hb[j]); fma2(an[j][1],wn1,hb[j]); }
                        }
                    }
                }
            }
            // gates + h update + store H
            #pragma unroll
            for (int m=0;m<2;m++){
                if (m==1 && !m1) break;
                const int e = m? e1 : e0;
                float2 b_r=*(const float2*)&sm[E_BIH+e];
                float2 b_z=*(const float2*)&sm[E_BIH+100+e];
                float2 b_n=*(const float2*)&sm[E_BIH+200+e];
                #pragma unroll
                for(int j=0;j<J;j++){
                    const float* wi=&sm[E_WIH+tok[j]*300];
                    float2 wir=*(const float2*)&wi[e], wiz=*(const float2*)&wi[100+e], win=*(const float2*)&wi[200+e];
                    float2 R=unpack2(ar[j][m]), Z=unpack2(az[j][m]), N=unpack2(an[j][m]);
                    float2 ho=*(const float2*)&hrow[j][e];
                    float r0=sigm(wir.x+b_r.x+R.x), z0=sigm(wiz.x+b_z.x+Z.x);
                    float n0=tanh_f(win.x+b_n.x + r0*N.x);
                    float r1=sigm(wir.y+b_r.y+R.y), z1=sigm(wiz.y+b_z.y+Z.y);
                    float n1=tanh_f(win.y+b_n.y + r1*N.y);
                    float2 hn; hn.x=(1.f-z0)*n0+z0*ho.x; hn.y=(1.f-z1)*n1+z1*ho.y;
                    *(float2*)&hrow[j][e]=hn;
                    *(float2*)&g_H[((size_t)(b*J+j)*TIN+t)*HDIM + e]=hn;
                }
            }
            __syncwarp();
            // HA = h @ A_w
            u64 ha[J][2];
            #pragma unroll
            for(int j=0;j<J;j++){ ha[j][0]=0ull; ha[j][1]=0ull; }
            #pragma unroll 2
            for (int e=0;e<HDIM;e+=2){
                float2 he[J];
                #pragma unroll
                for(int j=0;j<J;j++) he[j]=*(const float2*)&hrow[j][e];
                #pragma unroll
                for (int s=0;s<2;s++){
                    const float* arow=&sm[E_AW+(e+s)*100];
                    u64 hb[J];
                    #pragma unroll
                    for(int j=0;j<J;j++) hb[j]=dup2(s?he[j].y:he[j].x);
                    u64 a0=*(const u64*)(arow+e0);
                    #pragma unroll
                    for(int j=0;j<J;j++) fma2(ha[j][0],a0,hb[j]);
                    if(m1){
                        u64 a1=*(const u64*)(arow+e1);
                        #pragma unroll
                        for(int j=0;j<J;j++) fma2(ha[j][1],a1,hb[j]);
                    }
                }
            }
            #pragma unroll
            for(int j=0;j<J;j++){
                *(float2*)&g_HA[((size_t)(b*J+j)*TIN+t)*HDIM + e0]=unpack2(ha[j][0]);
                if(m1) *(float2*)&g_HA[((size_t)(b*J+j)*TIN+t)*HDIM + e1]=unpack2(ha[j][1]);
            }
            __syncwarp();
        }
    }
    __syncthreads();

    // ================= DECODER PHASE =================
    for (int i=tid;i<300*100;i+=NTHREADS){ int g=i/100,k=i%100; sm[D_WHH+k*300+g]=dWhh[i]; }
    for (int i=tid;i<300*11; i+=NTHREADS){ int g=i/11, v=i%11;  sm[D_WIH+v*300+g]=dWih[i]; }
    for (int i=tid;i<11*100; i+=NTHREADS) sm[D_VW+i]=Vw[i];
    for (int i=tid;i<300;    i+=NTHREADS){ sm[D_BIH+i]=dbih[i]; sm[D_BHH+i]=dbhh[i]; }
    for (int i=tid;i<100;    i+=NTHREADS) sm[D_WB+i]=Wb[i];
    for (int i=tid;i<VDIM;   i+=NTHREADS) sm[D_VB+i]=Vb[i];
    {
        __half2* w2=(__half2*)&sm[D_WW2];
        for (int i=tid;i<200*50;i+=NTHREADS){
            int k=i/50, p=i%50; int ee=2*p;
            w2[k*50+p]=__halves2half2(__float2half(Ww[ee*200+k]), __float2half(Ww[(ee+1)*200+k]));
        }
    }
    __syncthreads();

    float* pc=&sm[D_PC + warp*800];
    float* sc=&sm[D_SC + warp*40];
    const __half2* w2=(const __half2*)&sm[D_WW2];

    // init: c = H[:, t=9]; P0 = GRU(SOS, c)
    #pragma unroll
    for(int j=0;j<J;j++){
        *(float2*)&pc[j*200+100+e0]=*(const float2*)&g_H[((size_t)(b*J+j)*TIN+(TIN-1))*HDIM+e0];
        if(m1) *(float2*)&pc[j*200+100+e1]=*(const float2*)&g_H[((size_t)(b*J+j)*TIN+(TIN-1))*HDIM+e1];
    }
    __syncwarp();
    dec_gru(sm, pc, lane, VDIM-1);

    float score=0.f;
    #pragma unroll 1
    for (int t=0;t<TOUT;t++){
        // ---- A: scores[j][tt] = HA[j][tt] . P[j] ----
        {
            int j=lane/10, tt=lane-10*j;
            const u64* hap=(const u64*)&g_HA[((size_t)(b*J+j)*TIN+tt)*HDIM];
            const u64* pj =(const u64*)&pc[j*200];
            u64 acc=0ull;
            #pragma unroll 10
            for(int q=0;q<50;q++) fma2(acc,hap[q],pj[q]);
            float2 f=unpack2(acc); sc[lane]=f.x+f.y;
            if (lane<8){
                int t2=32+lane; int j2=t2/10, tt2=t2-10*j2;
                const u64* hap2=(const u64*)&g_HA[((size_t)(b*J+j2)*TIN+tt2)*HDIM];
                const u64* pj2 =(const u64*)&pc[j2*200];
                u64 acc2=0ull;
                #pragma unroll 10
                for(int q=0;q<50;q++) fma2(acc2,hap2[q],pj2[q]);
                float2 f2=unpack2(acc2); sc[t2]=f2.x+f2.y;
            }
        }
        __syncwarp();
        // ---- B: log_softmax over tt ----
        if (lane<J){
            float mx=-1e30f;
            #pragma unroll
            for(int tt=0;tt<TIN;tt++) mx=fmaxf(mx,sc[lane*10+tt]);
            float s=0.f;
            #pragma unroll
            for(int tt=0;tt<TIN;tt++) s+=__expf(sc[lane*10+tt]-mx);
            float lg=__logf(s)+mx;
            #pragma unroll
            for(int tt=0;tt<TIN;tt++) sc[lane*10+tt]-=lg;
        }
        __syncwarp();
        // ---- C: c[j] = sum_tt logs * H ----
        {
            u64 cacc[J][2];
            #pragma unroll
            for(int j=0;j<J;j++){ cacc[j][0]=0ull; cacc[j][1]=0ull; }
            #pragma unroll
            for(int j=0;j<J;j++){
                const float* hb=&g_H[((size_t)(b*J+j)*TIN)*HDIM];
                #pragma unroll
                for(int tt=0;tt<TIN;tt++){
                    u64 lg2=dup2(sc[j*10+tt]);
                    const float* hp=hb+tt*HDIM;
                    fma2(cacc[j][0], *(const u64*)(hp+e0), lg2);
                    if(m1) fma2(cacc[j][1], *(const u64*)(hp+e1), lg2);
                }
            }
            #pragma unroll
            for(int j=0;j<J;j++){
                *(float2*)&pc[j*200+100+e0]=unpack2(cacc[j][0]);
                if(m1) *(float2*)&pc[j*200+100+e1]=unpack2(cacc[j][1]);
            }
        }
        __syncwarp();
        // ---- D: fc = tanh(W_w @ [P|c] + W_b), max over j ----
        u64 accA[J], accB[J];
        {
            float2 wbA=*(const float2*)&sm[D_WB+e0];
            u64 a0=pack2(wbA.x,wbA.y);
            u64 b0=0ull;
            if(m1){ float2 wbB=*(const float2*)&sm[D_WB+e1]; b0=pack2(wbB.x,wbB.y); }
            #pragma unroll
            for(int j=0;j<J;j++){ accA[j]=a0; accB[j]=b0; }
        }
        #pragma unroll 2
        for (int k=0;k<200;k+=2){
            float2 pa[J];
            #pragma unroll
            for(int j=0;j<J;j++) pa[j]=*(const float2*)&pc[j*200+k];
            #pragma unroll
            for (int s=0;s<2;s++){
                int kk=k+s;
                float2 wAf=__half22float2(w2[kk*50+lane]);
                u64 wA=pack2(wAf.x,wAf.y);
                u64 pb[J];
                #pragma unroll
                for(int j=0;j<J;j++) pb[j]=dup2(s?pa[j].y:pa[j].x);
                #pragma unroll
                for(int j=0;j<J;j++) fma2(accA[j],wA,pb[j]);
                if(m1){
                    float2 wBf=__half22float2(w2[kk*50+32+lane]);
                    u64 wB=pack2(wBf.x,wBf.y);
                    #pragma unroll
                    for(int j=0;j<J;j++) fma2(accB[j],wB,pb[j]);
                }
            }
        }
        float2 mA; mA.x=-1e30f; mA.y=-1e30f;
        float2 mB=mA;
        #pragma unroll
        for(int j=0;j<J;j++){
            float2 fA=unpack2(accA[j]);
            mA.x=fmaxf(mA.x,tanh_f(fA.x)); mA.y=fmaxf(mA.y,tanh_f(fA.y));
            if(m1){ float2 fB=unpack2(accB[j]);
                mB.x=fmaxf(mB.x,tanh_f(fB.x)); mB.y=fmaxf(mB.y,tanh_f(fB.y)); }
        }
        // ---- E: logits + log_softmax + score ----
        float pv[VDIM];
        #pragma unroll
        for(int v=0;v<VDIM;v++){
            const float* vr=&sm[D_VW+v*HDIM];
            float2 vA=*(const float2*)&vr[e0];
            float p=vA.x*mA.x + vA.y*mA.y;
            if(m1){ float2 vB=*(const float2*)&vr[e1]; p=fmaf(vB.x,mB.x,p); p=fmaf(vB.y,mB.y,p); }
            pv[v]=p;
        }
        #pragma unroll
        for (int off=16; off>=1; off>>=1){
            #pragma unroll
            for(int v=0;v<VDIM;v++) pv[v]+=__shfl_xor_sync(0xffffffffu,pv[v],off);
        }
        int tok=target[t*BATCH+b];
        float mx=-1e30f;
        #pragma unroll
        for(int v=0;v<VDIM;v++){ pv[v]+=sm[D_VB+v]; mx=fmaxf(mx,pv[v]); }
        float ssum=0.f;
        #pragma unroll
        for(int v=0;v<VDIM;v++) ssum+=__expf(pv[v]-mx);
        score += pv[tok]-mx-__logf(ssum);
        // ---- F: P = GRU(onehot(tok), c) ----
        dec_gru(sm, pc, lane, tok);
    }
    if (lane==0) out[b]=score;
}

// =================================================================
extern "C" void kernel_launch(void* const* d_in, const int* in_sizes, int n_in,
                              void* d_out, int out_size)
{
    const int*   inputs = (const int*)  d_in[0];
    const int*   target = (const int*)  d_in[1];
    const float* eWih   = (const float*)d_in[2];
    const float* eWhh   = (const float*)d_in[3];
    const float* ebih   = (const float*)d_in[4];
    const float* ebhh   = (const float*)d_in[5];
    const float* dWih   = (const float*)d_in[6];
    const float* dWhh   = (const float*)d_in[7];
    const float* dbih   = (const float*)d_in[8];
    const float* dbhh   = (const float*)d_in[9];
    const float* Ww     = (const float*)d_in[10];
    const float* Wb     = (const float*)d_in[11];
    const float* Vw     = (const float*)d_in[12];
    const float* Vb     = (const float*)d_in[13];
    const float* Aw     = (const float*)d_in[14];
    float* out = (float*)d_out;

    cudaFuncSetAttribute(fused_kernel, cudaFuncAttributeMaxDynamicSharedMemorySize, SM_FLOATS*4);
    int grid = (BATCH + NWARP - 1)/NWARP;  // 683
    fused_kernel<<<grid, NTHREADS, SM_FLOATS*4>>>(inputs, target,
        eWih, eWhh, ebih, ebhh, dWih, dWhh, dbih, dbhh,
        Ww, Wb, Vw, Vb, Aw, out);
}

// round 5
// speedup vs baseline: 1.3016x; 1.3016x over previous
#include <cuda_runtime.h>
#include <cuda_fp16.h>
#include <cstdint>

#define J 4
#define BATCH 8192
#define TIN 10
#define TOUT 10
#define HDIM 100
#define VDIM 11
#define NWARP 12
#define NTHREADS 384
#define MROWS 48
typedef unsigned long long u64;
typedef uint32_t u32;

#define FCA 244
#define WST 116
#define GSZ (104*WST)
#define WWBST 228
#define WIHST 304

// smem byte offsets
#define OFF_WHH   0        // 3*104*116*2
#define OFF_WB2   72384    // 104*228*2 (dec fc B / enc AwT uses WST)
#define OFF_WIH   119808   // 11*304*2
#define OFF_VW    126496   // 11*104*4 f32
#define OFF_BIH   131072   // 304*4
#define OFF_BHH   132288
#define OFF_BSUM  133504
#define OFF_WBB   134720   // 104*4
#define OFF_VB    135136   // 16*4
#define OFF_FCAB  135200   // 48*244*2
#define OFF_HM    158624   // 48*104*4
#define OFF_P32   178592   // 48*104*4
#define OFF_BUF1  198560   // 48*104*2
#define OFF_BUF2  208544
#define OFF_SC    218528   // 12*40*4
#define OFF_TOK   220448   // 48*4
#define SMEM_BYTES 220640

__device__ float g_H [(size_t)J*BATCH*TIN*HDIM];
__device__ float g_HA[(size_t)J*BATCH*TIN*HDIM];

__device__ __forceinline__ void fma2(u64 &d, u64 a, u64 b){
    asm("fma.rn.f32x2 %0, %1, %2, %0;" : "+l"(d) : "l"(a), "l"(b));
}
__device__ __forceinline__ u64 dup2(float x){ u64 r; asm("mov.b64 %0, {%1, %1};" : "=l"(r) : "f"(x)); return r; }
__device__ __forceinline__ float2 unpack2(u64 v){ float2 f; asm("mov.b64 {%0, %1}, %2;" : "=f"(f.x), "=f"(f.y) : "l"(v)); return f; }
__device__ __forceinline__ float sigm(float x){ return __fdividef(1.f, 1.f+__expf(-x)); }
__device__ __forceinline__ float tanh_f(float x){ return fmaf(2.f, __fdividef(1.f, 1.f+__expf(-2.f*x)), -1.f); }
#define U32LD(p) (*(const u32*)(p))

template<int KT>
__device__ __forceinline__ void gemm_tile(const __half* A, int acol,
        const __half* B, int bst, int mt, int nt, int g, int tig, float d[4])
{
    const __half* Ar = A + (mt*16+g)*FCA + acol + 2*tig;
    const __half* Br = B + (nt*8+g)*bst + 2*tig;
    #pragma unroll
    for (int kt=0; kt<KT; kt++){
        u32 a0=U32LD(Ar), a1=U32LD(Ar+8*FCA), a2=U32LD(Ar+8), a3=U32LD(Ar+8*FCA+8);
        u32 b0=U32LD(Br), b1=U32LD(Br+8);
        asm("mma.sync.aligned.m16n8k16.row.col.f32.f16.f16.f32 "
            "{%0,%1,%2,%3}, {%4,%5,%6,%7}, {%8,%9}, {%0,%1,%2,%3};"
            : "+f"(d[0]),"+f"(d[1]),"+f"(d[2]),"+f"(d[3])
            : "r"(a0),"r"(a1),"r"(a2),"r"(a3), "r"(b0),"r"(b1));
        Ar += 16; Br += 16;
    }
}

// r,z gates -> buf1/buf2 (fp16 sigmoided)
__device__ __forceinline__ void pass_rz(const __half* fcA, int acol,
        const __half* whh, const __half* wih, const float* bsum,
        const int* toks, __half* buf1, __half* buf2, int warp, int g, int tig)
{
    for (int tile=warp; tile<78; tile+=NWARP){
        int gate = (tile>=39)?1:0, r2 = tile-39*gate;
        int mt=r2/13, nt=r2%13;
        float d[4]={0,0,0,0};
        gemm_tile<7>(fcA, acol, whh+gate*GSZ, WST, mt, nt, g, tig, d);
        int c = nt*8+2*tig;
        if (c<100){
            int gc = gate*100+c;
            float2 bs = *(const float2*)&bsum[gc];
            __half* dst = gate? buf2 : buf1;
            #pragma unroll
            for (int h2=0; h2<2; h2++){
                int r = mt*16+g+8*h2;
                float2 w = __half22float2(*(const __half2*)&wih[toks[r]*WIHST+gc]);
                *(__half2*)&dst[r*104+c] =
                    __floats2half2_rn(sigm(d[2*h2]+w.x+bs.x), sigm(d[2*h2+1]+w.y+bs.y));
            }
        }
    }
}

// n gate + state update -> fdst (f32), hcol (fp16 mirror), optional g_H
__device__ __forceinline__ void pass_n(const __half* fcA, int acol,
        const __half* whh, const __half* wih, const float* bih, const float* bhh,
        const int* toks, const __half* buf1, const __half* buf2,
        const float* hm, float* fdst, __half* hcol,
        bool wgh, int t, int blk0, int warp, int g, int tig)
{
    for (int tile=warp; tile<39; tile+=NWARP){
        int mt=tile/13, nt=tile%13;
        float d[4]={0,0,0,0};
        gemm_tile<7>(fcA, acol, whh+2*GSZ, WST, mt, nt, g, tig, d);
        int c = nt*8+2*tig;
        if (c<100){
            int gc = 200+c;
            float2 bi = *(const float2*)&bih[gc];
            float2 bh = *(const float2*)&bhh[gc];
            #pragma unroll
            for (int h2=0; h2<2; h2++){
                int r = mt*16+g+8*h2;
                float2 w  = __half22float2(*(const __half2*)&wih[toks[r]*WIHST+gc]);
                float2 rr = __half22float2(*(const __half2*)&buf1[r*104+c]);
                float2 zz = __half22float2(*(const __half2*)&buf2[r*104+c]);
                float n0 = tanh_f(w.x+bi.x + rr.x*(d[2*h2]  +bh.x));
                float n1 = tanh_f(w.y+bi.y + rr.y*(d[2*h2+1]+bh.y));
                float2 ho = *(const float2*)&hm[r*104+c];
                float2 hn; hn.x=(1.f-zz.x)*n0+zz.x*ho.x; hn.y=(1.f-zz.y)*n1+zz.y*ho.y;
                *(float2*)&fdst[r*104+c] = hn;
                *(__half2*)&hcol[r*FCA+c] = __floats2half2_rn(hn.x,hn.y);
                if (wgh){
                    int bb = min(blk0+(r>>2), BATCH-1);
                    *(float2*)&g_H[((size_t)(bb*J+(r&3))*TIN+t)*HDIM+c] = hn;
                }
            }
        }
    }
}

__global__ void __launch_bounds__(NTHREADS,1)
fused_kernel(const int* __restrict__ inputs, const int* __restrict__ target,
             const float* __restrict__ eWih, const float* __restrict__ eWhh,
             const float* __restrict__ ebih, const float* __restrict__ ebhh,
             const float* __restrict__ dWih, const float* __restrict__ dWhh,
             const float* __restrict__ dbih, const float* __restrict__ dbhh,
             const float* __restrict__ Ww,  const float* __restrict__ Wb,
             const float* __restrict__ Vw,  const float* __restrict__ Vb,
             const float* __restrict__ Aw,  float* __restrict__ out)
{
    extern __shared__ char smx[];
    __half* whh  = (__half*)(smx+OFF_WHH);
    __half* wb2  = (__half*)(smx+OFF_WB2);
    __half* wih  = (__half*)(smx+OFF_WIH);
    float*  vwf  = (float*)(smx+OFF_VW);
    float*  bih  = (float*)(smx+OFF_BIH);
    float*  bhh  = (float*)(smx+OFF_BHH);
    float*  bsum = (float*)(smx+OFF_BSUM);
    float*  wbb  = (float*)(smx+OFF_WBB);
    float*  vbb  = (float*)(smx+OFF_VB);
    __half* fcA  = (__half*)(smx+OFF_FCAB);
    float*  hm   = (float*)(smx+OFF_HM);
    float*  P32  = (float*)(smx+OFF_P32);
    __half* buf1 = (__half*)(smx+OFF_BUF1);
    __half* buf2 = (__half*)(smx+OFF_BUF2);
    float*  scb  = (float*)(smx+OFF_SC);
    int*    toks = (int*)(smx+OFF_TOK);

    const int tid=threadIdx.x, warp=tid>>5, lane=tid&31;
    const int g=lane>>2, tig=lane&3;
    const int blk0 = blockIdx.x*NWARP;
    const int b = min(blk0+warp, BATCH-1);
    const int e0=2*lane, e1=64+2*lane;
    const bool m1 = (lane<18);

    // ---- encoder weight load ----
    for (int i=tid;i<3*104*WST;i+=NTHREADS){
        int gate=i/GSZ, rem=i-gate*GSZ, n=rem/WST, k=rem-n*WST;
        whh[i]=(n<100&&k<100)?__float2half(eWhh[(gate*100+n)*100+k]):__half(0.f);
    }
    for (int i=tid;i<104*WST;i+=NTHREADS){
        int f=i/WST, e=i-f*WST;
        wb2[i]=(f<100&&e<100)?__float2half(Aw[e*100+f]):__half(0.f);
    }
    for (int i=tid;i<11*WIHST;i+=NTHREADS){
        int v=i/WIHST, gg=i-v*WIHST;
        wih[i]=(gg<300)?__float2half(eWih[gg*11+v]):__half(0.f);
    }
    for (int i=tid;i<304;i+=NTHREADS){
        float a=(i<300)?ebih[i]:0.f, c=(i<300)?ebhh[i]:0.f;
        bih[i]=a; bhh[i]=c; bsum[i]=a+c;
    }
    for (int i=tid;i<MROWS*FCA/2;i+=NTHREADS) ((u32*)fcA)[i]=0u;
    for (int i=tid;i<MROWS*104;i+=NTHREADS) hm[i]=0.f;
    __syncthreads();

    // ---- encoder ----
    for (int t=0;t<TIN;t++){
        if (lane<J) toks[warp*J+lane]=inputs[(lane*TIN+t)*BATCH+b];
        __syncthreads();
        int rcol=(t&1)?112:0, wcol=112-rcol;
        pass_rz(fcA,rcol,whh,wih,bsum,toks,buf1,buf2,warp,g,tig);
        __syncthreads();
        pass_n(fcA,rcol,whh,wih,bih,bhh,toks,buf1,buf2,hm,hm,fcA+wcol,true,t,blk0,warp,g,tig);
        __syncthreads();
        for (int tile=warp;tile<39;tile+=NWARP){   // HA = h @ Aw
            int mt=tile/13, nt=tile%13;
            float d[4]={0,0,0,0};
            gemm_tile<7>(fcA,wcol,wb2,WST,mt,nt,g,tig,d);
            int c=nt*8+2*tig;
            if (c<100){
                #pragma unroll
                for (int h2=0;h2<2;h2++){
                    int r=mt*16+g+8*h2;
                    int bb=min(blk0+(r>>2),BATCH-1);
                    float2 v; v.x=d[2*h2]; v.y=d[2*h2+1];
                    *(float2*)&g_HA[((size_t)(bb*J+(r&3))*TIN+t)*HDIM+c]=v;
                }
            }
        }
        __syncthreads();
    }

    // ---- decoder weight load ----
    for (int i=tid;i<3*104*WST;i+=NTHREADS){
        int gate=i/GSZ, rem=i-gate*GSZ, n=rem/WST, k=rem-n*WST;
        whh[i]=(n<100&&k<100)?__float2half(dWhh[(gate*100+n)*100+k]):__half(0.f);
    }
    for (int i=tid;i<104*WWBST;i+=NTHREADS){
        int e=i/WWBST, kk=i-e*WWBST;
        float v=0.f;
        if (e<100){ if (kk<100) v=Ww[e*200+kk]; else if (kk>=112&&kk<212) v=Ww[e*200+kk-12]; }
        wb2[i]=__float2half(v);
    }
    for (int i=tid;i<11*WIHST;i+=NTHREADS){
        int v=i/WIHST, gg=i-v*WIHST;
        wih[i]=(gg<300)?__float2half(dWih[gg*11+v]):__half(0.f);
    }
    for (int i=tid;i<304;i+=NTHREADS){
        float a=(i<300)?dbih[i]:0.f, c=(i<300)?dbhh[i]:0.f;
        bih[i]=a; bhh[i]=c; bsum[i]=a+c;
    }
    for (int i=tid;i<11*104;i+=NTHREADS){ int v=i/104,e=i-v*104; vwf[i]=(e<100)?Vw[v*100+e]:0.f; }
    for (int i=tid;i<104;i+=NTHREADS) wbb[i]=(i<100)?Wb[i]:0.f;
    for (int i=tid;i<16;i+=NTHREADS) vbb[i]=(i<VDIM)?Vb[i]:0.f;
    for (int i=tid;i<MROWS*112;i+=NTHREADS){ int r=i/112,c=i-r*112; fcA[r*FCA+112+c]=fcA[r*FCA+c]; }
    if (tid<MROWS) toks[tid]=VDIM-1;
    __syncthreads();

    // init P0 = GRU(SOS, h_last): hidden in region1, out region0/P32
    pass_rz(fcA,112,whh,wih,bsum,toks,buf1,buf2,warp,g,tig);
    __syncthreads();
    pass_n(fcA,112,whh,wih,bih,bhh,toks,buf1,buf2,hm,P32,fcA+0,false,0,blk0,warp,g,tig);
    __syncthreads();

    float score=0.f;
    float* sc=&scb[warp*40];
    for (int t=0;t<TOUT;t++){
        // scores = HA . P  (40 tasks/warp)
        {
            int j=lane/10, tt=lane-10*j;
            const u64* hap=(const u64*)&g_HA[((size_t)(b*J+j)*TIN+tt)*HDIM];
            const u64* pj =(const u64*)&P32[(warp*J+j)*104];
            u64 acc=0ull;
            #pragma unroll 10
            for(int q=0;q<50;q++) fma2(acc,hap[q],pj[q]);
            float2 f=unpack2(acc); sc[lane]=f.x+f.y;
            if (lane<8){
                int t2=32+lane, j2=t2/10, tt2=t2-10*j2;
                const u64* hap2=(const u64*)&g_HA[((size_t)(b*J+j2)*TIN+tt2)*HDIM];
                const u64* pj2 =(const u64*)&P32[(warp*J+j2)*104];
                u64 a2=0ull;
                #pragma unroll 10
                for(int q=0;q<50;q++) fma2(a2,hap2[q],pj2[q]);
                float2 f2=unpack2(a2); sc[t2]=f2.x+f2.y;
            }
        }
        __syncwarp();
        if (lane<J){   // log_softmax over tt
            float mx=-1e30f;
            #pragma unroll
            for(int tt=0;tt<TIN;tt++) mx=fmaxf(mx,sc[lane*10+tt]);
            float s=0.f;
            #pragma unroll
            for(int tt=0;tt<TIN;tt++) s+=__expf(sc[lane*10+tt]-mx);
            float lg=__logf(s)+mx;
            #pragma unroll
            for(int tt=0;tt<TIN;tt++) sc[lane*10+tt]-=lg;
        }
        __syncwarp();
        // c = logs . H  -> hm (f32) + fcA region1 (fp16)
        #pragma unroll
        for(int j=0;j<J;j++){
            u64 c0=0ull, c1=0ull;
            const float* hb=&g_H[((size_t)(b*J+j)*TIN)*HDIM];
            #pragma unroll
            for(int tt=0;tt<TIN;tt++){
                u64 lg2=dup2(sc[j*10+tt]);
                fma2(c0,*(const u64*)(hb+tt*HDIM+e0),lg2);
                if(m1) fma2(c1,*(const u64*)(hb+tt*HDIM+e1),lg2);
            }
            int r=warp*J+j;
            float2 f0=unpack2(c0);
            *(float2*)&hm[r*104+e0]=f0;
            *(__half2*)&fcA[r*FCA+112+e0]=__floats2half2_rn(f0.x,f0.y);
            if(m1){ float2 f1=unpack2(c1);
                *(float2*)&hm[r*104+e1]=f1;
                *(__half2*)&fcA[r*FCA+112+e1]=__floats2half2_rn(f1.x,f1.y); }
        }
        if (lane<J) toks[warp*J+lane]=target[t*BATCH+b];
        __syncthreads();
        // fc = tanh(Ww @ [P|c] + Wb) -> buf1 fp16
        for (int tile=warp;tile<39;tile+=NWARP){
            int mt=tile/13, nt=tile%13;
            float d[4]={0,0,0,0};
            gemm_tile<14>(fcA,0,wb2,WWBST,mt,nt,g,tig,d);
            int c=nt*8+2*tig;
            if (c<100){
                float2 wb=*(const float2*)&wbb[c];
                #pragma unroll
                for (int h2=0;h2<2;h2++){
                    int r=mt*16+g+8*h2;
                    *(__half2*)&buf1[r*104+c]=
                        __floats2half2_rn(tanh_f(d[2*h2]+wb.x), tanh_f(d[2*h2+1]+wb.y));
                }
            }
        }
        __syncthreads();
        // logits: m = max_j fc, out = log_softmax(m @ VwT + Vb)
        {
            float2 mA; mA.x=-1e30f; mA.y=-1e30f; float2 mB=mA;
            #pragma unroll
            for(int j=0;j<J;j++){
                int r=warp*J+j;
                float2 fA=__half22float2(*(const __half2*)&buf1[r*104+e0]);
                mA.x=fmaxf(mA.x,fA.x); mA.y=fmaxf(mA.y,fA.y);
                if(m1){ float2 fB=__half22float2(*(const __half2*)&buf1[r*104+e1]);
                    mB.x=fmaxf(mB.x,fB.x); mB.y=fmaxf(mB.y,fB.y); }
            }
            float pv[VDIM];
            #pragma unroll
            for(int v=0;v<VDIM;v++){
                const float* vr=&vwf[v*104];
                float p=vr[e0]*mA.x+vr[e0+1]*mA.y;
                if(m1){ p=fmaf(vr[e1],mB.x,p); p=fmaf(vr[e1+1],mB.y,p); }
                pv[v]=p;
            }
            #pragma unroll
            for (int off=16;off>=1;off>>=1){
                #pragma unroll
                for(int v=0;v<VDIM;v++) pv[v]+=__shfl_xor_sync(0xffffffffu,pv[v],off);
            }
            int tok=target[t*BATCH+b];
            float mx=-1e30f;
            #pragma unroll
            for(int v=0;v<VDIM;v++){ pv[v]+=vbb[v]; mx=fmaxf(mx,pv[v]); }
            float ss=0.f;
            #pragma unroll
            for(int v=0;v<VDIM;v++) ss+=__expf(pv[v]-mx);
            score += pv[tok]-mx-__logf(ss);
        }
        __syncthreads();
        // P = GRU(onehot(tok), c)
        pass_rz(fcA,112,whh,wih,bsum,toks,buf1,buf2,warp,g,tig);
        __syncthreads();
        pass_n(fcA,112,whh,wih,bih,bhh,toks,buf1,buf2,hm,P32,fcA+0,false,0,blk0,warp,g,tig);
        __syncthreads();
    }
    if (lane==0 && blk0+warp<BATCH) out[b]=score;
}

extern "C" void kernel_launch(void* const* d_in, const int* in_sizes, int n_in,
                              void* d_out, int out_size)
{
    cudaFuncSetAttribute(fused_kernel, cudaFuncAttributeMaxDynamicSharedMemorySize, SMEM_BYTES);
    int grid=(BATCH+NWARP-1)/NWARP;
    fused_kernel<<<grid, NTHREADS, SMEM_BYTES>>>(
        (const int*)d_in[0], (const int*)d_in[1],
        (const float*)d_in[2], (const float*)d_in[3], (const float*)d_in[4], (const float*)d_in[5],
        (const float*)d_in[6], (const float*)d_in[7], (const float*)d_in[8], (const float*)d_in[9],
        (const float*)d_in[10], (const float*)d_in[11], (const float*)d_in[12], (const float*)d_in[13],
        (const float*)d_in[14], (float*)d_out);
}

// round 6
// speedup vs baseline: 2.2272x; 1.7111x over previous
#include <cuda_runtime.h>
#include <cuda_fp16.h>
#include <cstdint>

#define J 4
#define BATCH 8192
#define TIN 10
#define TOUT 10
#define HDIM 100
#define VDIM 11
#define NWARP 12
#define NTHREADS 384
#define MROWS 48
typedef unsigned long long u64;
typedef uint32_t u32;

#define FCA 232
#define WST 104
#define GSZ (104*104)
#define WWBST 232
#define WIHST 304

// smem byte offsets (16B aligned)
#define OFF_WHH   0        // 3*104*104*2 = 64896
#define OFF_WB2   64896    // 104*232*2 = 48256
#define OFF_WIH   113152   // 11*304*2 = 6688
#define OFF_VW    119840   // 11*104*4
#define OFF_BIH   124416
#define OFF_BHH   125632
#define OFF_BSUM  126848
#define OFF_WBB   128064
#define OFF_VB    128480
#define OFF_FCAB  128544   // 48*232*2 = 22272
#define OFF_HM    150816   // 48*104*4
#define OFF_P32   170784
#define OFF_BUF1  190752   // 48*104*2
#define OFF_BUF2  200736
#define OFF_SC    210720   // 12*40*4
#define OFF_TOK   212640   // 48*4
#define SMEM_BYTES 212832

__device__ float  g_H [(size_t)J*BATCH*TIN*HDIM];
__device__ __half g_HA[(size_t)J*BATCH*TIN*HDIM];

__device__ __forceinline__ void fma2(u64 &d, u64 a, u64 b){
    asm("fma.rn.f32x2 %0, %1, %2, %0;" : "+l"(d) : "l"(a), "l"(b));
}
__device__ __forceinline__ u64 dup2(float x){ u64 r; asm("mov.b64 %0, {%1, %1};" : "=l"(r) : "f"(x)); return r; }
__device__ __forceinline__ float2 unpack2(u64 v){ float2 f; asm("mov.b64 {%0, %1}, %2;" : "=f"(f.x), "=f"(f.y) : "l"(v)); return f; }
__device__ __forceinline__ float sigm(float x){ return __fdividef(1.f, 1.f+__expf(-x)); }
__device__ __forceinline__ float tanh_f(float x){ return fmaf(2.f, __fdividef(1.f, 1.f+__expf(-2.f*x)), -1.f); }
__device__ __forceinline__ u32 smaddr(const void* p){ u32 a; asm("{.reg .u64 t; cvta.to.shared.u64 t, %1; cvt.u32.u64 %0, t;}":"=r"(a):"l"(p)); return a; }
__device__ __forceinline__ void ldsm4(u32&a0,u32&a1,u32&a2,u32&a3,u32 ad){
  asm volatile("ldmatrix.sync.aligned.m8n8.x4.shared.b16 {%0,%1,%2,%3},[%4];":"=r"(a0),"=r"(a1),"=r"(a2),"=r"(a3):"r"(ad));
}
__device__ __forceinline__ void ldsm2(u32&b0,u32&b1,u32 ad){
  asm volatile("ldmatrix.sync.aligned.m8n8.x2.shared.b16 {%0,%1},[%2];":"=r"(b0),"=r"(b1):"r"(ad));
}
__device__ __forceinline__ void mma_(float d[4], const u32 a[4], u32 b0,u32 b1){
  asm("mma.sync.aligned.m16n8k16.row.col.f32.f16.f16.f32 {%0,%1,%2,%3},{%4,%5,%6,%7},{%8,%9},{%0,%1,%2,%3};"
   :"+f"(d[0]),"+f"(d[1]),"+f"(d[2]),"+f"(d[3]):"r"(a[0]),"r"(a[1]),"r"(a[2]),"r"(a[3]),"r"(b0),"r"(b1));
}
#define BARWG() asm volatile("bar.sync %0, 128;"::"r"(wg+1):"memory")

__device__ __forceinline__ void ldA7(u32 Af[7][4], u32 fcA_sm, int row0, int acol, int lane){
  int arow=row0+(lane&7)+((lane&8)?8:0);
  u32 base=fcA_sm+(u32)((arow*FCA+acol+((lane&16)?8:0))*2);
  #pragma unroll
  for(int kt=0;kt<7;kt++) ldsm4(Af[kt][0],Af[kt][1],Af[kt][2],Af[kt][3],base+kt*32u);
}

__device__ __forceinline__ void gru_rz(u32 fcA_sm,int row0,int acol,u32 whh_sm,
    const __half* wih,const float* bsum,const int* toks,__half* buf1,__half* buf2,
    int wlocal,int lane){
  int g=lane>>2,tig=lane&3;
  u32 Af[7][4]; ldA7(Af,fcA_sm,row0,acol,lane);
  int l16=lane&15,brow=l16&7,bk=(l16&8)?8:0;
  for(int tl=wlocal;tl<26;tl+=4){
    int gate=tl/13, nt=tl-13*gate;
    u32 ba=whh_sm+(u32)(gate*GSZ*2)+(u32)((((nt*8+brow)*WST)+bk)*2);
    float d[4]={0,0,0,0};
    #pragma unroll
    for(int kt=0;kt<7;kt++){u32 b0,b1; ldsm2(b0,b1,ba+kt*32u); mma_(d,Af[kt],b0,b1);}
    int c=nt*8+2*tig;
    if(c<100){
      int gc=gate*100+c;
      float2 bs=*(const float2*)&bsum[gc];
      __half* dst=gate?buf2:buf1;
      #pragma unroll
      for(int h2=0;h2<2;h2++){
        int r=row0+g+8*h2;
        float2 w=__half22float2(*(const __half2*)&wih[toks[r]*WIHST+gc]);
        *(__half2*)&dst[r*104+c]=__floats2half2_rn(sigm(d[2*h2]+w.x+bs.x),sigm(d[2*h2+1]+w.y+bs.y));
      }
    }
  }
}

__device__ __forceinline__ void gru_n(u32 fcA_sm,int row0,int acol,u32 whh_sm,
    const __half* wih,const float* bih,const float* bhh,const int* toks,
    const __half* buf1,const __half* buf2,const float* hm,float* fdst,__half* hcol,
    bool wgh,int t,int blk0,int wlocal,int lane){
  int g=lane>>2,tig=lane&3;
  u32 Af[7][4]; ldA7(Af,fcA_sm,row0,acol,lane);
  int l16=lane&15,brow=l16&7,bk=(l16&8)?8:0;
  for(int nt=wlocal;nt<13;nt+=4){
    u32 ba=whh_sm+(u32)(2*GSZ*2)+(u32)((((nt*8+brow)*WST)+bk)*2);
    float d[4]={0,0,0,0};
    #pragma unroll
    for(int kt=0;kt<7;kt++){u32 b0,b1; ldsm2(b0,b1,ba+kt*32u); mma_(d,Af[kt],b0,b1);}
    int c=nt*8+2*tig;
    if(c<100){
      int gc=200+c;
      float2 bi=*(const float2*)&bih[gc], bh=*(const float2*)&bhh[gc];
      #pragma unroll
      for(int h2=0;h2<2;h2++){
        int r=row0+g+8*h2;
        float2 w=__half22float2(*(const __half2*)&wih[toks[r]*WIHST+gc]);
        float2 rr=__half22float2(*(const __half2*)&buf1[r*104+c]);
        float2 zz=__half22float2(*(const __half2*)&buf2[r*104+c]);
        float n0=tanh_f(w.x+bi.x+rr.x*(d[2*h2]+bh.x));
        float n1=tanh_f(w.y+bi.y+rr.y*(d[2*h2+1]+bh.y));
        float2 ho=*(const float2*)&hm[r*104+c];
        float2 hn; hn.x=(1.f-zz.x)*n0+zz.x*ho.x; hn.y=(1.f-zz.y)*n1+zz.y*ho.y;
        *(float2*)&fdst[r*104+c]=hn;
        *(__half2*)&hcol[r*FCA+c]=__floats2half2_rn(hn.x,hn.y);
        if(wgh){int bb=min(blk0+(r>>2),BATCH-1);
          *(float2*)&g_H[((size_t)(bb*J+(r&3))*TIN+t)*HDIM+c]=hn;}
      }
    }
  }
}

__device__ __forceinline__ void ha_pass(u32 fcA_sm,int row0,int acol,u32 aw_sm,
    int t,int blk0,int wlocal,int lane){
  int g=lane>>2,tig=lane&3;
  u32 Af[7][4]; ldA7(Af,fcA_sm,row0,acol,lane);
  int l16=lane&15,brow=l16&7,bk=(l16&8)?8:0;
  for(int nt=wlocal;nt<13;nt+=4){
    u32 ba=aw_sm+(u32)((((nt*8+brow)*WST)+bk)*2);
    float d[4]={0,0,0,0};
    #pragma unroll
    for(int kt=0;kt<7;kt++){u32 b0,b1; ldsm2(b0,b1,ba+kt*32u); mma_(d,Af[kt],b0,b1);}
    int c=nt*8+2*tig;
    if(c<100){
      #pragma unroll
      for(int h2=0;h2<2;h2++){
        int r=row0+g+8*h2;
        int bb=min(blk0+(r>>2),BATCH-1);
        *(__half2*)&g_HA[((size_t)(bb*J+(r&3))*TIN+t)*HDIM+c]=__floats2half2_rn(d[2*h2],d[2*h2+1]);
      }
    }
  }
}

__device__ __forceinline__ void fc_pass(u32 fcA_sm,int row0,u32 wb2_sm,
    const float* wbb,__half* buf1,int wlocal,int lane){
  int g=lane>>2,tig=lane&3;
  int l16=lane&15,brow=l16&7,bk=(l16&8)?8:0;
  float acc[4][4];
  #pragma unroll
  for(int i=0;i<4;i++){acc[i][0]=acc[i][1]=acc[i][2]=acc[i][3]=0.f;}
  #pragma unroll
  for(int hf=0;hf<2;hf++){
    u32 Af[7][4]; ldA7(Af,fcA_sm,row0,hf*112,lane);
    int ti=0;
    for(int nt=wlocal;nt<13;nt+=4,ti++){
      u32 ba=wb2_sm+(u32)((((nt*8+brow)*WWBST)+hf*112+bk)*2);
      #pragma unroll
      for(int kt=0;kt<7;kt++){u32 b0,b1; ldsm2(b0,b1,ba+kt*32u); mma_(acc[ti],Af[kt],b0,b1);}
    }
  }
  int ti=0;
  for(int nt=wlocal;nt<13;nt+=4,ti++){
    int c=nt*8+2*tig;
    if(c<100){
      float2 wb=*(const float2*)&wbb[c];
      #pragma unroll
      for(int h2=0;h2<2;h2++){
        int r=row0+g+8*h2;
        *(__half2*)&buf1[r*104+c]=__floats2half2_rn(tanh_f(acc[ti][2*h2]+wb.x),tanh_f(acc[ti][2*h2+1]+wb.y));
      }
    }
  }
}

__global__ void __launch_bounds__(NTHREADS,1)
fused_kernel(const int* __restrict__ inputs, const int* __restrict__ target,
             const float* __restrict__ eWih, const float* __restrict__ eWhh,
             const float* __restrict__ ebih, const float* __restrict__ ebhh,
             const float* __restrict__ dWih, const float* __restrict__ dWhh,
             const float* __restrict__ dbih, const float* __restrict__ dbhh,
             const float* __restrict__ Ww,  const float* __restrict__ Wb,
             const float* __restrict__ Vw,  const float* __restrict__ Vb,
             const float* __restrict__ Aw,  float* __restrict__ out)
{
    extern __shared__ char smx[];
    __half* whh =(__half*)(smx+OFF_WHH);
    __half* wb2 =(__half*)(smx+OFF_WB2);
    __half* wih =(__half*)(smx+OFF_WIH);
    float*  vwf =(float*)(smx+OFF_VW);
    float*  bih =(float*)(smx+OFF_BIH);
    float*  bhh =(float*)(smx+OFF_BHH);
    float*  bsum=(float*)(smx+OFF_BSUM);
    float*  wbb =(float*)(smx+OFF_WBB);
    float*  vbb =(float*)(smx+OFF_VB);
    __half* fcA =(__half*)(smx+OFF_FCAB);
    float*  hm  =(float*)(smx+OFF_HM);
    float*  P32 =(float*)(smx+OFF_P32);
    __half* buf1=(__half*)(smx+OFF_BUF1);
    __half* buf2=(__half*)(smx+OFF_BUF2);
    float*  scb =(float*)(smx+OFF_SC);
    int*    toks=(int*)(smx+OFF_TOK);

    const u32 fcA_sm=smaddr(fcA), whh_sm=smaddr(whh), wb2_sm=smaddr(wb2);
    const int tid=threadIdx.x, warp=tid>>5, lane=tid&31;
    const int wg=warp>>2, wlocal=warp&3, row0=wg*16;
    const int blk0=blockIdx.x*NWARP;
    const int b=min(blk0+warp,BATCH-1);
    const int e0=2*lane, e1=64+2*lane;
    const bool m1=(lane<18);

    // ---- encoder weight load ----
    for(int i=tid;i<3*GSZ;i+=NTHREADS){
        int gate=i/GSZ, rem=i-gate*GSZ, n=rem/WST, k=rem-n*WST;
        whh[i]=(n<100&&k<100)?__float2half(eWhh[(gate*100+n)*100+k]):__half(0.f);
    }
    for(int i=tid;i<104*WST;i+=NTHREADS){
        int f=i/WST,e=i-f*WST;
        wb2[i]=(f<100&&e<100)?__float2half(Aw[e*100+f]):__half(0.f);
    }
    for(int i=tid;i<11*WIHST;i+=NTHREADS){
        int v=i/WIHST,gg=i-v*WIHST;
        wih[i]=(gg<300)?__float2half(eWih[gg*11+v]):__half(0.f);
    }
    for(int i=tid;i<304;i+=NTHREADS){
        float a=(i<300)?ebih[i]:0.f, c=(i<300)?ebhh[i]:0.f;
        bih[i]=a; bhh[i]=c; bsum[i]=a+c;
    }
    for(int i=tid;i<MROWS*FCA/2;i+=NTHREADS) ((u32*)fcA)[i]=0u;
    for(int i=tid;i<MROWS*104;i+=NTHREADS) hm[i]=0.f;
    __syncthreads();

    // ---- encoder (wg-scoped) ----
    for(int t=0;t<TIN;t++){
        if(lane<J) toks[warp*J+lane]=inputs[(lane*TIN+t)*BATCH+b];
        BARWG();
        int rcol=(t&1)?112:0, wcol=112-rcol;
        gru_rz(fcA_sm,row0,rcol,whh_sm,wih,bsum,toks,buf1,buf2,wlocal,lane);
        BARWG();
        gru_n(fcA_sm,row0,rcol,whh_sm,wih,bih,bhh,toks,buf1,buf2,hm,hm,fcA+wcol,true,t,blk0,wlocal,lane);
        BARWG();
        ha_pass(fcA_sm,row0,wcol,wb2_sm,t,blk0,wlocal,lane);
        BARWG();
    }
    __syncthreads();

    // ---- decoder weight load ----
    for(int i=tid;i<3*GSZ;i+=NTHREADS){
        int gate=i/GSZ, rem=i-gate*GSZ, n=rem/WST, k=rem-n*WST;
        whh[i]=(n<100&&k<100)?__float2half(dWhh[(gate*100+n)*100+k]):__half(0.f);
    }
    for(int i=tid;i<104*WWBST;i+=NTHREADS){
        int e=i/WWBST, kk=i-e*WWBST;
        float v=0.f;
        if(e<100){ if(kk<100) v=Ww[e*200+kk]; else if(kk>=112&&kk<212) v=Ww[e*200+kk-12]; }
        wb2[i]=__float2half(v);
    }
    for(int i=tid;i<11*WIHST;i+=NTHREADS){
        int v=i/WIHST,gg=i-v*WIHST;
        wih[i]=(gg<300)?__float2half(dWih[gg*11+v]):__half(0.f);
    }
    for(int i=tid;i<304;i+=NTHREADS){
        float a=(i<300)?dbih[i]:0.f, c=(i<300)?dbhh[i]:0.f;
        bih[i]=a; bhh[i]=c; bsum[i]=a+c;
    }
    for(int i=tid;i<11*104;i+=NTHREADS){int v=i/104,e=i-v*104; vwf[i]=(e<100)?Vw[v*100+e]:0.f;}
    for(int i=tid;i<104;i+=NTHREADS) wbb[i]=(i<100)?Wb[i]:0.f;
    for(int i=tid;i<16;i+=NTHREADS) vbb[i]=(i<VDIM)?Vb[i]:0.f;
    for(int i=tid;i<MROWS*112;i+=NTHREADS){int r=i/112,c=i-r*112; fcA[r*FCA+112+c]=fcA[r*FCA+c];}
    if(tid<MROWS) toks[tid]=VDIM-1;
    __syncthreads();

    // init P0 = GRU(SOS, h_last)
    gru_rz(fcA_sm,row0,112,whh_sm,wih,bsum,toks,buf1,buf2,wlocal,lane);
    BARWG();
    gru_n(fcA_sm,row0,112,whh_sm,wih,bih,bhh,toks,buf1,buf2,hm,P32,fcA,false,0,blk0,wlocal,lane);
    BARWG();

    float score=0.f;
    float* sc=&scb[warp*40];
    for(int t=0;t<TOUT;t++){
        // scores = HA . P (own element per warp)
        {
            int j=lane/10, tt=lane-10*j;
            const __half2* hap=(const __half2*)&g_HA[((size_t)(b*J+j)*TIN+tt)*HDIM];
            const float2* pj=(const float2*)&P32[(warp*J+j)*104];
            float accs=0.f;
            #pragma unroll 10
            for(int q=0;q<50;q++){float2 hf=__half22float2(hap[q]);float2 pp=pj[q];
                accs=fmaf(hf.x,pp.x,accs); accs=fmaf(hf.y,pp.y,accs);}
            sc[lane]=accs;
            if(lane<8){
                int t2=32+lane, j2=t2/10, tt2=t2-10*j2;
                const __half2* hap2=(const __half2*)&g_HA[((size_t)(b*J+j2)*TIN+tt2)*HDIM];
                const float2* pj2=(const float2*)&P32[(warp*J+j2)*104];
                float a2=0.f;
                #pragma unroll 10
                for(int q=0;q<50;q++){float2 hf=__half22float2(hap2[q]);float2 pp=pj2[q];
                    a2=fmaf(hf.x,pp.x,a2); a2=fmaf(hf.y,pp.y,a2);}
                sc[t2]=a2;
            }
        }
        __syncwarp();
        if(lane<J){
            float mx=-1e30f;
            #pragma unroll
            for(int tt=0;tt<TIN;tt++) mx=fmaxf(mx,sc[lane*10+tt]);
            float s=0.f;
            #pragma unroll
            for(int tt=0;tt<TIN;tt++) s+=__expf(sc[lane*10+tt]-mx);
            float lg=__logf(s)+mx;
            #pragma unroll
            for(int tt=0;tt<TIN;tt++) sc[lane*10+tt]-=lg;
        }
        __syncwarp();
        // c = logs . H -> hm + fcA region1
        #pragma unroll
        for(int j=0;j<J;j++){
            u64 c0=0ull,c1=0ull;
            const float* hb=&g_H[((size_t)(b*J+j)*TIN)*HDIM];
            #pragma unroll
            for(int tt=0;tt<TIN;tt++){
                u64 lg2=dup2(sc[j*10+tt]);
                fma2(c0,*(const u64*)(hb+tt*HDIM+e0),lg2);
                if(m1) fma2(c1,*(const u64*)(hb+tt*HDIM+e1),lg2);
            }
            int r=warp*J+j;
            float2 f0=unpack2(c0);
            *(float2*)&hm[r*104+e0]=f0;
            *(__half2*)&fcA[r*FCA+112+e0]=__floats2half2_rn(f0.x,f0.y);
            if(m1){float2 f1=unpack2(c1);
                *(float2*)&hm[r*104+e1]=f1;
                *(__half2*)&fcA[r*FCA+112+e1]=__floats2half2_rn(f1.x,f1.y);}
        }
        if(lane<J) toks[warp*J+lane]=target[t*BATCH+b];
        BARWG();
        // fc = tanh(Ww @ [P|c] + Wb)
        fc_pass(fcA_sm,row0,wb2_sm,wbb,buf1,wlocal,lane);
        BARWG();
        // logits
        {
            float2 mA; mA.x=-1e30f; mA.y=-1e30f; float2 mB=mA;
            #pragma unroll
            for(int j=0;j<J;j++){
                int r=warp*J+j;
                float2 fA=__half22float2(*(const __half2*)&buf1[r*104+e0]);
                mA.x=fmaxf(mA.x,fA.x); mA.y=fmaxf(mA.y,fA.y);
                if(m1){float2 fB=__half22float2(*(const __half2*)&buf1[r*104+e1]);
                    mB.x=fmaxf(mB.x,fB.x); mB.y=fmaxf(mB.y,fB.y);}
            }
            float pv[VDIM];
            #pragma unroll
            for(int v=0;v<VDIM;v++){
                const float* vr=&vwf[v*104];
                float p=vr[e0]*mA.x+vr[e0+1]*mA.y;
                if(m1){p=fmaf(vr[e1],mB.x,p); p=fmaf(vr[e1+1],mB.y,p);}
                pv[v]=p;
            }
            #pragma unroll
            for(int off=16;off>=1;off>>=1){
                #pragma unroll
                for(int v=0;v<VDIM;v++) pv[v]+=__shfl_xor_sync(0xffffffffu,pv[v],off);
            }
            int tok=target[t*BATCH+b];
            float mx=-1e30f;
            #pragma unroll
            for(int v=0;v<VDIM;v++){pv[v]+=vbb[v]; mx=fmaxf(mx,pv[v]);}
            float ss=0.f;
            #pragma unroll
            for(int v=0;v<VDIM;v++) ss+=__expf(pv[v]-mx);
            score+=pv[tok]-mx-__logf(ss);
        }
        BARWG();  // protect buf1 before GRU overwrites
        gru_rz(fcA_sm,row0,112,whh_sm,wih,bsum,toks,buf1,buf2,wlocal,lane);
        BARWG();
        gru_n(fcA_sm,row0,112,whh_sm,wih,bih,bhh,toks,buf1,buf2,hm,P32,fcA,false,0,blk0,wlocal,lane);
        BARWG();
    }
    if(lane==0) out[b]=score;
}

extern "C" void kernel_launch(void* const* d_in, const int* in_sizes, int n_in,
                              void* d_out, int out_size)
{
    cudaFuncSetAttribute(fused_kernel, cudaFuncAttributeMaxDynamicSharedMemorySize, SMEM_BYTES);
    int grid=(BATCH+NWARP-1)/NWARP;
    fused_kernel<<<grid, NTHREADS, SMEM_BYTES>>>(
        (const int*)d_in[0], (const int*)d_in[1],
        (const float*)d_in[2], (const float*)d_in[3], (const float*)d_in[4], (const float*)d_in[5],
        (const float*)d_in[6], (const float*)d_in[7], (const float*)d_in[8], (const float*)d_in[9],
        (const float*)d_in[10], (const float*)d_in[11], (const float*)d_in[12], (const float*)d_in[13],
        (const float*)d_in[14], (float*)d_out);
}

// round 7
// speedup vs baseline: 2.4488x; 1.0995x over previous
#include <cuda_runtime.h>
#include <cuda_fp16.h>
#include <cstdint>

#define J 4
#define BATCH 8192
#define TIN 10
#define TOUT 10
#define HDIM 100
#define VDIM 11
#define NWARP 16
#define NTHREADS 512
#define MROWS 64
typedef unsigned long long u64;
typedef uint32_t u32;

#define FCA 232
#define WST 104
#define GSZ (104*104)
#define WWBST 232
#define WIHST 304

// smem byte offsets
#define OFF_WHH   0        // 64896
#define OFF_WB2   64896    // 48256
#define OFF_WIH   113152   // 6688
#define OFF_VW    119840   // 4576
#define OFF_BIH   124416   // 1216
#define OFF_BHH   125632
#define OFF_BSUM  126848
#define OFF_WBB   128064   // 416
#define OFF_VB    128480   // 64
#define OFF_FCAB  128544   // 64*232*2=29696
#define OFF_HM    158240   // 64*104*4=26624
#define OFF_BUF1  184864   // 13312
#define OFF_BUF2  198176   // 13312
#define OFF_BUF3  211488   // 13312
#define OFF_SC    224800   // 2560
#define OFF_TOK   227360   // 256
#define SMEM_BYTES 227616

__device__ float  g_H [(size_t)J*BATCH*TIN*HDIM];
__device__ __half g_HA[(size_t)J*BATCH*TIN*HDIM];

__device__ __forceinline__ void fma2(u64 &d, u64 a, u64 b){
    asm("fma.rn.f32x2 %0, %1, %2, %0;" : "+l"(d) : "l"(a), "l"(b));
}
__device__ __forceinline__ u64 dup2(float x){ u64 r; asm("mov.b64 %0, {%1, %1};" : "=l"(r) : "f"(x)); return r; }
__device__ __forceinline__ float2 unpack2(u64 v){ float2 f; asm("mov.b64 {%0, %1}, %2;" : "=f"(f.x), "=f"(f.y) : "l"(v)); return f; }
__device__ __forceinline__ float sigm(float x){ return __fdividef(1.f, 1.f+__expf(-x)); }
__device__ __forceinline__ float tanh_f(float x){ return fmaf(2.f, __fdividef(1.f, 1.f+__expf(-2.f*x)), -1.f); }
__device__ __forceinline__ u32 smaddr(const void* p){ u32 a; asm("{.reg .u64 t; cvta.to.shared.u64 t, %1; cvt.u32.u64 %0, t;}":"=r"(a):"l"(p)); return a; }
__device__ __forceinline__ void ldsm4(u32&a0,u32&a1,u32&a2,u32&a3,u32 ad){
  asm volatile("ldmatrix.sync.aligned.m8n8.x4.shared.b16 {%0,%1,%2,%3},[%4];":"=r"(a0),"=r"(a1),"=r"(a2),"=r"(a3):"r"(ad));
}
__device__ __forceinline__ void ldsm2(u32&b0,u32&b1,u32 ad){
  asm volatile("ldmatrix.sync.aligned.m8n8.x2.shared.b16 {%0,%1},[%2];":"=r"(b0),"=r"(b1):"r"(ad));
}
__device__ __forceinline__ void mma_(float d[4], const u32 a[4], u32 b0,u32 b1){
  asm("mma.sync.aligned.m16n8k16.row.col.f32.f16.f16.f32 {%0,%1,%2,%3},{%4,%5,%6,%7},{%8,%9},{%0,%1,%2,%3};"
   :"+f"(d[0]),"+f"(d[1]),"+f"(d[2]),"+f"(d[3]):"r"(a[0]),"r"(a[1]),"r"(a[2]),"r"(a[3]),"r"(b0),"r"(b1));
}
#define BARWG() asm volatile("bar.sync %0, 128;"::"r"(wg+1):"memory")

__device__ __forceinline__ void ldA7(u32 Af[7][4], u32 fcA_sm, int row0, int acol, int lane){
  int arow=row0+(lane&7)+((lane&8)?8:0);
  u32 base=fcA_sm+(u32)((arow*FCA+acol+((lane&16)?8:0))*2);
  #pragma unroll
  for(int kt=0;kt<7;kt++) ldsm4(Af[kt][0],Af[kt][1],Af[kt][2],Af[kt][3],base+kt*32u);
}

// r,z gates -> buf2 (r), buf3 (z)
__device__ __forceinline__ void gru_rz(u32 fcA_sm,int row0,int acol,u32 whh_sm,
    const __half* wih,const float* bsum,const int* toks,__half* buf2,__half* buf3,
    int wlocal,int lane){
  int g=lane>>2,tig=lane&3;
  u32 Af[7][4]; ldA7(Af,fcA_sm,row0,acol,lane);
  int l16=lane&15,brow=l16&7,bk=(l16&8)?8:0;
  for(int tl=wlocal;tl<26;tl+=4){
    int gate=tl/13, nt=tl-13*gate;
    u32 ba=whh_sm+(u32)(gate*GSZ*2)+(u32)((((nt*8+brow)*WST)+bk)*2);
    float d[4]={0,0,0,0};
    #pragma unroll
    for(int kt=0;kt<7;kt++){u32 b0,b1; ldsm2(b0,b1,ba+kt*32u); mma_(d,Af[kt],b0,b1);}
    int c=nt*8+2*tig;
    if(c<100){
      int gc=gate*100+c;
      float2 bs=*(const float2*)&bsum[gc];
      __half* dst=gate?buf3:buf2;
      #pragma unroll
      for(int h2=0;h2<2;h2++){
        int r=row0+g+8*h2;
        float2 w=__half22float2(*(const __half2*)&wih[toks[r]*WIHST+gc]);
        *(__half2*)&dst[r*104+c]=__floats2half2_rn(sigm(d[2*h2]+w.x+bs.x),sigm(d[2*h2+1]+w.y+bs.y));
      }
    }
  }
}

__device__ __forceinline__ void gru_n(u32 fcA_sm,int row0,int acol,u32 whh_sm,
    const __half* wih,const float* bih,const float* bhh,const int* toks,
    const __half* buf2,const __half* buf3,const float* hm,float* fdst,__half* hcol,
    bool wgh,int t,int blk0,int wlocal,int lane){
  int g=lane>>2,tig=lane&3;
  u32 Af[7][4]; ldA7(Af,fcA_sm,row0,acol,lane);
  int l16=lane&15,brow=l16&7,bk=(l16&8)?8:0;
  for(int nt=wlocal;nt<13;nt+=4){
    u32 ba=whh_sm+(u32)(2*GSZ*2)+(u32)((((nt*8+brow)*WST)+bk)*2);
    float d[4]={0,0,0,0};
    #pragma unroll
    for(int kt=0;kt<7;kt++){u32 b0,b1; ldsm2(b0,b1,ba+kt*32u); mma_(d,Af[kt],b0,b1);}
    int c=nt*8+2*tig;
    if(c<100){
      int gc=200+c;
      float2 bi=*(const float2*)&bih[gc], bh=*(const float2*)&bhh[gc];
      #pragma unroll
      for(int h2=0;h2<2;h2++){
        int r=row0+g+8*h2;
        float2 w=__half22float2(*(const __half2*)&wih[toks[r]*WIHST+gc]);
        float2 rr=__half22float2(*(const __half2*)&buf2[r*104+c]);
        float2 zz=__half22float2(*(const __half2*)&buf3[r*104+c]);
        float n0=tanh_f(w.x+bi.x+rr.x*(d[2*h2]+bh.x));
        float n1=tanh_f(w.y+bi.y+rr.y*(d[2*h2+1]+bh.y));
        float2 ho=*(const float2*)&hm[r*104+c];
        float2 hn; hn.x=(1.f-zz.x)*n0+zz.x*ho.x; hn.y=(1.f-zz.y)*n1+zz.y*ho.y;
        *(float2*)&fdst[r*104+c]=hn;
        *(__half2*)&hcol[r*FCA+c]=__floats2half2_rn(hn.x,hn.y);
        if(wgh){int bb=min(blk0+(r>>2),BATCH-1);
          *(float2*)&g_H[((size_t)(bb*J+(r&3))*TIN+t)*HDIM+c]=hn;}
      }
    }
  }
}

__device__ __forceinline__ void ha_pass(u32 fcA_sm,int row0,int acol,u32 aw_sm,
    int t,int blk0,int wlocal,int lane){
  int g=lane>>2,tig=lane&3;
  u32 Af[7][4]; ldA7(Af,fcA_sm,row0,acol,lane);
  int l16=lane&15,brow=l16&7,bk=(l16&8)?8:0;
  for(int nt=wlocal;nt<13;nt+=4){
    u32 ba=aw_sm+(u32)((((nt*8+brow)*WST)+bk)*2);
    float d[4]={0,0,0,0};
    #pragma unroll
    for(int kt=0;kt<7;kt++){u32 b0,b1; ldsm2(b0,b1,ba+kt*32u); mma_(d,Af[kt],b0,b1);}
    int c=nt*8+2*tig;
    if(c<100){
      #pragma unroll
      for(int h2=0;h2<2;h2++){
        int r=row0+g+8*h2;
        int bb=min(blk0+(r>>2),BATCH-1);
        *(__half2*)&g_HA[((size_t)(bb*J+(r&3))*TIN+t)*HDIM+c]=__floats2half2_rn(d[2*h2],d[2*h2+1]);
      }
    }
  }
}

__device__ __forceinline__ void fc_pass(u32 fcA_sm,int row0,u32 wb2_sm,
    const float* wbb,__half* buf1,int wlocal,int lane){
  int g=lane>>2,tig=lane&3;
  int l16=lane&15,brow=l16&7,bk=(l16&8)?8:0;
  float acc[4][4];
  #pragma unroll
  for(int i=0;i<4;i++){acc[i][0]=acc[i][1]=acc[i][2]=acc[i][3]=0.f;}
  #pragma unroll
  for(int hf=0;hf<2;hf++){
    u32 Af[7][4]; ldA7(Af,fcA_sm,row0,hf*112,lane);
    int ti=0;
    for(int nt=wlocal;nt<13;nt+=4,ti++){
      u32 ba=wb2_sm+(u32)((((nt*8+brow)*WWBST)+hf*112+bk)*2);
      #pragma unroll
      for(int kt=0;kt<7;kt++){u32 b0,b1; ldsm2(b0,b1,ba+kt*32u); mma_(acc[ti],Af[kt],b0,b1);}
    }
  }
  int ti=0;
  for(int nt=wlocal;nt<13;nt+=4,ti++){
    int c=nt*8+2*tig;
    if(c<100){
      float2 wb=*(const float2*)&wbb[c];
      #pragma unroll
      for(int h2=0;h2<2;h2++){
        int r=row0+g+8*h2;
        *(__half2*)&buf1[r*104+c]=__floats2half2_rn(tanh_f(acc[ti][2*h2]+wb.x),tanh_f(acc[ti][2*h2+1]+wb.y));
      }
    }
  }
}

__global__ void __launch_bounds__(NTHREADS,1)
fused_kernel(const int* __restrict__ inputs, const int* __restrict__ target,
             const float* __restrict__ eWih, const float* __restrict__ eWhh,
             const float* __restrict__ ebih, const float* __restrict__ ebhh,
             const float* __restrict__ dWih, const float* __restrict__ dWhh,
             const float* __restrict__ dbih, const float* __restrict__ dbhh,
             const float* __restrict__ Ww,  const float* __restrict__ Wb,
             const float* __restrict__ Vw,  const float* __restrict__ Vb,
             const float* __restrict__ Aw,  float* __restrict__ out)
{
    extern __shared__ char smx[];
    __half* whh =(__half*)(smx+OFF_WHH);
    __half* wb2 =(__half*)(smx+OFF_WB2);
    __half* wih =(__half*)(smx+OFF_WIH);
    float*  vwf =(float*)(smx+OFF_VW);
    float*  bih =(float*)(smx+OFF_BIH);
    float*  bhh =(float*)(smx+OFF_BHH);
    float*  bsum=(float*)(smx+OFF_BSUM);
    float*  wbb =(float*)(smx+OFF_WBB);
    float*  vbb =(float*)(smx+OFF_VB);
    __half* fcA =(__half*)(smx+OFF_FCAB);
    float*  hm  =(float*)(smx+OFF_HM);
    __half* buf1=(__half*)(smx+OFF_BUF1);
    __half* buf2=(__half*)(smx+OFF_BUF2);
    __half* buf3=(__half*)(smx+OFF_BUF3);
    float*  scb =(float*)(smx+OFF_SC);
    int*    toks=(int*)(smx+OFF_TOK);

    const u32 fcA_sm=smaddr(fcA), whh_sm=smaddr(whh), wb2_sm=smaddr(wb2);
    const int tid=threadIdx.x, warp=tid>>5, lane=tid&31;
    const int wg=warp>>2, wlocal=warp&3, row0=wg*16;
    const int blk0=blockIdx.x*NWARP;
    const int b=min(blk0+warp,BATCH-1);
    const int e0=2*lane, e1=64+2*lane;
    const bool m1=(lane<18);

    // ---- encoder weight load ----
    for(int i=tid;i<3*GSZ;i+=NTHREADS){
        int gate=i/GSZ, rem=i-gate*GSZ, n=rem/WST, k=rem-n*WST;
        whh[i]=(n<100&&k<100)?__float2half(eWhh[(gate*100+n)*100+k]):__half(0.f);
    }
    for(int i=tid;i<104*WST;i+=NTHREADS){
        int f=i/WST,e=i-f*WST;
        wb2[i]=(f<100&&e<100)?__float2half(Aw[e*100+f]):__half(0.f);
    }
    for(int i=tid;i<11*WIHST;i+=NTHREADS){
        int v=i/WIHST,gg=i-v*WIHST;
        wih[i]=(gg<300)?__float2half(eWih[gg*11+v]):__half(0.f);
    }
    for(int i=tid;i<304;i+=NTHREADS){
        float a=(i<300)?ebih[i]:0.f, c=(i<300)?ebhh[i]:0.f;
        bih[i]=a; bhh[i]=c; bsum[i]=a+c;
    }
    for(int i=tid;i<MROWS*FCA/2;i+=NTHREADS) ((u32*)fcA)[i]=0u;
    for(int i=tid;i<MROWS*104;i+=NTHREADS) hm[i]=0.f;
    __syncthreads();

    // ---- encoder ----
    for(int t=0;t<TIN;t++){
        if(lane<J) toks[warp*J+lane]=inputs[(lane*TIN+t)*BATCH+b];
        BARWG();
        int rcol=(t&1)?112:0, wcol=112-rcol;
        gru_rz(fcA_sm,row0,rcol,whh_sm,wih,bsum,toks,buf2,buf3,wlocal,lane);
        BARWG();
        gru_n(fcA_sm,row0,rcol,whh_sm,wih,bih,bhh,toks,buf2,buf3,hm,hm,fcA+wcol,true,t,blk0,wlocal,lane);
        BARWG();
        ha_pass(fcA_sm,row0,wcol,wb2_sm,t,blk0,wlocal,lane);
        BARWG();
    }
    __syncthreads();

    // ---- decoder weight load ----
    for(int i=tid;i<3*GSZ;i+=NTHREADS){
        int gate=i/GSZ, rem=i-gate*GSZ, n=rem/WST, k=rem-n*WST;
        whh[i]=(n<100&&k<100)?__float2half(dWhh[(gate*100+n)*100+k]):__half(0.f);
    }
    for(int i=tid;i<104*WWBST;i+=NTHREADS){
        int e=i/WWBST, kk=i-e*WWBST;
        float v=0.f;
        if(e<100){ if(kk<100) v=Ww[e*200+kk]; else if(kk>=112&&kk<212) v=Ww[e*200+kk-12]; }
        wb2[i]=__float2half(v);
    }
    for(int i=tid;i<11*WIHST;i+=NTHREADS){
        int v=i/WIHST,gg=i-v*WIHST;
        wih[i]=(gg<300)?__float2half(dWih[gg*11+v]):__half(0.f);
    }
    for(int i=tid;i<304;i+=NTHREADS){
        float a=(i<300)?dbih[i]:0.f, c=(i<300)?dbhh[i]:0.f;
        bih[i]=a; bhh[i]=c; bsum[i]=a+c;
    }
    for(int i=tid;i<11*104;i+=NTHREADS){int v=i/104,e=i-v*104; vwf[i]=(e<100)?Vw[v*100+e]:0.f;}
    for(int i=tid;i<104;i+=NTHREADS) wbb[i]=(i<100)?Wb[i]:0.f;
    for(int i=tid;i<16;i+=NTHREADS) vbb[i]=(i<VDIM)?Vb[i]:0.f;
    for(int i=tid;i<MROWS*112;i+=NTHREADS){int r=i/112,c=i-r*112; fcA[r*FCA+112+c]=fcA[r*FCA+c];}
    if(tid<MROWS) toks[tid]=VDIM-1;
    __syncthreads();

    // init P0 = GRU(SOS, h_last)
    gru_rz(fcA_sm,row0,112,whh_sm,wih,bsum,toks,buf2,buf3,wlocal,lane);
    BARWG();
    gru_n(fcA_sm,row0,112,whh_sm,wih,bih,bhh,toks,buf2,buf3,hm,hm,fcA,false,0,blk0,wlocal,lane);
    BARWG();

    float score=0.f;
    float* sc=&scb[warp*40];
    for(int t=0;t<TOUT;t++){
        // scores = HA . P (P fp16 from fcA region0)
        {
            int j=lane/10, tt=lane-10*j;
            const __half2* hap=(const __half2*)&g_HA[((size_t)(b*J+j)*TIN+tt)*HDIM];
            const __half2* pj=(const __half2*)&fcA[(warp*J+j)*FCA];
            float accs=0.f;
            #pragma unroll 10
            for(int q=0;q<50;q++){float2 hf=__half22float2(hap[q]);float2 pp=__half22float2(pj[q]);
                accs=fmaf(hf.x,pp.x,accs); accs=fmaf(hf.y,pp.y,accs);}
            sc[lane]=accs;
            if(lane<8){
                int t2=32+lane, j2=t2/10, tt2=t2-10*j2;
                const __half2* hap2=(const __half2*)&g_HA[((size_t)(b*J+j2)*TIN+tt2)*HDIM];
                const __half2* pj2=(const __half2*)&fcA[(warp*J+j2)*FCA];
                float a2=0.f;
                #pragma unroll 10
                for(int q=0;q<50;q++){float2 hf=__half22float2(hap2[q]);float2 pp=__half22float2(pj2[q]);
                    a2=fmaf(hf.x,pp.x,a2); a2=fmaf(hf.y,pp.y,a2);}
                sc[t2]=a2;
            }
        }
        __syncwarp();
        if(lane<J){
            float mx=-1e30f;
            #pragma unroll
            for(int tt=0;tt<TIN;tt++) mx=fmaxf(mx,sc[lane*10+tt]);
            float s=0.f;
            #pragma unroll
            for(int tt=0;tt<TIN;tt++) s+=__expf(sc[lane*10+tt]-mx);
            float lg=__logf(s)+mx;
            #pragma unroll
            for(int tt=0;tt<TIN;tt++) sc[lane*10+tt]-=lg;
        }
        __syncwarp();
        // c = logs . H -> hm (f32) + fcA region1 (fp16)
        #pragma unroll
        for(int j=0;j<J;j++){
            u64 c0=0ull,c1=0ull;
            const float* hb=&g_H[((size_t)(b*J+j)*TIN)*HDIM];
            #pragma unroll
            for(int tt=0;tt<TIN;tt++){
                u64 lg2=dup2(sc[j*10+tt]);
                fma2(c0,*(const u64*)(hb+tt*HDIM+e0),lg2);
                if(m1) fma2(c1,*(const u64*)(hb+tt*HDIM+e1),lg2);
            }
            int r=warp*J+j;
            float2 f0=unpack2(c0);
            *(float2*)&hm[r*104+e0]=f0;
            *(__half2*)&fcA[r*FCA+112+e0]=__floats2half2_rn(f0.x,f0.y);
            if(m1){float2 f1=unpack2(c1);
                *(float2*)&hm[r*104+e1]=f1;
                *(__half2*)&fcA[r*FCA+112+e1]=__floats2half2_rn(f1.x,f1.y);}
        }
        if(lane<J) toks[warp*J+lane]=target[t*BATCH+b];
        BARWG();
        // pass A: fc (writes buf1) + rz gates (write buf2/buf3)
        fc_pass(fcA_sm,row0,wb2_sm,wbb,buf1,wlocal,lane);
        gru_rz(fcA_sm,row0,112,whh_sm,wih,bsum,toks,buf2,buf3,wlocal,lane);
        BARWG();
        // pass B: logits (reads buf1) + gru_n (reads buf2/3, writes hm + fcA region0)
        {
            float2 mA; mA.x=-1e30f; mA.y=-1e30f; float2 mB=mA;
            #pragma unroll
            for(int j=0;j<J;j++){
                int r=warp*J+j;
                float2 fA=__half22float2(*(const __half2*)&buf1[r*104+e0]);
                mA.x=fmaxf(mA.x,fA.x); mA.y=fmaxf(mA.y,fA.y);
                if(m1){float2 fB=__half22float2(*(const __half2*)&buf1[r*104+e1]);
                    mB.x=fmaxf(mB.x,fB.x); mB.y=fmaxf(mB.y,fB.y);}
            }
            float pv[VDIM];
            #pragma unroll
            for(int v=0;v<VDIM;v++){
                const float* vr=&vwf[v*104];
                float p=vr[e0]*mA.x+vr[e0+1]*mA.y;
                if(m1){p=fmaf(vr[e1],mB.x,p); p=fmaf(vr[e1+1],mB.y,p);}
                pv[v]=p;
            }
            #pragma unroll
            for(int off=16;off>=1;off>>=1){
                #pragma unroll
                for(int v=0;v<VDIM;v++) pv[v]+=__shfl_xor_sync(0xffffffffu,pv[v],off);
            }
            int tok=target[t*BATCH+b];
            float mx=-1e30f;
            #pragma unroll
            for(int v=0;v<VDIM;v++){pv[v]+=vbb[v]; mx=fmaxf(mx,pv[v]);}
            float ss=0.f;
            #pragma unroll
            for(int v=0;v<VDIM;v++) ss+=__expf(pv[v]-mx);
            score+=pv[tok]-mx-__logf(ss);
        }
        gru_n(fcA_sm,row0,112,whh_sm,wih,bih,bhh,toks,buf2,buf3,hm,hm,fcA,false,0,blk0,wlocal,lane);
        BARWG();
    }
    if(lane==0) out[b]=score;
}

extern "C" void kernel_launch(void* const* d_in, const int* in_sizes, int n_in,
                              void* d_out, int out_size)
{
    cudaFuncSetAttribute(fused_kernel, cudaFuncAttributeMaxDynamicSharedMemorySize, SMEM_BYTES);
    int grid=(BATCH+NWARP-1)/NWARP;  // 512
    fused_kernel<<<grid, NTHREADS, SMEM_BYTES>>>(
        (const int*)d_in[0], (const int*)d_in[1],
        (const float*)d_in[2], (const float*)d_in[3], (const float*)d_in[4], (const float*)d_in[5],
        (const float*)d_in[6], (const float*)d_in[7], (const float*)d_in[8], (const float*)d_in[9],
        (const float*)d_in[10], (const float*)d_in[11], (const float*)d_in[12], (const float*)d_in[13],
        (const float*)d_in[14], (float*)d_out);
}

// round 8
// speedup vs baseline: 2.9794x; 1.2167x over previous
#include <cuda_runtime.h>
#include <cuda_fp16.h>
#include <cstdint>

#define J 4
#define BATCH 8192
#define TIN 10
#define TOUT 10
#define VDIM 11
#define NWARP 16
#define NTHREADS 512
#define MROWS 64
typedef unsigned long long u64;
typedef uint32_t u32;

#define FCA 232
#define WST 104
#define GSZ (104*104)
#define WWBST 232
#define WIHST 304
#define HP 104   // padded row length for g_H / g_HA

// smem byte offsets
#define OFF_WHH   0
#define OFF_WB2   64896
#define OFF_WIH   113152
#define OFF_VW    119840
#define OFF_BIH   124416
#define OFF_BHH   125632
#define OFF_BSUM  126848
#define OFF_WBB   128064
#define OFF_VB    128480
#define OFF_FCAB  128544
#define OFF_HM    158240
#define OFF_BUF1  184864
#define OFF_BUF2  198176
#define OFF_BUF3  211488
#define OFF_SC    224800
#define OFF_TOK   227360
#define SMEM_BYTES 227616

__device__ float  g_H [(size_t)J*BATCH*TIN*HP];
__device__ __half g_HA[(size_t)J*BATCH*TIN*HP];

__device__ __forceinline__ float sigm(float x){ return __fdividef(1.f, 1.f+__expf(-x)); }
__device__ __forceinline__ float tanh_f(float x){ return fmaf(2.f, __fdividef(1.f, 1.f+__expf(-2.f*x)), -1.f); }
__device__ __forceinline__ u32 smaddr(const void* p){ u32 a; asm("{.reg .u64 t; cvta.to.shared.u64 t, %1; cvt.u32.u64 %0, t;}":"=r"(a):"l"(p)); return a; }
__device__ __forceinline__ void ldsm4(u32&a0,u32&a1,u32&a2,u32&a3,u32 ad){
  asm volatile("ldmatrix.sync.aligned.m8n8.x4.shared.b16 {%0,%1,%2,%3},[%4];":"=r"(a0),"=r"(a1),"=r"(a2),"=r"(a3):"r"(ad));
}
__device__ __forceinline__ void ldsm2(u32&b0,u32&b1,u32 ad){
  asm volatile("ldmatrix.sync.aligned.m8n8.x2.shared.b16 {%0,%1},[%2];":"=r"(b0),"=r"(b1):"r"(ad));
}
__device__ __forceinline__ void mma_(float d[4], const u32 a[4], u32 b0,u32 b1){
  asm("mma.sync.aligned.m16n8k16.row.col.f32.f16.f16.f32 {%0,%1,%2,%3},{%4,%5,%6,%7},{%8,%9},{%0,%1,%2,%3};"
   :"+f"(d[0]),"+f"(d[1]),"+f"(d[2]),"+f"(d[3]):"r"(a[0]),"r"(a[1]),"r"(a[2]),"r"(a[3]),"r"(b0),"r"(b1));
}
#define BARWG() asm volatile("bar.sync %0, 128;"::"r"(wg+1):"memory")

__device__ __forceinline__ void ldA7(u32 Af[7][4], u32 fcA_sm, int row0, int acol, int lane){
  int arow=row0+(lane&7)+((lane&8)?8:0);
  u32 base=fcA_sm+(u32)((arow*FCA+acol+((lane&16)?8:0))*2);
  #pragma unroll
  for(int kt=0;kt<7;kt++) ldsm4(Af[kt][0],Af[kt][1],Af[kt][2],Af[kt][3],base+kt*32u);
}

// one n-super-tile: un<6 => pair of n-tiles (cols un*16..+15) via ldsm4-B;
// un==6 => single tile (cols 96..103) via ldsm2. Accumulates into d2.
__device__ __forceinline__ void unit_mma(const u32 Af[7][4], u32 bbase, int bst,
                                         int un, float d2[2][4], int lane){
  if(un<6){
    int row=un*16+(lane&7)+((lane&16)?8:0);
    u32 ba=bbase+(u32)((row*bst+((lane&8)?8:0))*2);
    #pragma unroll
    for(int kt=0;kt<7;kt++){
      u32 b0,b1,b2,b3; ldsm4(b0,b1,b2,b3,ba+kt*32u);
      mma_(d2[0],Af[kt],b0,b1); mma_(d2[1],Af[kt],b2,b3);
    }
  }else{
    int l16=lane&15;
    u32 ba=bbase+(u32)(((96+(l16&7))*bst+((l16&8)?8:0))*2);
    #pragma unroll
    for(int kt=0;kt<7;kt++){ u32 b0,b1; ldsm2(b0,b1,ba+kt*32u); mma_(d2[0],Af[kt],b0,b1); }
  }
}

// rz epilogue for one super-tile
__device__ __forceinline__ void rz_epi(int gate,int un,float d2[2][4],
    const __half* wih,const float* bsum,const int* toks,
    __half* buf2,__half* buf3,int row0,int g,int tig){
  __half* dst=gate?buf3:buf2;
  int ns=(un<6)?2:1;
  #pragma unroll
  for(int s=0;s<ns;s++){
    int c=un*16+8*s+2*tig, gc=gate*100+c;
    float2 bs=*(const float2*)&bsum[gc];
    #pragma unroll
    for(int h2=0;h2<2;h2++){
      int r=row0+g+8*h2;
      float2 w=__half22float2(*(const __half2*)&wih[toks[r]*WIHST+gc]);
      *(__half2*)&dst[r*104+c]=__floats2half2_rn(sigm(d2[s][2*h2]+w.x+bs.x),sigm(d2[s][2*h2+1]+w.y+bs.y));
    }
  }
}

// interval A of encoder step: rz(t) (+ ha(t-1) if do_ha). One shared ldA7.
__device__ __forceinline__ void enc_passA(u32 fcA_sm,int row0,int acol,u32 whh_sm,u32 aw_sm,
    const __half* wih,const float* bsum,const int* toks,
    __half* buf2,__half* buf3,int tprev,int blk0,int wlocal,int lane,bool do_ha){
  int g=lane>>2,tig=lane&3;
  u32 Af[7][4]; ldA7(Af,fcA_sm,row0,acol,lane);
  int nunits=do_ha?21:14;
  for(int u=wlocal;u<nunits;u+=4){
    float d2[2][4]={{0,0,0,0},{0,0,0,0}};
    if(u<14){
      int gate=u/7, un=u-7*gate;
      unit_mma(Af,whh_sm+(u32)(gate*GSZ*2),WST,un,d2,lane);
      rz_epi(gate,un,d2,wih,bsum,toks,buf2,buf3,row0,g,tig);
    }else{
      int un=u-14;
      unit_mma(Af,aw_sm,WST,un,d2,lane);
      int ns=(un<6)?2:1;
      #pragma unroll
      for(int s=0;s<ns;s++){
        int c=un*16+8*s+2*tig;
        #pragma unroll
        for(int h2=0;h2<2;h2++){
          int r=row0+g+8*h2;
          int bb=min(blk0+(r>>2),BATCH-1);
          *(__half2*)&g_HA[((size_t)(bb*J+(r&3))*TIN+tprev)*HP+c]=__floats2half2_rn(d2[s][2*h2],d2[s][2*h2+1]);
        }
      }
    }
  }
}

__device__ __forceinline__ void gru_n_units(u32 fcA_sm,int row0,int acol,u32 whh_sm,
    const __half* wih,const float* bih,const float* bhh,const int* toks,
    const __half* buf2,const __half* buf3,float* hm,__half* hcol,
    bool wgh,int t,int blk0,int wlocal,int lane){
  int g=lane>>2,tig=lane&3;
  u32 Af[7][4]; ldA7(Af,fcA_sm,row0,acol,lane);
  for(int un=wlocal;un<7;un+=4){
    float d2[2][4]={{0,0,0,0},{0,0,0,0}};
    unit_mma(Af,whh_sm+(u32)(2*GSZ*2),WST,un,d2,lane);
    int ns=(un<6)?2:1;
    #pragma unroll
    for(int s=0;s<ns;s++){
      int c=un*16+8*s+2*tig, gc=200+c;
      float2 bi=*(const float2*)&bih[gc], bh=*(const float2*)&bhh[gc];
      #pragma unroll
      for(int h2=0;h2<2;h2++){
        int r=row0+g+8*h2;
        float2 w=__half22float2(*(const __half2*)&wih[toks[r]*WIHST+gc]);
        float2 rr=__half22float2(*(const __half2*)&buf2[r*104+c]);
        float2 zz=__half22float2(*(const __half2*)&buf3[r*104+c]);
        float n0=tanh_f(w.x+bi.x+rr.x*(d2[s][2*h2]+bh.x));
        float n1=tanh_f(w.y+bi.y+rr.y*(d2[s][2*h2+1]+bh.y));
        float2 ho=*(const float2*)&hm[r*104+c];
        float2 hn; hn.x=(1.f-zz.x)*n0+zz.x*ho.x; hn.y=(1.f-zz.y)*n1+zz.y*ho.y;
        *(float2*)&hm[r*104+c]=hn;
        *(__half2*)&hcol[r*FCA+c]=__floats2half2_rn(hn.x,hn.y);
        if(wgh){int bb=min(blk0+(r>>2),BATCH-1);
          *(float2*)&g_H[((size_t)(bb*J+(r&3))*TIN+t)*HP+c]=hn;}
      }
    }
  }
}

// decoder interval A: rz (on c, acol=112) + fc (both halves)
__device__ __forceinline__ void dec_passA(u32 fcA_sm,int row0,u32 whh_sm,u32 wb2_sm,
    const __half* wih,const float* bsum,const float* wbb,const int* toks,
    __half* buf1,__half* buf2,__half* buf3,int wlocal,int lane){
  int g=lane>>2,tig=lane&3;
  u32 Af1[7][4]; ldA7(Af1,fcA_sm,row0,112,lane);
  for(int u=wlocal;u<21;u+=4){
    float d2[2][4]={{0,0,0,0},{0,0,0,0}};
    if(u<14){
      int gate=u/7, un=u-7*gate;
      unit_mma(Af1,whh_sm+(u32)(gate*GSZ*2),WST,un,d2,lane);
      rz_epi(gate,un,d2,wih,bsum,toks,buf2,buf3,row0,g,tig);
    }else{
      int un=u-14;
      unit_mma(Af1,wb2_sm+(u32)(112*2),WWBST,un,d2,lane);
      u32 Af0[7][4]; ldA7(Af0,fcA_sm,row0,0,lane);
      unit_mma(Af0,wb2_sm,WWBST,un,d2,lane);
      int ns=(un<6)?2:1;
      #pragma unroll
      for(int s=0;s<ns;s++){
        int c=un*16+8*s+2*tig;
        float2 wb=*(const float2*)&wbb[c];
        #pragma unroll
        for(int h2=0;h2<2;h2++){
          int r=row0+g+8*h2;
          *(__half2*)&buf1[r*104+c]=__floats2half2_rn(tanh_f(d2[s][2*h2]+wb.x),tanh_f(d2[s][2*h2+1]+wb.y));
        }
      }
    }
  }
}

__global__ void __launch_bounds__(NTHREADS,1)
fused_kernel(const int* __restrict__ inputs, const int* __restrict__ target,
             const float* __restrict__ eWih, const float* __restrict__ eWhh,
             const float* __restrict__ ebih, const float* __restrict__ ebhh,
             const float* __restrict__ dWih, const float* __restrict__ dWhh,
             const float* __restrict__ dbih, const float* __restrict__ dbhh,
             const float* __restrict__ Ww,  const float* __restrict__ Wb,
             const float* __restrict__ Vw,  const float* __restrict__ Vb,
             const float* __restrict__ Aw,  float* __restrict__ out)
{
    extern __shared__ char smx[];
    __half* whh =(__half*)(smx+OFF_WHH);
    __half* wb2 =(__half*)(smx+OFF_WB2);
    __half* wih =(__half*)(smx+OFF_WIH);
    float*  vwf =(float*)(smx+OFF_VW);
    float*  bih =(float*)(smx+OFF_BIH);
    float*  bhh =(float*)(smx+OFF_BHH);
    float*  bsum=(float*)(smx+OFF_BSUM);
    float*  wbb =(float*)(smx+OFF_WBB);
    float*  vbb =(float*)(smx+OFF_VB);
    __half* fcA =(__half*)(smx+OFF_FCAB);
    float*  hm  =(float*)(smx+OFF_HM);
    __half* buf1=(__half*)(smx+OFF_BUF1);
    __half* buf2=(__half*)(smx+OFF_BUF2);
    __half* buf3=(__half*)(smx+OFF_BUF3);
    float*  scb =(float*)(smx+OFF_SC);
    int*    toks=(int*)(smx+OFF_TOK);

    const u32 fcA_sm=smaddr(fcA), whh_sm=smaddr(whh), wb2_sm=smaddr(wb2);
    const int tid=threadIdx.x, warp=tid>>5, lane=tid&31;
    const int wg=warp>>2, wlocal=warp&3, row0=wg*16;
    const int blk0=blockIdx.x*NWARP;
    const int b=min(blk0+warp,BATCH-1);
    const int e0=2*lane, e1=64+2*lane;
    const bool m1=(lane<18);

    // ---- encoder weight load + token preload ----
    for(int i=tid;i<3*GSZ;i+=NTHREADS){
        int gate=i/GSZ, rem=i-gate*GSZ, n=rem/WST, k=rem-n*WST;
        whh[i]=(n<100&&k<100)?__float2half(eWhh[(gate*100+n)*100+k]):__half(0.f);
    }
    for(int i=tid;i<104*WST;i+=NTHREADS){
        int f=i/WST,e=i-f*WST;
        wb2[i]=(f<100&&e<100)?__float2half(Aw[e*100+f]):__half(0.f);
    }
    for(int i=tid;i<11*WIHST;i+=NTHREADS){
        int v=i/WIHST,gg=i-v*WIHST;
        wih[i]=(gg<300)?__float2half(eWih[gg*11+v]):__half(0.f);
    }
    for(int i=tid;i<304;i+=NTHREADS){
        float a=(i<300)?ebih[i]:0.f, c=(i<300)?ebhh[i]:0.f;
        bih[i]=a; bhh[i]=c; bsum[i]=a+c;
    }
    for(int i=tid;i<MROWS*FCA/2;i+=NTHREADS) ((u32*)fcA)[i]=0u;
    for(int i=tid;i<MROWS*104;i+=NTHREADS) hm[i]=0.f;
    int* toks2=(int*)scb;   // [TIN][MROWS] reuses score scratch during encoder
    for(int i=tid;i<TIN*MROWS;i+=NTHREADS){
        int t=i/MROWS, r=i-t*MROWS;
        int bb=min(blk0+(r>>2),BATCH-1);
        toks2[i]=inputs[((r&3)*TIN+t)*BATCH+bb];
    }
    __syncthreads();

    // ---- encoder: 2 wg-barriers per step ----
    for(int t=0;t<TIN;t++){
        int rcol=(t&1)?112:0, wcol=112-rcol;
        enc_passA(fcA_sm,row0,rcol,whh_sm,wb2_sm,wih,bsum,&toks2[t*MROWS],
                  buf2,buf3,t-1,blk0,wlocal,lane,t>0);
        BARWG();
        gru_n_units(fcA_sm,row0,rcol,whh_sm,wih,bih,bhh,&toks2[t*MROWS],
                    buf2,buf3,hm,fcA+wcol,true,t,blk0,wlocal,lane);
        BARWG();
    }
    {   // final HA(9): h(9) lives at col 0
        int g=lane>>2,tig=lane&3;
        u32 Af[7][4]; ldA7(Af,fcA_sm,row0,0,lane);
        for(int un=wlocal;un<7;un+=4){
            float d2[2][4]={{0,0,0,0},{0,0,0,0}};
            unit_mma(Af,wb2_sm,WST,un,d2,lane);
            int ns=(un<6)?2:1;
            #pragma unroll
            for(int s=0;s<ns;s++){
                int c=un*16+8*s+2*tig;
                #pragma unroll
                for(int h2=0;h2<2;h2++){
                    int r=row0+g+8*h2;
                    int bb=min(blk0+(r>>2),BATCH-1);
                    *(__half2*)&g_HA[((size_t)(bb*J+(r&3))*TIN+(TIN-1))*HP+c]=__floats2half2_rn(d2[s][2*h2],d2[s][2*h2+1]);
                }
            }
        }
    }
    __syncthreads();

    // ---- decoder weight load ----
    for(int i=tid;i<3*GSZ;i+=NTHREADS){
        int gate=i/GSZ, rem=i-gate*GSZ, n=rem/WST, k=rem-n*WST;
        whh[i]=(n<100&&k<100)?__float2half(dWhh[(gate*100+n)*100+k]):__half(0.f);
    }
    for(int i=tid;i<104*WWBST;i+=NTHREADS){
        int e=i/WWBST, kk=i-e*WWBST;
        float v=0.f;
        if(e<100){ if(kk<100) v=Ww[e*200+kk]; else if(kk>=112&&kk<212) v=Ww[e*200+kk-12]; }
        wb2[i]=__float2half(v);
    }
    for(int i=tid;i<11*WIHST;i+=NTHREADS){
        int v=i/WIHST,gg=i-v*WIHST;
        wih[i]=(gg<300)?__float2half(dWih[gg*11+v]):__half(0.f);
    }
    for(int i=tid;i<304;i+=NTHREADS){
        float a=(i<300)?dbih[i]:0.f, c=(i<300)?dbhh[i]:0.f;
        bih[i]=a; bhh[i]=c; bsum[i]=a+c;
    }
    for(int i=tid;i<11*104;i+=NTHREADS){int v=i/104,e=i-v*104; vwf[i]=(e<100)?Vw[v*100+e]:0.f;}
    for(int i=tid;i<104;i+=NTHREADS) wbb[i]=(i<100)?Wb[i]:0.f;
    for(int i=tid;i<16;i+=NTHREADS) vbb[i]=(i<VDIM)?Vb[i]:0.f;
    for(int i=tid;i<MROWS*112;i+=NTHREADS){int r=i/112,c=i-r*112; fcA[r*FCA+112+c]=fcA[r*FCA+c];}
    if(tid<MROWS) toks[tid]=VDIM-1;
    __syncthreads();

    // init P0 = GRU(SOS, h_last): hidden mirror in region1, hm holds h_last
    enc_passA(fcA_sm,row0,112,whh_sm,wb2_sm,wih,bsum,toks,buf2,buf3,0,blk0,wlocal,lane,false);
    BARWG();
    gru_n_units(fcA_sm,row0,112,whh_sm,wih,bih,bhh,toks,buf2,buf3,hm,fcA,false,0,blk0,wlocal,lane);
    BARWG();

    float score=0.f;
    float* sc=&scb[warp*40];
    for(int t=0;t<TOUT;t++){
        // ---- scores = HA . P (vectorized int4) ----
        {
            int j=lane/10, tt=lane-10*j;
            const int4* hap=(const int4*)&g_HA[((size_t)(b*J+j)*TIN+tt)*HP];
            const int4* pj =(const int4*)&fcA[(warp*J+j)*FCA];
            float accs=0.f;
            #pragma unroll 13
            for(int q=0;q<13;q++){
                int4 hv=hap[q], pv4=pj[q];
                float2 h0=__half22float2(*(__half2*)&hv.x), p0=__half22float2(*(__half2*)&pv4.x);
                float2 h1=__half22float2(*(__half2*)&hv.y), p1=__half22float2(*(__half2*)&pv4.y);
                float2 h2=__half22float2(*(__half2*)&hv.z), p2=__half22float2(*(__half2*)&pv4.z);
                float2 h3=__half22float2(*(__half2*)&hv.w), p3=__half22float2(*(__half2*)&pv4.w);
                accs=fmaf(h0.x,p0.x,accs); accs=fmaf(h0.y,p0.y,accs);
                accs=fmaf(h1.x,p1.x,accs); accs=fmaf(h1.y,p1.y,accs);
                accs=fmaf(h2.x,p2.x,accs); accs=fmaf(h2.y,p2.y,accs);
                accs=fmaf(h3.x,p3.x,accs); accs=fmaf(h3.y,p3.y,accs);
            }
            sc[lane]=accs;
            if(lane<8){
                int t2=32+lane, j2=t2/10, tt2=t2-10*j2;
                const int4* hap2=(const int4*)&g_HA[((size_t)(b*J+j2)*TIN+tt2)*HP];
                const int4* pj2 =(const int4*)&fcA[(warp*J+j2)*FCA];
                float a2=0.f;
                #pragma unroll 13
                for(int q=0;q<13;q++){
                    int4 hv=hap2[q], pv4=pj2[q];
                    float2 h0=__half22float2(*(__half2*)&hv.x), p0=__half22float2(*(__half2*)&pv4.x);
                    float2 h1=__half22float2(*(__half2*)&hv.y), p1=__half22float2(*(__half2*)&pv4.y);
                    float2 h2=__half22float2(*(__half2*)&hv.z), p2=__half22float2(*(__half2*)&pv4.z);
                    float2 h3=__half22float2(*(__half2*)&hv.w), p3=__half22float2(*(__half2*)&pv4.w);
                    a2=fmaf(h0.x,p0.x,a2); a2=fmaf(h0.y,p0.y,a2);
                    a2=fmaf(h1.x,p1.x,a2); a2=fmaf(h1.y,p1.y,a2);
                    a2=fmaf(h2.x,p2.x,a2); a2=fmaf(h2.y,p2.y,a2);
                    a2=fmaf(h3.x,p3.x,a2); a2=fmaf(h3.y,p3.y,a2);
                }
                sc[t2]=a2;
            }
        }
        __syncwarp();
        if(lane<J){
            float mx=-1e30f;
            #pragma unroll
            for(int tt=0;tt<TIN;tt++) mx=fmaxf(mx,sc[lane*10+tt]);
            float s=0.f;
            #pragma unroll
            for(int tt=0;tt<TIN;tt++) s+=__expf(sc[lane*10+tt]-mx);
            float lg=__logf(s)+mx;
            #pragma unroll
            for(int tt=0;tt<TIN;tt++) sc[lane*10+tt]-=lg;
        }
        __syncwarp();
        // ---- c = logs . H (float4 per lane, lanes 0-24) ----
        if(lane<25){
            #pragma unroll
            for(int j=0;j<J;j++){
                const float* hb=&g_H[((size_t)(b*J+j)*TIN)*HP + 4*lane];
                float4 acc; acc.x=0.f; acc.y=0.f; acc.z=0.f; acc.w=0.f;
                #pragma unroll
                for(int tt=0;tt<TIN;tt++){
                    float lg=sc[j*10+tt];
                    float4 h4=*(const float4*)(hb+tt*HP);
                    acc.x=fmaf(lg,h4.x,acc.x); acc.y=fmaf(lg,h4.y,acc.y);
                    acc.z=fmaf(lg,h4.z,acc.z); acc.w=fmaf(lg,h4.w,acc.w);
                }
                int r=warp*J+j;
                *(float4*)&hm[r*104+4*lane]=acc;
                __half2 p0=__floats2half2_rn(acc.x,acc.y), p1=__floats2half2_rn(acc.z,acc.w);
                uint2 pk; pk.x=*(u32*)&p0; pk.y=*(u32*)&p1;
                *(uint2*)&fcA[r*FCA+112+4*lane]=pk;
            }
        }
        if(lane<J) toks[warp*J+lane]=target[t*BATCH+b];
        BARWG();
        // ---- pass A: fc + rz ----
        dec_passA(fcA_sm,row0,whh_sm,wb2_sm,wih,bsum,wbb,toks,buf1,buf2,buf3,wlocal,lane);
        BARWG();
        // ---- pass B: logits + gru_n ----
        {
            float2 mA; mA.x=-1e30f; mA.y=-1e30f; float2 mB=mA;
            #pragma unroll
            for(int j=0;j<J;j++){
                int r=warp*J+j;
                float2 fA=__half22float2(*(const __half2*)&buf1[r*104+e0]);
                mA.x=fmaxf(mA.x,fA.x); mA.y=fmaxf(mA.y,fA.y);
                if(m1){float2 fB=__half22float2(*(const __half2*)&buf1[r*104+e1]);
                    mB.x=fmaxf(mB.x,fB.x); mB.y=fmaxf(mB.y,fB.y);}
            }
            float pv[VDIM];
            #pragma unroll
            for(int v=0;v<VDIM;v++){
                const float* vr=&vwf[v*104];
                float p=vr[e0]*mA.x+vr[e0+1]*mA.y;
                if(m1){p=fmaf(vr[e1],mB.x,p); p=fmaf(vr[e1+1],mB.y,p);}
                pv[v]=p;
            }
            #pragma unroll
            for(int off=16;off>=1;off>>=1){
                #pragma unroll
                for(int v=0;v<VDIM;v++) pv[v]+=__shfl_xor_sync(0xffffffffu,pv[v],off);
            }
            int tok=target[t*BATCH+b];
            float mx=-1e30f;
            #pragma unroll
            for(int v=0;v<VDIM;v++){pv[v]+=vbb[v]; mx=fmaxf(mx,pv[v]);}
            float ss=0.f;
            #pragma unroll
            for(int v=0;v<VDIM;v++) ss+=__expf(pv[v]-mx);
            score+=pv[tok]-mx-__logf(ss);
        }
        gru_n_units(fcA_sm,row0,112,whh_sm,wih,bih,bhh,toks,buf2,buf3,hm,fcA,false,0,blk0,wlocal,lane);
        BARWG();
    }
    if(lane==0) out[b]=score;
}

extern "C" void kernel_launch(void* const* d_in, const int* in_sizes, int n_in,
                              void* d_out, int out_size)
{
    cudaFuncSetAttribute(fused_kernel, cudaFuncAttributeMaxDynamicSharedMemorySize, SMEM_BYTES);
    int grid=(BATCH+NWARP-1)/NWARP;  // 512
    fused_kernel<<<grid, NTHREADS, SMEM_BYTES>>>(
        (const int*)d_in[0], (const int*)d_in[1],
        (const float*)d_in[2], (const float*)d_in[3], (const float*)d_in[4], (const float*)d_in[5],
        (const float*)d_in[6], (const float*)d_in[7], (const float*)d_in[8], (const float*)d_in[9],
        (const float*)d_in[10], (const float*)d_in[11], (const float*)d_in[12], (const float*)d_in[13],
        (const float*)d_in[14], (float*)d_out);
}

// round 9
// speedup vs baseline: 3.1394x; 1.0537x over previous
#include <cuda_runtime.h>
#include <cuda_fp16.h>
#include <cstdint>

#define J 4
#define BATCH 8192
#define TIN 10
#define TOUT 10
#define VDIM 11
#define NWARP 16
#define NTHREADS 512
#define MROWS 64
typedef unsigned long long u64;
typedef uint32_t u32;

#define FCA 232
#define WST 104
#define GSZ (104*104)
#define WWBST 232
#define WIHST 304
#define HP 104

// smem byte offsets
#define OFF_WHH   0
#define OFF_WB2   64896
#define OFF_WIH   113152
#define OFF_VW    119840
#define OFF_BIH   124416
#define OFF_BHH   125632
#define OFF_BSUM  126848
#define OFF_WBB   128064
#define OFF_VB    128480
#define OFF_FCAB  128544
#define OFF_HM    158240
#define OFF_BUF1  184864
#define OFF_BUF2  198176
#define OFF_BUF3  211488
#define OFF_SC    224800
#define OFF_TOK   227360
#define SMEM_BYTES 227616

__device__ float  g_H [(size_t)J*BATCH*TIN*HP];
__device__ __half g_HA[(size_t)J*BATCH*TIN*HP];

__device__ __forceinline__ u32 smaddr(const void* p){ u32 a; asm("{.reg .u64 t; cvta.to.shared.u64 t, %1; cvt.u32.u64 %0, t;}":"=r"(a):"l"(p)); return a; }
__device__ __forceinline__ __half2 tanh_h2(__half2 x){
  __half2 r; asm("tanh.approx.f16x2 %0, %1;":"=r"(*(u32*)&r):"r"(*(u32*)&x)); return r;
}
// packed sigmoid via tanh: sig(x)=0.5*tanh(0.5x)+0.5
__device__ __forceinline__ __half2 sigm_h2(float a, float b){
  __half2 t=tanh_h2(__floats2half2_rn(0.5f*a,0.5f*b));
  const __half2 hh=__floats2half2_rn(0.5f,0.5f);
  return __hfma2(t,hh,hh);
}
__device__ __forceinline__ __half2 tanh2f(float a, float b){
  return tanh_h2(__floats2half2_rn(a,b));
}
__device__ __forceinline__ void ldsm4(u32&a0,u32&a1,u32&a2,u32&a3,u32 ad){
  asm volatile("ldmatrix.sync.aligned.m8n8.x4.shared.b16 {%0,%1,%2,%3},[%4];":"=r"(a0),"=r"(a1),"=r"(a2),"=r"(a3):"r"(ad));
}
__device__ __forceinline__ void ldsm2(u32&b0,u32&b1,u32 ad){
  asm volatile("ldmatrix.sync.aligned.m8n8.x2.shared.b16 {%0,%1},[%2];":"=r"(b0),"=r"(b1):"r"(ad));
}
__device__ __forceinline__ void mma_(float d[4], const u32 a[4], u32 b0,u32 b1){
  asm("mma.sync.aligned.m16n8k16.row.col.f32.f16.f16.f32 {%0,%1,%2,%3},{%4,%5,%6,%7},{%8,%9},{%0,%1,%2,%3};"
   :"+f"(d[0]),"+f"(d[1]),"+f"(d[2]),"+f"(d[3]):"r"(a[0]),"r"(a[1]),"r"(a[2]),"r"(a[3]),"r"(b0),"r"(b1));
}
#define BARWG() asm volatile("bar.sync %0, 128;"::"r"(wg+1):"memory")

__device__ __forceinline__ void ldA7(u32 Af[7][4], u32 fcA_sm, int row0, int acol, int lane){
  int arow=row0+(lane&7)+((lane&8)?8:0);
  u32 base=fcA_sm+(u32)((arow*FCA+acol+((lane&16)?8:0))*2);
  #pragma unroll
  for(int kt=0;kt<7;kt++) ldsm4(Af[kt][0],Af[kt][1],Af[kt][2],Af[kt][3],base+kt*32u);
}

__device__ __forceinline__ void unit_mma(const u32 Af[7][4], u32 bbase, int bst,
                                         int un, float d2[2][4], int lane){
  if(un<6){
    int row=un*16+(lane&7)+((lane&16)?8:0);
    u32 ba=bbase+(u32)((row*bst+((lane&8)?8:0))*2);
    #pragma unroll
    for(int kt=0;kt<7;kt++){
      u32 b0,b1,b2,b3; ldsm4(b0,b1,b2,b3,ba+kt*32u);
      mma_(d2[0],Af[kt],b0,b1); mma_(d2[1],Af[kt],b2,b3);
    }
  }else{
    int l16=lane&15;
    u32 ba=bbase+(u32)(((96+(l16&7))*bst+((l16&8)?8:0))*2);
    #pragma unroll
    for(int kt=0;kt<7;kt++){ u32 b0,b1; ldsm2(b0,b1,ba+kt*32u); mma_(d2[0],Af[kt],b0,b1); }
  }
}

__device__ __forceinline__ void rz_epi(int gate,int un,float d2[2][4],
    const __half* wih,const float* bsum,const int* toks,
    __half* buf2,__half* buf3,int row0,int g,int tig){
  __half* dst=gate?buf3:buf2;
  int ns=(un<6)?2:1;
  #pragma unroll
  for(int s=0;s<ns;s++){
    int c=un*16+8*s+2*tig, gc=gate*100+c;
    float2 bs=*(const float2*)&bsum[gc];
    #pragma unroll
    for(int h2=0;h2<2;h2++){
      int r=row0+g+8*h2;
      float2 w=__half22float2(*(const __half2*)&wih[toks[r]*WIHST+gc]);
      *(__half2*)&dst[r*104+c]=sigm_h2(d2[s][2*h2]+w.x+bs.x, d2[s][2*h2+1]+w.y+bs.y);
    }
  }
}

__device__ __forceinline__ void enc_passA(u32 fcA_sm,int row0,int acol,u32 whh_sm,u32 aw_sm,
    const __half* wih,const float* bsum,const int* toks,
    __half* buf2,__half* buf3,int tprev,int blk0,int wlocal,int lane,bool do_ha){
  int g=lane>>2,tig=lane&3;
  u32 Af[7][4]; ldA7(Af,fcA_sm,row0,acol,lane);
  int nunits=do_ha?21:14;
  for(int u=wlocal;u<nunits;u+=4){
    float d2[2][4]={{0,0,0,0},{0,0,0,0}};
    if(u<14){
      int gate=u/7, un=u-7*gate;
      unit_mma(Af,whh_sm+(u32)(gate*GSZ*2),WST,un,d2,lane);
      rz_epi(gate,un,d2,wih,bsum,toks,buf2,buf3,row0,g,tig);
    }else{
      int un=u-14;
      unit_mma(Af,aw_sm,WST,un,d2,lane);
      int ns=(un<6)?2:1;
      #pragma unroll
      for(int s=0;s<ns;s++){
        int c=un*16+8*s+2*tig;
        #pragma unroll
        for(int h2=0;h2<2;h2++){
          int r=row0+g+8*h2;
          int bb=min(blk0+(r>>2),BATCH-1);
          *(__half2*)&g_HA[((size_t)(bb*J+(r&3))*TIN+tprev)*HP+c]=__floats2half2_rn(d2[s][2*h2],d2[s][2*h2+1]);
        }
      }
    }
  }
}

__device__ __forceinline__ void gru_n_units(u32 fcA_sm,int row0,int acol,u32 whh_sm,
    const __half* wih,const float* bih,const float* bhh,const int* toks,
    const __half* buf2,const __half* buf3,float* hm,__half* hcol,
    bool wgh,int t,int blk0,int wlocal,int lane){
  int g=lane>>2,tig=lane&3;
  u32 Af[7][4]; ldA7(Af,fcA_sm,row0,acol,lane);
  for(int un=wlocal;un<7;un+=4){
    float d2[2][4]={{0,0,0,0},{0,0,0,0}};
    unit_mma(Af,whh_sm+(u32)(2*GSZ*2),WST,un,d2,lane);
    int ns=(un<6)?2:1;
    #pragma unroll
    for(int s=0;s<ns;s++){
      int c=un*16+8*s+2*tig, gc=200+c;
      float2 bi=*(const float2*)&bih[gc], bh=*(const float2*)&bhh[gc];
      #pragma unroll
      for(int h2=0;h2<2;h2++){
        int r=row0+g+8*h2;
        float2 w=__half22float2(*(const __half2*)&wih[toks[r]*WIHST+gc]);
        float2 rr=__half22float2(*(const __half2*)&buf2[r*104+c]);
        float2 zz=__half22float2(*(const __half2*)&buf3[r*104+c]);
        __half2 nh=tanh2f(w.x+bi.x+rr.x*(d2[s][2*h2]+bh.x),
                          w.y+bi.y+rr.y*(d2[s][2*h2+1]+bh.y));
        float2 nn=__half22float2(nh);
        float2 ho=*(const float2*)&hm[r*104+c];
        float2 hn; hn.x=(1.f-zz.x)*nn.x+zz.x*ho.x; hn.y=(1.f-zz.y)*nn.y+zz.y*ho.y;
        *(float2*)&hm[r*104+c]=hn;
        *(__half2*)&hcol[r*FCA+c]=__floats2half2_rn(hn.x,hn.y);
        if(wgh){int bb=min(blk0+(r>>2),BATCH-1);
          *(float2*)&g_H[((size_t)(bb*J+(r&3))*TIN+t)*HP+c]=hn;}
      }
    }
  }
}

__device__ __forceinline__ void dec_passA(u32 fcA_sm,int row0,u32 whh_sm,u32 wb2_sm,
    const __half* wih,const float* bsum,const float* wbb,const int* toks,
    __half* buf1,__half* buf2,__half* buf3,int wlocal,int lane){
  int g=lane>>2,tig=lane&3;
  u32 Af1[7][4]; ldA7(Af1,fcA_sm,row0,112,lane);
  for(int u=wlocal;u<21;u+=4){
    float d2[2][4]={{0,0,0,0},{0,0,0,0}};
    if(u<14){
      int gate=u/7, un=u-7*gate;
      unit_mma(Af1,whh_sm+(u32)(gate*GSZ*2),WST,un,d2,lane);
      rz_epi(gate,un,d2,wih,bsum,toks,buf2,buf3,row0,g,tig);
    }else{
      int un=u-14;
      unit_mma(Af1,wb2_sm+(u32)(112*2),WWBST,un,d2,lane);
      u32 Af0[7][4]; ldA7(Af0,fcA_sm,row0,0,lane);
      unit_mma(Af0,wb2_sm,WWBST,un,d2,lane);
      int ns=(un<6)?2:1;
      #pragma unroll
      for(int s=0;s<ns;s++){
        int c=un*16+8*s+2*tig;
        float2 wb=*(const float2*)&wbb[c];
        #pragma unroll
        for(int h2=0;h2<2;h2++){
          int r=row0+g+8*h2;
          *(__half2*)&buf1[r*104+c]=tanh2f(d2[s][2*h2]+wb.x, d2[s][2*h2+1]+wb.y);
        }
      }
    }
  }
}

__global__ void __launch_bounds__(NTHREADS,1)
fused_kernel(const int* __restrict__ inputs, const int* __restrict__ target,
             const float* __restrict__ eWih, const float* __restrict__ eWhh,
             const float* __restrict__ ebih, const float* __restrict__ ebhh,
             const float* __restrict__ dWih, const float* __restrict__ dWhh,
             const float* __restrict__ dbih, const float* __restrict__ dbhh,
             const float* __restrict__ Ww,  const float* __restrict__ Wb,
             const float* __restrict__ Vw,  const float* __restrict__ Vb,
             const float* __restrict__ Aw,  float* __restrict__ out)
{
    extern __shared__ char smx[];
    __half* whh =(__half*)(smx+OFF_WHH);
    __half* wb2 =(__half*)(smx+OFF_WB2);
    __half* wih =(__half*)(smx+OFF_WIH);
    float*  vwf =(float*)(smx+OFF_VW);
    float*  bih =(float*)(smx+OFF_BIH);
    float*  bhh =(float*)(smx+OFF_BHH);
    float*  bsum=(float*)(smx+OFF_BSUM);
    float*  wbb =(float*)(smx+OFF_WBB);
    float*  vbb =(float*)(smx+OFF_VB);
    __half* fcA =(__half*)(smx+OFF_FCAB);
    float*  hm  =(float*)(smx+OFF_HM);
    __half* buf1=(__half*)(smx+OFF_BUF1);
    __half* buf2=(__half*)(smx+OFF_BUF2);
    __half* buf3=(__half*)(smx+OFF_BUF3);
    float*  scb =(float*)(smx+OFF_SC);
    int*    toks=(int*)(smx+OFF_TOK);

    const u32 fcA_sm=smaddr(fcA), whh_sm=smaddr(whh), wb2_sm=smaddr(wb2);
    const int tid=threadIdx.x, warp=tid>>5, lane=tid&31;
    const int wg=warp>>2, wlocal=warp&3, row0=wg*16;
    const int blk0=blockIdx.x*NWARP;
    const int b=min(blk0+warp,BATCH-1);
    const int e0=2*lane, e1=64+2*lane;
    const bool m1=(lane<18);

    for(int i=tid;i<3*GSZ;i+=NTHREADS){
        int gate=i/GSZ, rem=i-gate*GSZ, n=rem/WST, k=rem-n*WST;
        whh[i]=(n<100&&k<100)?__float2half(eWhh[(gate*100+n)*100+k]):__half(0.f);
    }
    for(int i=tid;i<104*WST;i+=NTHREADS){
        int f=i/WST,e=i-f*WST;
        wb2[i]=(f<100&&e<100)?__float2half(Aw[e*100+f]):__half(0.f);
    }
    for(int i=tid;i<11*WIHST;i+=NTHREADS){
        int v=i/WIHST,gg=i-v*WIHST;
        wih[i]=(gg<300)?__float2half(eWih[gg*11+v]):__half(0.f);
    }
    for(int i=tid;i<304;i+=NTHREADS){
        float a=(i<300)?ebih[i]:0.f, c=(i<300)?ebhh[i]:0.f;
        bih[i]=a; bhh[i]=c; bsum[i]=a+c;
    }
    for(int i=tid;i<MROWS*FCA/2;i+=NTHREADS) ((u32*)fcA)[i]=0u;
    for(int i=tid;i<MROWS*104;i+=NTHREADS) hm[i]=0.f;
    int* toks2=(int*)scb;
    for(int i=tid;i<TIN*MROWS;i+=NTHREADS){
        int t=i/MROWS, r=i-t*MROWS;
        int bb=min(blk0+(r>>2),BATCH-1);
        toks2[i]=inputs[((r&3)*TIN+t)*BATCH+bb];
    }
    __syncthreads();

    for(int t=0;t<TIN;t++){
        int rcol=(t&1)?112:0, wcol=112-rcol;
        enc_passA(fcA_sm,row0,rcol,whh_sm,wb2_sm,wih,bsum,&toks2[t*MROWS],
                  buf2,buf3,t-1,blk0,wlocal,lane,t>0);
        BARWG();
        gru_n_units(fcA_sm,row0,rcol,whh_sm,wih,bih,bhh,&toks2[t*MROWS],
                    buf2,buf3,hm,fcA+wcol,true,t,blk0,wlocal,lane);
        BARWG();
    }
    {
        int g=lane>>2,tig=lane&3;
        u32 Af[7][4]; ldA7(Af,fcA_sm,row0,0,lane);
        for(int un=wlocal;un<7;un+=4){
            float d2[2][4]={{0,0,0,0},{0,0,0,0}};
            unit_mma(Af,wb2_sm,WST,un,d2,lane);
            int ns=(un<6)?2:1;
            #pragma unroll
            for(int s=0;s<ns;s++){
                int c=un*16+8*s+2*tig;
                #pragma unroll
                for(int h2=0;h2<2;h2++){
                    int r=row0+g+8*h2;
                    int bb=min(blk0+(r>>2),BATCH-1);
                    *(__half2*)&g_HA[((size_t)(bb*J+(r&3))*TIN+(TIN-1))*HP+c]=__floats2half2_rn(d2[s][2*h2],d2[s][2*h2+1]);
                }
            }
        }
    }
    __syncthreads();

    for(int i=tid;i<3*GSZ;i+=NTHREADS){
        int gate=i/GSZ, rem=i-gate*GSZ, n=rem/WST, k=rem-n*WST;
        whh[i]=(n<100&&k<100)?__float2half(dWhh[(gate*100+n)*100+k]):__half(0.f);
    }
    for(int i=tid;i<104*WWBST;i+=NTHREADS){
        int e=i/WWBST, kk=i-e*WWBST;
        float v=0.f;
        if(e<100){ if(kk<100) v=Ww[e*200+kk]; else if(kk>=112&&kk<212) v=Ww[e*200+kk-12]; }
        wb2[i]=__float2half(v);
    }
    for(int i=tid;i<11*WIHST;i+=NTHREADS){
        int v=i/WIHST,gg=i-v*WIHST;
        wih[i]=(gg<300)?__float2half(dWih[gg*11+v]):__half(0.f);
    }
    for(int i=tid;i<304;i+=NTHREADS){
        float a=(i<300)?dbih[i]:0.f, c=(i<300)?dbhh[i]:0.f;
        bih[i]=a; bhh[i]=c; bsum[i]=a+c;
    }
    for(int i=tid;i<11*104;i+=NTHREADS){int v=i/104,e=i-v*104; vwf[i]=(e<100)?Vw[v*100+e]:0.f;}
    for(int i=tid;i<104;i+=NTHREADS) wbb[i]=(i<100)?Wb[i]:0.f;
    for(int i=tid;i<16;i+=NTHREADS) vbb[i]=(i<VDIM)?Vb[i]:0.f;
    for(int i=tid;i<MROWS*112;i+=NTHREADS){int r=i/112,c=i-r*112; fcA[r*FCA+112+c]=fcA[r*FCA+c];}
    if(tid<MROWS) toks[tid]=VDIM-1;
    __syncthreads();

    enc_passA(fcA_sm,row0,112,whh_sm,wb2_sm,wih,bsum,toks,buf2,buf3,0,blk0,wlocal,lane,false);
    BARWG();
    gru_n_units(fcA_sm,row0,112,whh_sm,wih,bih,bhh,toks,buf2,buf3,hm,fcA,false,0,blk0,wlocal,lane);
    BARWG();

    float score=0.f;
    float* sc=&scb[warp*40];
    for(int t=0;t<TOUT;t++){
        {
            int j=lane/10, tt=lane-10*j;
            const int4* hap=(const int4*)&g_HA[((size_t)(b*J+j)*TIN+tt)*HP];
            const int4* pj =(const int4*)&fcA[(warp*J+j)*FCA];
            float accs=0.f;
            #pragma unroll 13
            for(int q=0;q<13;q++){
                int4 hv=hap[q], pv4=pj[q];
                float2 h0=__half22float2(*(__half2*)&hv.x), p0=__half22float2(*(__half2*)&pv4.x);
                float2 h1=__half22float2(*(__half2*)&hv.y), p1=__half22float2(*(__half2*)&pv4.y);
                float2 h2=__half22float2(*(__half2*)&hv.z), p2=__half22float2(*(__half2*)&pv4.z);
                float2 h3=__half22float2(*(__half2*)&hv.w), p3=__half22float2(*(__half2*)&pv4.w);
                accs=fmaf(h0.x,p0.x,accs); accs=fmaf(h0.y,p0.y,accs);
                accs=fmaf(h1.x,p1.x,accs); accs=fmaf(h1.y,p1.y,accs);
                accs=fmaf(h2.x,p2.x,accs); accs=fmaf(h2.y,p2.y,accs);
                accs=fmaf(h3.x,p3.x,accs); accs=fmaf(h3.y,p3.y,accs);
            }
            sc[lane]=accs;
            if(lane<8){
                int t2=32+lane, j2=t2/10, tt2=t2-10*j2;
                const int4* hap2=(const int4*)&g_HA[((size_t)(b*J+j2)*TIN+tt2)*HP];
                const int4* pj2 =(const int4*)&fcA[(warp*J+j2)*FCA];
                float a2=0.f;
                #pragma unroll 13
                for(int q=0;q<13;q++){
                    int4 hv=hap2[q], pv4=pj2[q];
                    float2 h0=__half22float2(*(__half2*)&hv.x), p0=__half22float2(*(__half2*)&pv4.x);
                    float2 h1=__half22float2(*(__half2*)&hv.y), p1=__half22float2(*(__half2*)&pv4.y);
                    float2 h2=__half22float2(*(__half2*)&hv.z), p2=__half22float2(*(__half2*)&pv4.z);
                    float2 h3=__half22float2(*(__half2*)&hv.w), p3=__half22float2(*(__half2*)&pv4.w);
                    a2=fmaf(h0.x,p0.x,a2); a2=fmaf(h0.y,p0.y,a2);
                    a2=fmaf(h1.x,p1.x,a2); a2=fmaf(h1.y,p1.y,a2);
                    a2=fmaf(h2.x,p2.x,a2); a2=fmaf(h2.y,p2.y,a2);
                    a2=fmaf(h3.x,p3.x,a2); a2=fmaf(h3.y,p3.y,a2);
                }
                sc[t2]=a2;
            }
        }
        __syncwarp();
        if(lane<J){
            float mx=-1e30f;
            #pragma unroll
            for(int tt=0;tt<TIN;tt++) mx=fmaxf(mx,sc[lane*10+tt]);
            float s=0.f;
            #pragma unroll
            for(int tt=0;tt<TIN;tt++) s+=__expf(sc[lane*10+tt]-mx);
            float lg=__logf(s)+mx;
            #pragma unroll
            for(int tt=0;tt<TIN;tt++) sc[lane*10+tt]-=lg;
        }
        __syncwarp();
        if(lane<25){
            #pragma unroll
            for(int j=0;j<J;j++){
                const float* hb=&g_H[((size_t)(b*J+j)*TIN)*HP + 4*lane];
                float4 acc; acc.x=0.f; acc.y=0.f; acc.z=0.f; acc.w=0.f;
                #pragma unroll
                for(int tt=0;tt<TIN;tt++){
                    float lg=sc[j*10+tt];
                    float4 h4=*(const float4*)(hb+tt*HP);
                    acc.x=fmaf(lg,h4.x,acc.x); acc.y=fmaf(lg,h4.y,acc.y);
                    acc.z=fmaf(lg,h4.z,acc.z); acc.w=fmaf(lg,h4.w,acc.w);
                }
                int r=warp*J+j;
                *(float4*)&hm[r*104+4*lane]=acc;
                __half2 p0=__floats2half2_rn(acc.x,acc.y), p1=__floats2half2_rn(acc.z,acc.w);
                uint2 pk; pk.x=*(u32*)&p0; pk.y=*(u32*)&p1;
                *(uint2*)&fcA[r*FCA+112+4*lane]=pk;
            }
        }
        if(lane<J) toks[warp*J+lane]=target[t*BATCH+b];
        BARWG();
        dec_passA(fcA_sm,row0,whh_sm,wb2_sm,wih,bsum,wbb,toks,buf1,buf2,buf3,wlocal,lane);
        BARWG();
        {
            float2 mA; mA.x=-1e30f; mA.y=-1e30f; float2 mB=mA;
            #pragma unroll
            for(int j=0;j<J;j++){
                int r=warp*J+j;
                float2 fA=__half22float2(*(const __half2*)&buf1[r*104+e0]);
                mA.x=fmaxf(mA.x,fA.x); mA.y=fmaxf(mA.y,fA.y);
                if(m1){float2 fB=__half22float2(*(const __half2*)&buf1[r*104+e1]);
                    mB.x=fmaxf(mB.x,fB.x); mB.y=fmaxf(mB.y,fB.y);}
            }
            float pv[VDIM];
            #pragma unroll
            for(int v=0;v<VDIM;v++){
                const float* vr=&vwf[v*104];
                float p=vr[e0]*mA.x+vr[e0+1]*mA.y;
                if(m1){p=fmaf(vr[e1],mB.x,p); p=fmaf(vr[e1+1],mB.y,p);}
                pv[v]=p;
            }
            #pragma unroll
            for(int off=16;off>=1;off>>=1){
                #pragma unroll
                for(int v=0;v<VDIM;v++) pv[v]+=__shfl_xor_sync(0xffffffffu,pv[v],off);
            }
            int tok=target[t*BATCH+b];
            float mx=-1e30f;
            #pragma unroll
            for(int v=0;v<VDIM;v++){pv[v]+=vbb[v]; mx=fmaxf(mx,pv[v]);}
            float ss=0.f;
            #pragma unroll
            for(int v=0;v<VDIM;v++) ss+=__expf(pv[v]-mx);
            score+=pv[tok]-mx-__logf(ss);
        }
        gru_n_units(fcA_sm,row0,112,whh_sm,wih,bih,bhh,toks,buf2,buf3,hm,fcA,false,0,blk0,wlocal,lane);
        BARWG();
    }
    if(lane==0) out[b]=score;
}

extern "C" void kernel_launch(void* const* d_in, const int* in_sizes, int n_in,
                              void* d_out, int out_size)
{
    cudaFuncSetAttribute(fused_kernel, cudaFuncAttributeMaxDynamicSharedMemorySize, SMEM_BYTES);
    int grid=(BATCH+NWARP-1)/NWARP;
    fused_kernel<<<grid, NTHREADS, SMEM_BYTES>>>(
        (const int*)d_in[0], (const int*)d_in[1],
        (const float*)d_in[2], (const float*)d_in[3], (const float*)d_in[4], (const float*)d_in[5],
        (const float*)d_in[6], (const float*)d_in[7], (const float*)d_in[8], (const float*)d_in[9],
        (const float*)d_in[10], (const float*)d_in[11], (const float*)d_in[12], (const float*)d_in[13],
        (const float*)d_in[14], (float*)d_out);
}

// round 11
// speedup vs baseline: 3.2283x; 1.0283x over previous
#include <cuda_runtime.h>
#include <cuda_fp16.h>
#include <cstdint>

#define J 4
#define BATCH 8192
#define TIN 10
#define TOUT 10
#define VDIM 11
#define NWARP 16
#define NTHREADS 512
#define MROWS 64
typedef unsigned long long u64;
typedef uint32_t u32;

#define FCA 232
#define WST 104
#define GSZ (104*104)
#define WWBST 232
#define WIHST 304
#define HP 104

#define OFF_WHH   0
#define OFF_WB2   64896
#define OFF_WIH   113152
#define OFF_VW    119840
#define OFF_BIH   124416
#define OFF_BHH   125632
#define OFF_BSUM  126848
#define OFF_WBB   128064
#define OFF_VB    128480
#define OFF_FCAB  128544
#define OFF_HM    158240
#define OFF_BUF1  184864
#define OFF_BUF2  198176
#define OFF_BUF3  211488
#define OFF_SC    224800
#define OFF_TOK   227360
#define SMEM_BYTES 227616

__device__ float  g_H [(size_t)J*BATCH*TIN*HP];
__device__ __half g_HA[(size_t)J*BATCH*TIN*HP];

__device__ __forceinline__ u32 smaddr(const void* p){ u32 a; asm("{.reg .u64 t; cvta.to.shared.u64 t, %1; cvt.u32.u64 %0, t;}":"=r"(a):"l"(p)); return a; }
__device__ __forceinline__ __half2 tanh_h2(__half2 x){
  __half2 r; asm("tanh.approx.f16x2 %0, %1;":"=r"(*(u32*)&r):"r"(*(u32*)&x)); return r;
}
__device__ __forceinline__ __half2 sigm_h2(float a, float b){
  __half2 t=tanh_h2(__floats2half2_rn(0.5f*a,0.5f*b));
  const __half2 hh=__floats2half2_rn(0.5f,0.5f);
  return __hfma2(t,hh,hh);
}
__device__ __forceinline__ __half2 tanh2f(float a, float b){
  return tanh_h2(__floats2half2_rn(a,b));
}
__device__ __forceinline__ void ldsm4(u32&a0,u32&a1,u32&a2,u32&a3,u32 ad){
  asm volatile("ldmatrix.sync.aligned.m8n8.x4.shared.b16 {%0,%1,%2,%3},[%4];":"=r"(a0),"=r"(a1),"=r"(a2),"=r"(a3):"r"(ad));
}
__device__ __forceinline__ void ldsm2(u32&b0,u32&b1,u32 ad){
  asm volatile("ldmatrix.sync.aligned.m8n8.x2.shared.b16 {%0,%1},[%2];":"=r"(b0),"=r"(b1):"r"(ad));
}
__device__ __forceinline__ void mma_(float d[4], const u32 a[4], u32 b0,u32 b1){
  asm("mma.sync.aligned.m16n8k16.row.col.f32.f16.f16.f32 {%0,%1,%2,%3},{%4,%5,%6,%7},{%8,%9},{%0,%1,%2,%3};"
   :"+f"(d[0]),"+f"(d[1]),"+f"(d[2]),"+f"(d[3]):"r"(a[0]),"r"(a[1]),"r"(a[2]),"r"(a[3]),"r"(b0),"r"(b1));
}
#define BARWG() asm volatile("bar.sync %0, 128;"::"r"(wg+1):"memory")

__device__ __forceinline__ void ldA7(u32 Af[7][4], u32 fcA_sm, int row0, int acol, int lane){
  int arow=row0+(lane&7)+((lane&8)?8:0);
  u32 base=fcA_sm+(u32)((arow*FCA+acol+((lane&16)?8:0))*2);
  #pragma unroll
  for(int kt=0;kt<7;kt++) ldsm4(Af[kt][0],Af[kt][1],Af[kt][2],Af[kt][3],base+kt*32u);
}

__device__ __forceinline__ void unit_mma(const u32 Af[7][4], u32 bbase, int bst,
                                         int un, float d2[2][4], int lane){
  if(un<6){
    int row=un*16+(lane&7)+((lane&16)?8:0);
    u32 ba=bbase+(u32)((row*bst+((lane&8)?8:0))*2);
    #pragma unroll
    for(int kt=0;kt<7;kt++){
      u32 b0,b1,b2,b3; ldsm4(b0,b1,b2,b3,ba+kt*32u);
      mma_(d2[0],Af[kt],b0,b1); mma_(d2[1],Af[kt],b2,b3);
    }
  }else{
    int l16=lane&15;
    u32 ba=bbase+(u32)(((96+(l16&7))*bst+((l16&8)?8:0))*2);
    #pragma unroll
    for(int kt=0;kt<7;kt++){ u32 b0,b1; ldsm2(b0,b1,ba+kt*32u); mma_(d2[0],Af[kt],b0,b1); }
  }
}

__device__ __forceinline__ void rz_epi(int gate,int un,float d2[2][4],
    const __half* wih,const float* bsum,const int* toks,
    __half* buf2,__half* buf3,int row0,int g,int tig){
  __half* dst=gate?buf3:buf2;
  int ns=(un<6)?2:1;
  #pragma unroll
  for(int s=0;s<ns;s++){
    int c=un*16+8*s+2*tig, gc=gate*100+c;
    float2 bs=*(const float2*)&bsum[gc];
    #pragma unroll
    for(int h2=0;h2<2;h2++){
      int r=row0+g+8*h2;
      float2 w=__half22float2(*(const __half2*)&wih[toks[r]*WIHST+gc]);
      *(__half2*)&dst[r*104+c]=sigm_h2(d2[s][2*h2]+w.x+bs.x, d2[s][2*h2+1]+w.y+bs.y);
    }
  }
}

// pass A (encoder): rz + optional ha MMAs round-robin; n-gate MMA accumulated
// into register nacc (per-warp units wlocal, wlocal+4). One shared ldA7.
__device__ __forceinline__ void enc_passA2(u32 fcA_sm,int row0,int acol,u32 whh_sm,u32 aw_sm,
    const __half* wih,const float* bsum,const int* toks,
    __half* buf2,__half* buf3,int tprev,int blk0,int wlocal,int lane,bool do_ha,
    float nacc[2][2][4]){
  int g=lane>>2,tig=lane&3;
  u32 Af[7][4]; ldA7(Af,fcA_sm,row0,acol,lane);
  int nunits=do_ha?21:14;
  for(int u=wlocal;u<nunits;u+=4){
    float d2[2][4]={{0,0,0,0},{0,0,0,0}};
    if(u<14){
      int gate=u/7, un=u-7*gate;
      unit_mma(Af,whh_sm+(u32)(gate*GSZ*2),WST,un,d2,lane);
      rz_epi(gate,un,d2,wih,bsum,toks,buf2,buf3,row0,g,tig);
    }else{
      int un=u-14;
      unit_mma(Af,aw_sm,WST,un,d2,lane);
      int ns=(un<6)?2:1;
      #pragma unroll
      for(int s=0;s<ns;s++){
        int c=un*16+8*s+2*tig;
        #pragma unroll
        for(int h2=0;h2<2;h2++){
          int r=row0+g+8*h2;
          int bb=blk0+(r>>2);
          *(__half2*)&g_HA[((size_t)(bb*J+(r&3))*TIN+tprev)*HP+c]=__floats2half2_rn(d2[s][2*h2],d2[s][2*h2+1]);
        }
      }
    }
  }
  #pragma unroll
  for(int i=0;i<2;i++){
    int un=wlocal+4*i;
    if(un<7) unit_mma(Af,whh_sm+(u32)(2*GSZ*2),WST,un,nacc[i],lane);
  }
}

// n-gate epilogue from register accumulators (no MMA, no ldsm)
__device__ __forceinline__ void gru_n_epi(float nacc[2][2][4],int row0,
    const __half* wih,const float* bih,const float* bhh,const int* toks,
    const __half* buf2,const __half* buf3,float* hm,__half* hcol,
    bool wgh,int t,int blk0,int wlocal,int lane){
  int g=lane>>2,tig=lane&3;
  #pragma unroll
  for(int i=0;i<2;i++){
    int un=wlocal+4*i;
    if(un<7){
      int ns=(un<6)?2:1;
      #pragma unroll
      for(int s=0;s<ns;s++){
        int c=un*16+8*s+2*tig, gc=200+c;
        float2 bi=*(const float2*)&bih[gc], bh=*(const float2*)&bhh[gc];
        #pragma unroll
        for(int h2=0;h2<2;h2++){
          int r=row0+g+8*h2;
          float2 w=__half22float2(*(const __half2*)&wih[toks[r]*WIHST+gc]);
          float2 rr=__half22float2(*(const __half2*)&buf2[r*104+c]);
          float2 zz=__half22float2(*(const __half2*)&buf3[r*104+c]);
          __half2 nh=tanh2f(w.x+bi.x+rr.x*(nacc[i][s][2*h2]+bh.x),
                            w.y+bi.y+rr.y*(nacc[i][s][2*h2+1]+bh.y));
          float2 nn=__half22float2(nh);
          float2 ho=*(const float2*)&hm[r*104+c];
          float2 hn; hn.x=(1.f-zz.x)*nn.x+zz.x*ho.x; hn.y=(1.f-zz.y)*nn.y+zz.y*ho.y;
          *(float2*)&hm[r*104+c]=hn;
          *(__half2*)&hcol[r*FCA+c]=__floats2half2_rn(hn.x,hn.y);
          if(wgh){int bb=blk0+(r>>2);
            *(float2*)&g_H[((size_t)(bb*J+(r&3))*TIN+t)*HP+c]=hn;}
        }
      }
    }
  }
}

// pass A (decoder): rz + fc MMAs round-robin; n-gate into nacc. Af1 shared.
__device__ __forceinline__ void dec_passA2(u32 fcA_sm,int row0,u32 whh_sm,u32 wb2_sm,
    const __half* wih,const float* bsum,const float* wbb,const int* toks,
    __half* buf1,__half* buf2,__half* buf3,int wlocal,int lane,float nacc[2][2][4]){
  int g=lane>>2,tig=lane&3;
  u32 Af1[7][4]; ldA7(Af1,fcA_sm,row0,112,lane);
  for(int u=wlocal;u<21;u+=4){
    float d2[2][4]={{0,0,0,0},{0,0,0,0}};
    if(u<14){
      int gate=u/7, un=u-7*gate;
      unit_mma(Af1,whh_sm+(u32)(gate*GSZ*2),WST,un,d2,lane);
      rz_epi(gate,un,d2,wih,bsum,toks,buf2,buf3,row0,g,tig);
    }else{
      int un=u-14;
      unit_mma(Af1,wb2_sm+(u32)(112*2),WWBST,un,d2,lane);
      u32 Af0[7][4]; ldA7(Af0,fcA_sm,row0,0,lane);
      unit_mma(Af0,wb2_sm,WWBST,un,d2,lane);
      int ns=(un<6)?2:1;
      #pragma unroll
      for(int s=0;s<ns;s++){
        int c=un*16+8*s+2*tig;
        float2 wb=*(const float2*)&wbb[c];
        #pragma unroll
        for(int h2=0;h2<2;h2++){
          int r=row0+g+8*h2;
          *(__half2*)&buf1[r*104+c]=tanh2f(d2[s][2*h2]+wb.x, d2[s][2*h2+1]+wb.y);
        }
      }
    }
  }
  #pragma unroll
  for(int i=0;i<2;i++){
    int un=wlocal+4*i;
    if(un<7) unit_mma(Af1,whh_sm+(u32)(2*GSZ*2),WST,un,nacc[i],lane);
  }
}

__global__ void __launch_bounds__(NTHREADS,1)
fused_kernel(const int* __restrict__ inputs, const int* __restrict__ target,
             const float* __restrict__ eWih, const float* __restrict__ eWhh,
             const float* __restrict__ ebih, const float* __restrict__ ebhh,
             const float* __restrict__ dWih, const float* __restrict__ dWhh,
             const float* __restrict__ dbih, const float* __restrict__ dbhh,
             const float* __restrict__ Ww,  const float* __restrict__ Wb,
             const float* __restrict__ Vw,  const float* __restrict__ Vb,
             const float* __restrict__ Aw,  float* __restrict__ out)
{
    extern __shared__ char smx[];
    __half* whh =(__half*)(smx+OFF_WHH);
    __half* wb2 =(__half*)(smx+OFF_WB2);
    __half* wih =(__half*)(smx+OFF_WIH);
    float*  vwf =(float*)(smx+OFF_VW);
    float*  bih =(float*)(smx+OFF_BIH);
    float*  bhh =(float*)(smx+OFF_BHH);
    float*  bsum=(float*)(smx+OFF_BSUM);
    float*  wbb =(float*)(smx+OFF_WBB);
    float*  vbb =(float*)(smx+OFF_VB);
    __half* fcA =(__half*)(smx+OFF_FCAB);
    float*  hm  =(float*)(smx+OFF_HM);
    __half* buf1=(__half*)(smx+OFF_BUF1);
    __half* buf2=(__half*)(smx+OFF_BUF2);
    __half* buf3=(__half*)(smx+OFF_BUF3);
    float*  scb =(float*)(smx+OFF_SC);
    int*    toks=(int*)(smx+OFF_TOK);

    const u32 fcA_sm=smaddr(fcA), whh_sm=smaddr(whh), wb2_sm=smaddr(wb2);
    const int tid=threadIdx.x, warp=tid>>5, lane=tid&31;
    const int wg=warp>>2, wlocal=warp&3, row0=wg*16;
    const int blk0=blockIdx.x*NWARP;
    const int b=blk0+warp;
    const int e0=2*lane, e1=64+2*lane;
    const bool m1=(lane<18);

    for(int i=tid;i<3*GSZ;i+=NTHREADS){
        int gate=i/GSZ, rem=i-gate*GSZ, n=rem/WST, k=rem-n*WST;
        whh[i]=(n<100&&k<100)?__float2half(eWhh[(gate*100+n)*100+k]):__half(0.f);
    }
    for(int i=tid;i<104*WST;i+=NTHREADS){
        int f=i/WST,e=i-f*WST;
        wb2[i]=(f<100&&e<100)?__float2half(Aw[e*100+f]):__half(0.f);
    }
    for(int i=tid;i<11*WIHST;i+=NTHREADS){
        int v=i/WIHST,gg=i-v*WIHST;
        wih[i]=(gg<300)?__float2half(eWih[gg*11+v]):__half(0.f);
    }
    for(int i=tid;i<304;i+=NTHREADS){
        float a=(i<300)?ebih[i]:0.f, c=(i<300)?ebhh[i]:0.f;
        bih[i]=a; bhh[i]=c; bsum[i]=a+c;
    }
    for(int i=tid;i<MROWS*FCA/2;i+=NTHREADS) ((u32*)fcA)[i]=0u;
    for(int i=tid;i<MROWS*104;i+=NTHREADS) hm[i]=0.f;
    int* toks2=(int*)scb;
    for(int i=tid;i<TIN*MROWS;i+=NTHREADS){
        int t=i/MROWS, r=i-t*MROWS;
        int bb=blk0+(r>>2);
        toks2[i]=inputs[((r&3)*TIN+t)*BATCH+bb];
    }
    __syncthreads();

    for(int t=0;t<TIN;t++){
        int rcol=(t&1)?112:0, wcol=112-rcol;
        float nacc[2][2][4]={{{0,0,0,0},{0,0,0,0}},{{0,0,0,0},{0,0,0,0}}};
        enc_passA2(fcA_sm,row0,rcol,whh_sm,wb2_sm,wih,bsum,&toks2[t*MROWS],
                   buf2,buf3,t-1,blk0,wlocal,lane,t>0,nacc);
        BARWG();
        gru_n_epi(nacc,row0,wih,bih,bhh,&toks2[t*MROWS],buf2,buf3,hm,fcA+wcol,true,t,blk0,wlocal,lane);
        BARWG();
    }
    {   // final HA(9): h(9) at col 0
        int g=lane>>2,tig=lane&3;
        u32 Af[7][4]; ldA7(Af,fcA_sm,row0,0,lane);
        for(int un=wlocal;un<7;un+=4){
            float d2[2][4]={{0,0,0,0},{0,0,0,0}};
            unit_mma(Af,wb2_sm,WST,un,d2,lane);
            int ns=(un<6)?2:1;
            #pragma unroll
            for(int s=0;s<ns;s++){
                int c=un*16+8*s+2*tig;
                #pragma unroll
                for(int h2=0;h2<2;h2++){
                    int r=row0+g+8*h2;
                    int bb=blk0+(r>>2);
                    *(__half2*)&g_HA[((size_t)(bb*J+(r&3))*TIN+(TIN-1))*HP+c]=__floats2half2_rn(d2[s][2*h2],d2[s][2*h2+1]);
                }
            }
        }
    }
    __syncthreads();

    for(int i=tid;i<3*GSZ;i+=NTHREADS){
        int gate=i/GSZ, rem=i-gate*GSZ, n=rem/WST, k=rem-n*WST;
        whh[i]=(n<100&&k<100)?__float2half(dWhh[(gate*100+n)*100+k]):__half(0.f);
    }
    for(int i=tid;i<104*WWBST;i+=NTHREADS){
        int e=i/WWBST, kk=i-e*WWBST;
        float v=0.f;
        if(e<100){ if(kk<100) v=Ww[e*200+kk]; else if(kk>=112&&kk<212) v=Ww[e*200+kk-12]; }
        wb2[i]=__float2half(v);
    }
    for(int i=tid;i<11*WIHST;i+=NTHREADS){
        int v=i/WIHST,gg=i-v*WIHST;
        wih[i]=(gg<300)?__float2half(dWih[gg*11+v]):__half(0.f);
    }
    for(int i=tid;i<304;i+=NTHREADS){
        float a=(i<300)?dbih[i]:0.f, c=(i<300)?dbhh[i]:0.f;
        bih[i]=a; bhh[i]=c; bsum[i]=a+c;
    }
    for(int i=tid;i<11*104;i+=NTHREADS){int v=i/104,e=i-v*104; vwf[i]=(e<100)?Vw[v*100+e]:0.f;}
    for(int i=tid;i<104;i+=NTHREADS) wbb[i]=(i<100)?Wb[i]:0.f;
    for(int i=tid;i<16;i+=NTHREADS) vbb[i]=(i<VDIM)?Vb[i]:0.f;
    for(int i=tid;i<MROWS*112;i+=NTHREADS){int r=i/112,c=i-r*112; fcA[r*FCA+112+c]=fcA[r*FCA+c];}
    if(tid<MROWS) toks[tid]=VDIM-1;
    __syncthreads();

    {   // init P0 = GRU(SOS, h_last)
        float nacc[2][2][4]={{{0,0,0,0},{0,0,0,0}},{{0,0,0,0},{0,0,0,0}}};
        enc_passA2(fcA_sm,row0,112,whh_sm,wb2_sm,wih,bsum,toks,buf2,buf3,0,blk0,wlocal,lane,false,nacc);
        BARWG();
        gru_n_epi(nacc,row0,wih,bih,bhh,toks,buf2,buf3,hm,fcA,false,0,blk0,wlocal,lane);
        BARWG();
    }

    float score=0.f;
    float* sc=&scb[warp*40];
    for(int t=0;t<TOUT;t++){
        {
            int j=lane/10, tt=lane-10*j;
            const int4* hap=(const int4*)&g_HA[((size_t)(b*J+j)*TIN+tt)*HP];
            const int4* pj =(const int4*)&fcA[(warp*J+j)*FCA];
            float accs=0.f;
            #pragma unroll 13
            for(int q=0;q<13;q++){
                int4 hv=hap[q], pv4=pj[q];
                float2 h0=__half22float2(*(__half2*)&hv.x), p0=__half22float2(*(__half2*)&pv4.x);
                float2 h1=__half22float2(*(__half2*)&hv.y), p1=__half22float2(*(__half2*)&pv4.y);
                float2 h2=__half22float2(*(__half2*)&hv.z), p2=__half22float2(*(__half2*)&pv4.z);
                float2 h3=__half22float2(*(__half2*)&hv.w), p3=__half22float2(*(__half2*)&pv4.w);
                accs=fmaf(h0.x,p0.x,accs); accs=fmaf(h0.y,p0.y,accs);
                accs=fmaf(h1.x,p1.x,accs); accs=fmaf(h1.y,p1.y,accs);
                accs=fmaf(h2.x,p2.x,accs); accs=fmaf(h2.y,p2.y,accs);
                accs=fmaf(h3.x,p3.x,accs); accs=fmaf(h3.y,p3.y,accs);
            }
            sc[lane]=accs;
            if(lane<8){
                int t2=32+lane, j2=t2/10, tt2=t2-10*j2;
                const int4* hap2=(const int4*)&g_HA[((size_t)(b*J+j2)*TIN+tt2)*HP];
                const int4* pj2 =(const int4*)&fcA[(warp*J+j2)*FCA];
                float a2=0.f;
                #pragma unroll 13
                for(int q=0;q<13;q++){
                    int4 hv=hap2[q], pv4=pj2[q];
                    float2 h0=__half22float2(*(__half2*)&hv.x), p0=__half22float2(*(__half2*)&pv4.x);
                    float2 h1=__half22float2(*(__half2*)&hv.y), p1=__half22float2(*(__half2*)&pv4.y);
                    float2 h2=__half22float2(*(__half2*)&hv.z), p2=__half22float2(*(__half2*)&pv4.z);
                    float2 h3=__half22float2(*(__half2*)&hv.w), p3=__half22float2(*(__half2*)&pv4.w);
                    a2=fmaf(h0.x,p0.x,a2); a2=fmaf(h0.y,p0.y,a2);
                    a2=fmaf(h1.x,p1.x,a2); a2=fmaf(h1.y,p1.y,a2);
                    a2=fmaf(h2.x,p2.x,a2); a2=fmaf(h2.y,p2.y,a2);
                    a2=fmaf(h3.x,p3.x,a2); a2=fmaf(h3.y,p3.y,a2);
                }
                sc[t2]=a2;
            }
        }
        __syncwarp();
        if(lane<J){
            float mx=-1e30f;
            #pragma unroll
            for(int tt=0;tt<TIN;tt++) mx=fmaxf(mx,sc[lane*10+tt]);
            float s=0.f;
            #pragma unroll
            for(int tt=0;tt<TIN;tt++) s+=__expf(sc[lane*10+tt]-mx);
            float lg=__logf(s)+mx;
            #pragma unroll
            for(int tt=0;tt<TIN;tt++) sc[lane*10+tt]-=lg;
        }
        __syncwarp();
        if(lane<25){
            #pragma unroll
            for(int j=0;j<J;j++){
                const float* hb=&g_H[((size_t)(b*J+j)*TIN)*HP + 4*lane];
                float4 acc; acc.x=0.f; acc.y=0.f; acc.z=0.f; acc.w=0.f;
                #pragma unroll
                for(int tt=0;tt<TIN;tt++){
                    float lg=sc[j*10+tt];
                    float4 h4=*(const float4*)(hb+tt*HP);
                    acc.x=fmaf(lg,h4.x,acc.x); acc.y=fmaf(lg,h4.y,acc.y);
                    acc.z=fmaf(lg,h4.z,acc.z); acc.w=fmaf(lg,h4.w,acc.w);
                }
                int r=warp*J+j;
                *(float4*)&hm[r*104+4*lane]=acc;
                __half2 p0=__floats2half2_rn(acc.x,acc.y), p1=__floats2half2_rn(acc.z,acc.w);
                uint2 pk; pk.x=*(u32*)&p0; pk.y=*(u32*)&p1;
                *(uint2*)&fcA[r*FCA+112+4*lane]=pk;
            }
        }
        if(lane<J) toks[warp*J+lane]=target[t*BATCH+b];
        BARWG();
        float nacc[2][2][4]={{{0,0,0,0},{0,0,0,0}},{{0,0,0,0},{0,0,0,0}}};
        dec_passA2(fcA_sm,row0,whh_sm,wb2_sm,wih,bsum,wbb,toks,buf1,buf2,buf3,wlocal,lane,nacc);
        BARWG();
        {
            float2 mA; mA.x=-1e30f; mA.y=-1e30f; float2 mB=mA;
            #pragma unroll
            for(int j=0;j<J;j++){
                int r=warp*J+j;
                float2 fA=__half22float2(*(const __half2*)&buf1[r*104+e0]);
                mA.x=fmaxf(mA.x,fA.x); mA.y=fmaxf(mA.y,fA.y);
                if(m1){float2 fB=__half22float2(*(const __half2*)&buf1[r*104+e1]);
                    mB.x=fmaxf(mB.x,fB.x); mB.y=fmaxf(mB.y,fB.y);}
            }
            float pv[VDIM];
            #pragma unroll
            for(int v=0;v<VDIM;v++){
                const float* vr=&vwf[v*104];
                float p=vr[e0]*mA.x+vr[e0+1]*mA.y;
                if(m1){p=fmaf(vr[e1],mB.x,p); p=fmaf(vr[e1+1],mB.y,p);}
                pv[v]=p;
            }
            #pragma unroll
            for(int off=16;off>=1;off>>=1){
                #pragma unroll
                for(int v=0;v<VDIM;v++) pv[v]+=__shfl_xor_sync(0xffffffffu,pv[v],off);
            }
            int tok=target[t*BATCH+b];
            float mx=-1e30f;
            #pragma unroll
            for(int v=0;v<VDIM;v++){pv[v]+=vbb[v]; mx=fmaxf(mx,pv[v]);}
            float ss=0.f;
            #pragma unroll
            for(int v=0;v<VDIM;v++) ss+=__expf(pv[v]-mx);
            score+=pv[tok]-mx-__logf(ss);
        }
        gru_n_epi(nacc,row0,wih,bih,bhh,toks,buf2,buf3,hm,fcA,false,0,blk0,wlocal,lane);
        BARWG();
    }
    if(lane==0) out[b]=score;
}

extern "C" void kernel_launch(void* const* d_in, const int* in_sizes, int n_in,
                              void* d_out, int out_size)
{
    cudaFuncSetAttribute(fused_kernel, cudaFuncAttributeMaxDynamicSharedMemorySize, SMEM_BYTES);
    int grid=(BATCH+NWARP-1)/NWARP;
    fused_kernel<<<grid, NTHREADS, SMEM_BYTES>>>(
        (const int*)d_in[0], (const int*)d_in[1],
        (const float*)d_in[2], (const float*)d_in[3], (const float*)d_in[4], (const float*)d_in[5],
        (const float*)d_in[6], (const float*)d_in[7], (const float*)d_in[8], (const float*)d_in[9],
        (const float*)d_in[10], (const float*)d_in[11], (const float*)d_in[12], (const float*)d_in[13],
        (const float*)d_in[14], (float*)d_out);
}

// round 13
// speedup vs baseline: 3.5372x; 1.0957x over previous
#include <cuda_runtime.h>
#include <cuda_fp16.h>
#include <cstdint>

#define J 4
#define BATCH 8192
#define TIN 10
#define TOUT 10
#define VDIM 11
#define NWARP 16
#define NTHREADS 512
#define MROWS 64
typedef unsigned long long u64;
typedef uint32_t u32;

#define FCA 232
#define WST 104
#define GSZ (104*104)
#define WWBST 232
#define WIHST 304
#define HP 104

#define OFF_WHH   0
#define OFF_WB2   64896
#define OFF_WIH   113152
#define OFF_VW    119840
#define OFF_BIH   124416
#define OFF_BHH   125632
#define OFF_BSUM  126848
#define OFF_WBB   128064
#define OFF_VB    128480
#define OFF_FCAB  128544
#define OFF_HM    158240
#define OFF_BUF1  184864
#define OFF_BUF2  198176
#define OFF_BUF3  211488
#define OFF_SC    224800
#define OFF_TOK   227360
#define SMEM_BYTES 227616

__device__ __half g_H [(size_t)J*BATCH*TIN*HP];
__device__ __half g_HA[(size_t)J*BATCH*TIN*HP];

__device__ __forceinline__ u32 smaddr(const void* p){ u32 a; asm("{.reg .u64 t; cvta.to.shared.u64 t, %1; cvt.u32.u64 %0, t;}":"=r"(a):"l"(p)); return a; }
__device__ __forceinline__ __half2 tanh_h2(__half2 x){
  __half2 r; asm("tanh.approx.f16x2 %0, %1;":"=r"(*(u32*)&r):"r"(*(u32*)&x)); return r;
}
__device__ __forceinline__ __half2 sigm_h2(float a, float b){
  __half2 t=tanh_h2(__floats2half2_rn(0.5f*a,0.5f*b));
  const __half2 hh=__floats2half2_rn(0.5f,0.5f);
  return __hfma2(t,hh,hh);
}
__device__ __forceinline__ __half2 tanh2f(float a, float b){
  return tanh_h2(__floats2half2_rn(a,b));
}
__device__ __forceinline__ void ldsm4(u32&a0,u32&a1,u32&a2,u32&a3,u32 ad){
  asm volatile("ldmatrix.sync.aligned.m8n8.x4.shared.b16 {%0,%1,%2,%3},[%4];":"=r"(a0),"=r"(a1),"=r"(a2),"=r"(a3):"r"(ad));
}
__device__ __forceinline__ void ldsm2(u32&b0,u32&b1,u32 ad){
  asm volatile("ldmatrix.sync.aligned.m8n8.x2.shared.b16 {%0,%1},[%2];":"=r"(b0),"=r"(b1):"r"(ad));
}
__device__ __forceinline__ void stsm4(u32 ad,u32 x0,u32 x1,u32 x2,u32 x3){
  asm volatile("stmatrix.sync.aligned.m8n8.x4.shared.b16 [%0],{%1,%2,%3,%4};"::"r"(ad),"r"(x0),"r"(x1),"r"(x2),"r"(x3):"memory");
}
__device__ __forceinline__ void stsm2(u32 ad,u32 x0,u32 x1){
  asm volatile("stmatrix.sync.aligned.m8n8.x2.shared.b16 [%0],{%1,%2};"::"r"(ad),"r"(x0),"r"(x1):"memory");
}
__device__ __forceinline__ void mma_(float d[4], const u32 a[4], u32 b0,u32 b1){
  asm("mma.sync.aligned.m16n8k16.row.col.f32.f16.f16.f32 {%0,%1,%2,%3},{%4,%5,%6,%7},{%8,%9},{%0,%1,%2,%3};"
   :"+f"(d[0]),"+f"(d[1]),"+f"(d[2]),"+f"(d[3]):"r"(a[0]),"r"(a[1]),"r"(a[2]),"r"(a[3]),"r"(b0),"r"(b1));
}
#define BARWG() asm volatile("bar.sync %0, 128;"::"r"(wg+1):"memory")

__device__ __forceinline__ void ldA7(u32 Af[7][4], u32 fcA_sm, int row0, int acol, int lane){
  int arow=row0+(lane&7)+((lane&8)?8:0);
  u32 base=fcA_sm+(u32)((arow*FCA+acol+((lane&16)?8:0))*2);
  #pragma unroll
  for(int kt=0;kt<7;kt++) ldsm4(Af[kt][0],Af[kt][1],Af[kt][2],Af[kt][3],base+kt*32u);
}

__device__ __forceinline__ void unit_mma(const u32 Af[7][4], u32 bbase, int bst,
                                         int un, float d2[2][4], int lane){
  if(un<6){
    int row=un*16+(lane&7)+((lane&16)?8:0);
    u32 ba=bbase+(u32)((row*bst+((lane&8)?8:0))*2);
    #pragma unroll
    for(int kt=0;kt<7;kt++){
      u32 b0,b1,b2,b3; ldsm4(b0,b1,b2,b3,ba+kt*32u);
      mma_(d2[0],Af[kt],b0,b1); mma_(d2[1],Af[kt],b2,b3);
    }
  }else{
    int l16=lane&15;
    u32 ba=bbase+(u32)(((96+(l16&7))*bst+((l16&8)?8:0))*2);
    #pragma unroll
    for(int kt=0;kt<7;kt++){ u32 b0,b1; ldsm2(b0,b1,ba+kt*32u); mma_(d2[0],Af[kt],b0,b1); }
  }
}

// stmatrix dest address for this lane within a 16x16 (or 16x8) region
__device__ __forceinline__ u32 stsm_addr(u32 base_sm,int row0,int stride,int c0,int lane){
  int row=row0+(lane&15), col=c0+((lane>>4)<<3);
  return base_sm + (u32)((row*stride+col)*2);
}

__device__ __forceinline__ void rz_epi(int gate,int un,float d2[2][4],
    const __half* wih,const float* bsum,const int* toks,
    u32 buf2_sm,u32 buf3_sm,int row0,int g,int tig,int lane){
  int ns=(un<6)?2:1;
  u32 x[4]={0,0,0,0};
  #pragma unroll
  for(int s=0;s<2;s++){
    if(s<ns){
      int c=un*16+8*s+2*tig, gc=gate*100+c;
      float2 bs=*(const float2*)&bsum[gc];
      #pragma unroll
      for(int h2=0;h2<2;h2++){
        int r=row0+g+8*h2;
        float2 w=__half22float2(*(const __half2*)&wih[toks[r]*WIHST+gc]);
        __half2 v=sigm_h2(d2[s][2*h2]+w.x+bs.x, d2[s][2*h2+1]+w.y+bs.y);
        x[2*s+h2]=*(u32*)&v;
      }
    }
  }
  u32 ad=stsm_addr(gate?buf3_sm:buf2_sm,row0,104,un*16,lane);
  if(ns==2) stsm4(ad,x[0],x[1],x[2],x[3]); else stsm2(ad,x[0],x[1]);
}

// encoder pass A: rz + optional ha; n-gate into nacc regs
__device__ __forceinline__ void enc_passA2(u32 fcA_sm,int row0,int acol,u32 whh_sm,u32 aw_sm,
    const __half* wih,const float* bsum,const int* toks,
    u32 buf2_sm,u32 buf3_sm,int tprev,int blk0,int wlocal,int lane,bool do_ha,
    float nacc[2][2][4]){
  int g=lane>>2,tig=lane&3;
  u32 Af[7][4]; ldA7(Af,fcA_sm,row0,acol,lane);
  int nunits=do_ha?21:14;
  for(int u=wlocal;u<nunits;u+=4){
    float d2[2][4]={{0,0,0,0},{0,0,0,0}};
    if(u<14){
      int gate=u/7, un=u-7*gate;
      unit_mma(Af,whh_sm+(u32)(gate*GSZ*2),WST,un,d2,lane);
      rz_epi(gate,un,d2,wih,bsum,toks,buf2_sm,buf3_sm,row0,g,tig,lane);
    }else{
      int un=u-14;
      unit_mma(Af,aw_sm,WST,un,d2,lane);
      int ns=(un<6)?2:1;
      #pragma unroll
      for(int s=0;s<ns;s++){
        int c=un*16+8*s+2*tig;
        #pragma unroll
        for(int h2=0;h2<2;h2++){
          int r=row0+g+8*h2;
          int bb=blk0+(r>>2);
          *(__half2*)&g_HA[((size_t)(bb*J+(r&3))*TIN+tprev)*HP+c]=__floats2half2_rn(d2[s][2*h2],d2[s][2*h2+1]);
        }
      }
    }
  }
  #pragma unroll
  for(int i=0;i<2;i++){
    int un=wlocal+4*i;
    if(un<7) unit_mma(Af,whh_sm+(u32)(2*GSZ*2),WST,un,nacc[i],lane);
  }
}

// encoder n epilogue: hm f32 master + fp16 mirror (stsm) + g_H fp16
__device__ __forceinline__ void gru_n_epi_enc(float nacc[2][2][4],int row0,
    const __half* wih,const float* bih,const float* bhh,const int* toks,
    const __half* buf2,const __half* buf3,float* hm,u32 fcA_sm,int wcol,
    int t,int blk0,int wlocal,int lane){
  int g=lane>>2,tig=lane&3;
  #pragma unroll
  for(int i=0;i<2;i++){
    int un=wlocal+4*i;
    if(un<7){
      int ns=(un<6)?2:1;
      u32 x[4]={0,0,0,0};
      #pragma unroll
      for(int s=0;s<2;s++){
        if(s<ns){
          int c=un*16+8*s+2*tig, gc=200+c;
          float2 bi=*(const float2*)&bih[gc], bh=*(const float2*)&bhh[gc];
          #pragma unroll
          for(int h2=0;h2<2;h2++){
            int r=row0+g+8*h2;
            float2 w=__half22float2(*(const __half2*)&wih[toks[r]*WIHST+gc]);
            float2 rr=__half22float2(*(const __half2*)&buf2[r*104+c]);
            float2 zz=__half22float2(*(const __half2*)&buf3[r*104+c]);
            __half2 nh=tanh2f(w.x+bi.x+rr.x*(nacc[i][s][2*h2]+bh.x),
                              w.y+bi.y+rr.y*(nacc[i][s][2*h2+1]+bh.y));
            float2 nn=__half22float2(nh);
            float2 ho=*(const float2*)&hm[r*104+c];
            float2 hn; hn.x=(1.f-zz.x)*nn.x+zz.x*ho.x; hn.y=(1.f-zz.y)*nn.y+zz.y*ho.y;
            *(float2*)&hm[r*104+c]=hn;
            __half2 hh=__floats2half2_rn(hn.x,hn.y);
            x[2*s+h2]=*(u32*)&hh;
            int bb=blk0+(r>>2);
            *(__half2*)&g_H[((size_t)(bb*J+(r&3))*TIN+t)*HP+c]=hh;
          }
        }
      }
      u32 ad=stsm_addr(fcA_sm,row0,FCA,wcol+un*16,lane);
      if(ns==2) stsm4(ad,x[0],x[1],x[2],x[3]); else stsm2(ad,x[0],x[1]);
    }
  }
}

// decoder n epilogue: old state from fp16 c-mirror (region1), write P-mirror only
__device__ __forceinline__ void gru_n_epi_dec(float nacc[2][2][4],int row0,
    const __half* wih,const float* bih,const float* bhh,const int* toks,
    const __half* buf2,const __half* buf3,const __half* fcA,u32 fcA_sm,
    int wlocal,int lane){
  int g=lane>>2,tig=lane&3;
  #pragma unroll
  for(int i=0;i<2;i++){
    int un=wlocal+4*i;
    if(un<7){
      int ns=(un<6)?2:1;
      u32 x[4]={0,0,0,0};
      #pragma unroll
      for(int s=0;s<2;s++){
        if(s<ns){
          int c=un*16+8*s+2*tig, gc=200+c;
          float2 bi=*(const float2*)&bih[gc], bh=*(const float2*)&bhh[gc];
          #pragma unroll
          for(int h2=0;h2<2;h2++){
            int r=row0+g+8*h2;
            float2 w=__half22float2(*(const __half2*)&wih[toks[r]*WIHST+gc]);
            float2 rr=__half22float2(*(const __half2*)&buf2[r*104+c]);
            float2 zz=__half22float2(*(const __half2*)&buf3[r*104+c]);
            __half2 nh=tanh2f(w.x+bi.x+rr.x*(nacc[i][s][2*h2]+bh.x),
                              w.y+bi.y+rr.y*(nacc[i][s][2*h2+1]+bh.y));
            float2 nn=__half22float2(nh);
            float2 ho=__half22float2(*(const __half2*)&fcA[r*FCA+112+c]);
            __half2 hh=__floats2half2_rn((1.f-zz.x)*nn.x+zz.x*ho.x,
                                         (1.f-zz.y)*nn.y+zz.y*ho.y);
            x[2*s+h2]=*(u32*)&hh;
          }
        }
      }
      u32 ad=stsm_addr(fcA_sm,row0,FCA,un*16,lane);
      if(ns==2) stsm4(ad,x[0],x[1],x[2],x[3]); else stsm2(ad,x[0],x[1]);
    }
  }
}

// decoder pass A: rz + fc; n-gate into nacc
__device__ __forceinline__ void dec_passA2(u32 fcA_sm,int row0,u32 whh_sm,u32 wb2_sm,
    const __half* wih,const float* bsum,const float* wbb,const int* toks,
    u32 buf1_sm,u32 buf2_sm,u32 buf3_sm,int wlocal,int lane,float nacc[2][2][4]){
  int g=lane>>2,tig=lane&3;
  u32 Af1[7][4]; ldA7(Af1,fcA_sm,row0,112,lane);
  for(int u=wlocal;u<21;u+=4){
    float d2[2][4]={{0,0,0,0},{0,0,0,0}};
    if(u<14){
      int gate=u/7, un=u-7*gate;
      unit_mma(Af1,whh_sm+(u32)(gate*GSZ*2),WST,un,d2,lane);
      rz_epi(gate,un,d2,wih,bsum,toks,buf2_sm,buf3_sm,row0,g,tig,lane);
    }else{
      int un=u-14;
      unit_mma(Af1,wb2_sm+(u32)(112*2),WWBST,un,d2,lane);
      u32 Af0[7][4]; ldA7(Af0,fcA_sm,row0,0,lane);
      unit_mma(Af0,wb2_sm,WWBST,un,d2,lane);
      int ns=(un<6)?2:1;
      u32 x[4]={0,0,0,0};
      #pragma unroll
      for(int s=0;s<2;s++){
        if(s<ns){
          int c=un*16+8*s+2*tig;
          float2 wb=*(const float2*)&wbb[c];
          #pragma unroll
          for(int h2=0;h2<2;h2++){
            __half2 v=tanh2f(d2[s][2*h2]+wb.x, d2[s][2*h2+1]+wb.y);
            x[2*s+h2]=*(u32*)&v;
          }
        }
      }
      u32 ad=stsm_addr(buf1_sm,row0,104,un*16,lane);
      if(ns==2) stsm4(ad,x[0],x[1],x[2],x[3]); else stsm2(ad,x[0],x[1]);
    }
  }
  #pragma unroll
  for(int i=0;i<2;i++){
    int un=wlocal+4*i;
    if(un<7) unit_mma(Af1,whh_sm+(u32)(2*GSZ*2),WST,un,nacc[i],lane);
  }
}

__global__ void __launch_bounds__(NTHREADS,1)
fused_kernel(const int* __restrict__ inputs, const int* __restrict__ target,
             const float* __restrict__ eWih, const float* __restrict__ eWhh,
             const float* __restrict__ ebih, const float* __restrict__ ebhh,
             const float* __restrict__ dWih, const float* __restrict__ dWhh,
             const float* __restrict__ dbih, const float* __restrict__ dbhh,
             const float* __restrict__ Ww,  const float* __restrict__ Wb,
             const float* __restrict__ Vw,  const float* __restrict__ Vb,
             const float* __restrict__ Aw,  float* __restrict__ out)
{
    extern __shared__ char smx[];
    __half* whh =(__half*)(smx+OFF_WHH);
    __half* wb2 =(__half*)(smx+OFF_WB2);
    __half* wih =(__half*)(smx+OFF_WIH);
    float*  vwf =(float*)(smx+OFF_VW);
    float*  bih =(float*)(smx+OFF_BIH);
    float*  bhh =(float*)(smx+OFF_BHH);
    float*  bsum=(float*)(smx+OFF_BSUM);
    float*  wbb =(float*)(smx+OFF_WBB);
    float*  vbb =(float*)(smx+OFF_VB);
    __half* fcA =(__half*)(smx+OFF_FCAB);
    float*  hm  =(float*)(smx+OFF_HM);
    __half* buf1=(__half*)(smx+OFF_BUF1);
    __half* buf2=(__half*)(smx+OFF_BUF2);
    __half* buf3=(__half*)(smx+OFF_BUF3);
    float*  scb =(float*)(smx+OFF_SC);
    int*    toks=(int*)(smx+OFF_TOK);

    const u32 fcA_sm=smaddr(fcA), whh_sm=smaddr(whh), wb2_sm=smaddr(wb2);
    const u32 buf1_sm=smaddr(buf1), buf2_sm=smaddr(buf2), buf3_sm=smaddr(buf3);
    const int tid=threadIdx.x, warp=tid>>5, lane=tid&31;
    const int wg=warp>>2, wlocal=warp&3, row0=wg*16;
    const int blk0=blockIdx.x*NWARP;
    const int b=blk0+warp;
    const int e0=2*lane, e1=64+2*lane;
    const bool m1=(lane<18);

    for(int i=tid;i<3*GSZ;i+=NTHREADS){
        int gate=i/GSZ, rem=i-gate*GSZ, n=rem/WST, k=rem-n*WST;
        whh[i]=(n<100&&k<100)?__float2half(eWhh[(gate*100+n)*100+k]):__half(0.f);
    }
    for(int i=tid;i<104*WST;i+=NTHREADS){
        int f=i/WST,e=i-f*WST;
        wb2[i]=(f<100&&e<100)?__float2half(Aw[e*100+f]):__half(0.f);
    }
    for(int i=tid;i<11*WIHST;i+=NTHREADS){
        int v=i/WIHST,gg=i-v*WIHST;
        wih[i]=(gg<300)?__float2half(eWih[gg*11+v]):__half(0.f);
    }
    for(int i=tid;i<304;i+=NTHREADS){
        float a=(i<300)?ebih[i]:0.f, c=(i<300)?ebhh[i]:0.f;
        bih[i]=a; bhh[i]=c; bsum[i]=a+c;
    }
    for(int i=tid;i<MROWS*FCA/2;i+=NTHREADS) ((u32*)fcA)[i]=0u;
    for(int i=tid;i<MROWS*104;i+=NTHREADS) hm[i]=0.f;
    int* toks2=(int*)scb;
    for(int i=tid;i<TIN*MROWS;i+=NTHREADS){
        int t=i/MROWS, r=i-t*MROWS;
        int bb=blk0+(r>>2);
        toks2[i]=inputs[((r&3)*TIN+t)*BATCH+bb];
    }
    __syncthreads();

    for(int t=0;t<TIN;t++){
        int rcol=(t&1)?112:0, wcol=112-rcol;
        float nacc[2][2][4]={{{0,0,0,0},{0,0,0,0}},{{0,0,0,0},{0,0,0,0}}};
        enc_passA2(fcA_sm,row0,rcol,whh_sm,wb2_sm,wih,bsum,&toks2[t*MROWS],
                   buf2_sm,buf3_sm,t-1,blk0,wlocal,lane,t>0,nacc);
        BARWG();
        gru_n_epi_enc(nacc,row0,wih,bih,bhh,&toks2[t*MROWS],buf2,buf3,hm,fcA_sm,wcol,t,blk0,wlocal,lane);
        BARWG();
    }
    {   // final HA(9): h(9) mirror at col 0
        int g=lane>>2,tig=lane&3;
        u32 Af[7][4]; ldA7(Af,fcA_sm,row0,0,lane);
        for(int un=wlocal;un<7;un+=4){
            float d2[2][4]={{0,0,0,0},{0,0,0,0}};
            unit_mma(Af,wb2_sm,WST,un,d2,lane);
            int ns=(un<6)?2:1;
            #pragma unroll
            for(int s=0;s<ns;s++){
                int c=un*16+8*s+2*tig;
                #pragma unroll
                for(int h2=0;h2<2;h2++){
                    int r=row0+g+8*h2;
                    int bb=blk0+(r>>2);
                    *(__half2*)&g_HA[((size_t)(bb*J+(r&3))*TIN+(TIN-1))*HP+c]=__floats2half2_rn(d2[s][2*h2],d2[s][2*h2+1]);
                }
            }
        }
    }
    __syncthreads();

    for(int i=tid;i<3*GSZ;i+=NTHREADS){
        int gate=i/GSZ, rem=i-gate*GSZ, n=rem/WST, k=rem-n*WST;
        whh[i]=(n<100&&k<100)?__float2half(dWhh[(gate*100+n)*100+k]):__half(0.f);
    }
    for(int i=tid;i<104*WWBST;i+=NTHREADS){
        int e=i/WWBST, kk=i-e*WWBST;
        float v=0.f;
        if(e<100){ if(kk<100) v=Ww[e*200+kk]; else if(kk>=112&&kk<212) v=Ww[e*200+kk-12]; }
        wb2[i]=__float2half(v);
    }
    for(int i=tid;i<11*WIHST;i+=NTHREADS){
        int v=i/WIHST,gg=i-v*WIHST;
        wih[i]=(gg<300)?__float2half(dWih[gg*11+v]):__half(0.f);
    }
    for(int i=tid;i<304;i+=NTHREADS){
        float a=(i<300)?dbih[i]:0.f, c=(i<300)?dbhh[i]:0.f;
        bih[i]=a; bhh[i]=c; bsum[i]=a+c;
    }
    for(int i=tid;i<11*104;i+=NTHREADS){int v=i/104,e=i-v*104; vwf[i]=(e<100)?Vw[v*100+e]:0.f;}
    for(int i=tid;i<104;i+=NTHREADS) wbb[i]=(i<100)?Wb[i]:0.f;
    for(int i=tid;i<16;i+=NTHREADS) vbb[i]=(i<VDIM)?Vb[i]:0.f;
    for(int i=tid;i<MROWS*112;i+=NTHREADS){int r=i/112,c=i-r*112; fcA[r*FCA+112+c]=fcA[r*FCA+c];}
    if(tid<MROWS) toks[tid]=VDIM-1;
    __syncthreads();

    {   // init P0 = GRU(SOS, h_last); h_last mirror in region1
        float nacc[2][2][4]={{{0,0,0,0},{0,0,0,0}},{{0,0,0,0},{0,0,0,0}}};
        enc_passA2(fcA_sm,row0,112,whh_sm,wb2_sm,wih,bsum,toks,buf2_sm,buf3_sm,0,blk0,wlocal,lane,false,nacc);
        BARWG();
        gru_n_epi_dec(nacc,row0,wih,bih,bhh,toks,buf2,buf3,fcA,fcA_sm,wlocal,lane);
        BARWG();
    }

    float score=0.f;
    float* sc=&scb[warp*40];
    for(int t=0;t<TOUT;t++){
        {   // scores = HA . P
            int j=lane/10, tt=lane-10*j;
            const int4* hap=(const int4*)&g_HA[((size_t)(b*J+j)*TIN+tt)*HP];
            const int4* pj =(const int4*)&fcA[(warp*J+j)*FCA];
            float accs=0.f;
            #pragma unroll 13
            for(int q=0;q<13;q++){
                int4 hv=hap[q], pv4=pj[q];
                float2 h0=__half22float2(*(__half2*)&hv.x), p0=__half22float2(*(__half2*)&pv4.x);
                float2 h1=__half22float2(*(__half2*)&hv.y), p1=__half22float2(*(__half2*)&pv4.y);
                float2 h2=__half22float2(*(__half2*)&hv.z), p2=__half22float2(*(__half2*)&pv4.z);
                float2 h3=__half22float2(*(__half2*)&hv.w), p3=__half22float2(*(__half2*)&pv4.w);
                accs=fmaf(h0.x,p0.x,accs); accs=fmaf(h0.y,p0.y,accs);
                accs=fmaf(h1.x,p1.x,accs); accs=fmaf(h1.y,p1.y,accs);
                accs=fmaf(h2.x,p2.x,accs); accs=fmaf(h2.y,p2.y,accs);
                accs=fmaf(h3.x,p3.x,accs); accs=fmaf(h3.y,p3.y,accs);
            }
            sc[lane]=accs;
            if(lane<8){
                int t2=32+lane, j2=t2/10, tt2=t2-10*j2;
                const int4* hap2=(const int4*)&g_HA[((size_t)(b*J+j2)*TIN+tt2)*HP];
                const int4* pj2 =(const int4*)&fcA[(warp*J+j2)*FCA];
                float a2=0.f;
                #pragma unroll 13
                for(int q=0;q<13;q++){
                    int4 hv=hap2[q], pv4=pj2[q];
                    float2 h0=__half22float2(*(__half2*)&hv.x), p0=__half22float2(*(__half2*)&pv4.x);
                    float2 h1=__half22float2(*(__half2*)&hv.y), p1=__half22float2(*(__half2*)&pv4.y);
                    float2 h2=__half22float2(*(__half2*)&hv.z), p2=__half22float2(*(__half2*)&pv4.z);
                    float2 h3=__half22float2(*(__half2*)&hv.w), p3=__half22float2(*(__half2*)&pv4.w);
                    a2=fmaf(h0.x,p0.x,a2); a2=fmaf(h0.y,p0.y,a2);
                    a2=fmaf(h1.x,p1.x,a2); a2=fmaf(h1.y,p1.y,a2);
                    a2=fmaf(h2.x,p2.x,a2); a2=fmaf(h2.y,p2.y,a2);
                    a2=fmaf(h3.x,p3.x,a2); a2=fmaf(h3.y,p3.y,a2);
                }
                sc[t2]=a2;
            }
        }
        __syncwarp();
        if(lane<J){
            float mx=-1e30f;
            #pragma unroll
            for(int tt=0;tt<TIN;tt++) mx=fmaxf(mx,sc[lane*10+tt]);
            float s=0.f;
            #pragma unroll
            for(int tt=0;tt<TIN;tt++) s+=__expf(sc[lane*10+tt]-mx);
            float lg=__logf(s)+mx;
            #pragma unroll
            for(int tt=0;tt<TIN;tt++) sc[lane*10+tt]-=lg;
        }
        __syncwarp();
        {   // c = logs . H  (52 tasks over 32 lanes; fp16 H, 8 cols each)
            #pragma unroll
            for(int pass=0;pass<2;pass++){
                int task = pass? 32+lane : lane;
                if(pass && lane>=20) break;
                int j=task/13, q=task-13*j;
                const int4* hb=(const int4*)&g_H[((size_t)(b*J+j)*TIN)*HP];
                float a0=0,a1=0,a2=0,a3=0,a4=0,a5=0,a6=0,a7=0;
                #pragma unroll
                for(int tt=0;tt<TIN;tt++){
                    float lg=sc[j*10+tt];
                    int4 hv=hb[tt*13+q];
                    float2 f0=__half22float2(*(__half2*)&hv.x);
                    float2 f1=__half22float2(*(__half2*)&hv.y);
                    float2 f2=__half22float2(*(__half2*)&hv.z);
                    float2 f3=__half22float2(*(__half2*)&hv.w);
                    a0=fmaf(lg,f0.x,a0); a1=fmaf(lg,f0.y,a1);
                    a2=fmaf(lg,f1.x,a2); a3=fmaf(lg,f1.y,a3);
                    a4=fmaf(lg,f2.x,a4); a5=fmaf(lg,f2.y,a5);
                    a6=fmaf(lg,f3.x,a6); a7=fmaf(lg,f3.y,a7);
                }
                int r=warp*J+j;
                __half2 p0=__floats2half2_rn(a0,a1), p1=__floats2half2_rn(a2,a3);
                __half2 p2=__floats2half2_rn(a4,a5), p3=__floats2half2_rn(a6,a7);
                uint4 pk; pk.x=*(u32*)&p0; pk.y=*(u32*)&p1; pk.z=*(u32*)&p2; pk.w=*(u32*)&p3;
                *(uint4*)&fcA[r*FCA+112+8*q]=pk;
            }
        }
        if(lane<J) toks[warp*J+lane]=target[t*BATCH+b];
        BARWG();
        float nacc[2][2][4]={{{0,0,0,0},{0,0,0,0}},{{0,0,0,0},{0,0,0,0}}};
        dec_passA2(fcA_sm,row0,whh_sm,wb2_sm,wih,bsum,wbb,toks,buf1_sm,buf2_sm,buf3_sm,wlocal,lane,nacc);
        BARWG();
        {   // logits
            float2 mA; mA.x=-1e30f; mA.y=-1e30f; float2 mB=mA;
            #pragma unroll
            for(int j=0;j<J;j++){
                int r=warp*J+j;
                float2 fA=__half22float2(*(const __half2*)&buf1[r*104+e0]);
                mA.x=fmaxf(mA.x,fA.x); mA.y=fmaxf(mA.y,fA.y);
                if(m1){float2 fB=__half22float2(*(const __half2*)&buf1[r*104+e1]);
                    mB.x=fmaxf(mB.x,fB.x); mB.y=fmaxf(mB.y,fB.y);}
            }
            float pv[VDIM];
            #pragma unroll
            for(int v=0;v<VDIM;v++){
                const float* vr=&vwf[v*104];
                float p=vr[e0]*mA.x+vr[e0+1]*mA.y;
                if(m1){p=fmaf(vr[e1],mB.x,p); p=fmaf(vr[e1+1],mB.y,p);}
                pv[v]=p;
            }
            #pragma unroll
            for(int off=16;off>=1;off>>=1){
                #pragma unroll
                for(int v=0;v<VDIM;v++) pv[v]+=__shfl_xor_sync(0xffffffffu,pv[v],off);
            }
            int tok=target[t*BATCH+b];
            float mx=-1e30f;
            #pragma unroll
            for(int v=0;v<VDIM;v++){pv[v]+=vbb[v]; mx=fmaxf(mx,pv[v]);}
            float ss=0.f;
            #pragma unroll
            for(int v=0;v<VDIM;v++) ss+=__expf(pv[v]-mx);
            score+=pv[tok]-mx-__logf(ss);
        }
        gru_n_epi_dec(nacc,row0,wih,bih,bhh,toks,buf2,buf3,fcA,fcA_sm,wlocal,lane);
        BARWG();
    }
    if(lane==0) out[b]=score;
}

extern "C" void kernel_launch(void* const* d_in, const int* in_sizes, int n_in,
                              void* d_out, int out_size)
{
    cudaFuncSetAttribute(fused_kernel, cudaFuncAttributeMaxDynamicSharedMemorySize, SMEM_BYTES);
    int grid=(BATCH+NWARP-1)/NWARP;
    fused_kernel<<<grid, NTHREADS, SMEM_BYTES>>>(
        (const int*)d_in[0], (const int*)d_in[1],
        (const float*)d_in[2], (const float*)d_in[3], (const float*)d_in[4], (const float*)d_in[5],
        (const float*)d_in[6], (const float*)d_in[7], (const float*)d_in[8], (const float*)d_in[9],
        (const float*)d_in[10], (const float*)d_in[11], (const float*)d_in[12], (const float*)d_in[13],
        (const float*)d_in[14], (float*)d_out);
}

// round 14
// speedup vs baseline: 3.6197x; 1.0233x over previous
#include <cuda_runtime.h>
#include <cuda_fp16.h>
#include <cstdint>

#define J 4
#define BATCH 8192
#define TIN 10
#define TOUT 10
#define VDIM 11
#define NWARP 16
#define NTHREADS 512
#define MROWS 64
typedef unsigned long long u64;
typedef uint32_t u32;

#define FCA 232
#define WST 104
#define GSZ (104*104)
#define WWBST 232
#define WIHST 304
#define HP 104

#define OFF_WHH   0
#define OFF_WB2   64896
#define OFF_WIH   113152
#define OFF_VW    119840
#define OFF_BIH   124416
#define OFF_BHH   125632
#define OFF_BSUM  126848
#define OFF_WBB   128064
#define OFF_VB    128480
#define OFF_FCAB  128544
#define OFF_HM    158240
#define OFF_BUF1  184864
#define OFF_BUF2  198176
#define OFF_BUF3  211488
#define OFF_SC    224800
#define OFF_TOK   227360
#define OFF_T2    227616   // half2 tables: bsum2[104], bin2[52], bhn2[52], wbb2[52]
#define SMEM_BYTES 228656

__device__ __half g_H [(size_t)J*BATCH*TIN*HP];
__device__ __half g_HA[(size_t)J*BATCH*TIN*HP];

__device__ __forceinline__ u32 smaddr(const void* p){ u32 a; asm("{.reg .u64 t; cvta.to.shared.u64 t, %1; cvt.u32.u64 %0, t;}":"=r"(a):"l"(p)); return a; }
__device__ __forceinline__ __half2 tanh_h2(__half2 x){
  __half2 r; asm("tanh.approx.f16x2 %0, %1;":"=r"(*(u32*)&r):"r"(*(u32*)&x)); return r;
}
__device__ __forceinline__ __half2 sigm_h2(float a, float b){
  __half2 t=tanh_h2(__floats2half2_rn(0.5f*a,0.5f*b));
  const __half2 hh=__floats2half2_rn(0.5f,0.5f);
  return __hfma2(t,hh,hh);
}
__device__ __forceinline__ __half2 tanh2f(float a, float b){
  return tanh_h2(__floats2half2_rn(a,b));
}
__device__ __forceinline__ void ldsm4(u32&a0,u32&a1,u32&a2,u32&a3,u32 ad){
  asm volatile("ldmatrix.sync.aligned.m8n8.x4.shared.b16 {%0,%1,%2,%3},[%4];":"=r"(a0),"=r"(a1),"=r"(a2),"=r"(a3):"r"(ad));
}
__device__ __forceinline__ void ldsm2(u32&b0,u32&b1,u32 ad){
  asm volatile("ldmatrix.sync.aligned.m8n8.x2.shared.b16 {%0,%1},[%2];":"=r"(b0),"=r"(b1):"r"(ad));
}
__device__ __forceinline__ void stsm4(u32 ad,u32 x0,u32 x1,u32 x2,u32 x3){
  asm volatile("stmatrix.sync.aligned.m8n8.x4.shared.b16 [%0],{%1,%2,%3,%4};"::"r"(ad),"r"(x0),"r"(x1),"r"(x2),"r"(x3):"memory");
}
__device__ __forceinline__ void stsm2(u32 ad,u32 x0,u32 x1){
  asm volatile("stmatrix.sync.aligned.m8n8.x2.shared.b16 [%0],{%1,%2};"::"r"(ad),"r"(x0),"r"(x1):"memory");
}
__device__ __forceinline__ void mma_(float d[4], const u32 a[4], u32 b0,u32 b1){
  asm("mma.sync.aligned.m16n8k16.row.col.f32.f16.f16.f32 {%0,%1,%2,%3},{%4,%5,%6,%7},{%8,%9},{%0,%1,%2,%3};"
   :"+f"(d[0]),"+f"(d[1]),"+f"(d[2]),"+f"(d[3]):"r"(a[0]),"r"(a[1]),"r"(a[2]),"r"(a[3]),"r"(b0),"r"(b1));
}
#define BARWG() asm volatile("bar.sync %0, 128;"::"r"(wg+1):"memory")

__device__ __forceinline__ void ldA7(u32 Af[7][4], u32 fcA_sm, int row0, int acol, int lane){
  int arow=row0+(lane&7)+((lane&8)?8:0);
  u32 base=fcA_sm+(u32)((arow*FCA+acol+((lane&16)?8:0))*2);
  #pragma unroll
  for(int kt=0;kt<7;kt++) ldsm4(Af[kt][0],Af[kt][1],Af[kt][2],Af[kt][3],base+kt*32u);
}

__device__ __forceinline__ void unit_mma(const u32 Af[7][4], u32 bbase, int bst,
                                         int un, float d2[2][4], int lane){
  if(un<6){
    int row=un*16+(lane&7)+((lane&16)?8:0);
    u32 ba=bbase+(u32)((row*bst+((lane&8)?8:0))*2);
    #pragma unroll
    for(int kt=0;kt<7;kt++){
      u32 b0,b1,b2,b3; ldsm4(b0,b1,b2,b3,ba+kt*32u);
      mma_(d2[0],Af[kt],b0,b1); mma_(d2[1],Af[kt],b2,b3);
    }
  }else{
    int l16=lane&15;
    u32 ba=bbase+(u32)(((96+(l16&7))*bst+((l16&8)?8:0))*2);
    #pragma unroll
    for(int kt=0;kt<7;kt++){ u32 b0,b1; ldsm2(b0,b1,ba+kt*32u); mma_(d2[0],Af[kt],b0,b1); }
  }
}

__device__ __forceinline__ u32 stsm_addr(u32 base_sm,int row0,int stride,int c0,int lane){
  int row=row0+(lane&15), col=c0+((lane>>4)<<3);
  return base_sm + (u32)((row*stride+col)*2);
}

// ---- encoder (f32) rz epilogue ----
__device__ __forceinline__ void rz_epi(int gate,int un,float d2[2][4],
    const __half* wih,const float* bsum,const int* toks,
    u32 buf2_sm,u32 buf3_sm,int row0,int g,int tig,int lane){
  int ns=(un<6)?2:1;
  u32 x[4]={0,0,0,0};
  #pragma unroll
  for(int s=0;s<2;s++){
    if(s<ns){
      int c=un*16+8*s+2*tig, gc=gate*100+c;
      float2 bs=*(const float2*)&bsum[gc];
      #pragma unroll
      for(int h2=0;h2<2;h2++){
        int r=row0+g+8*h2;
        float2 w=__half22float2(*(const __half2*)&wih[toks[r]*WIHST+gc]);
        __half2 v=sigm_h2(d2[s][2*h2]+w.x+bs.x, d2[s][2*h2+1]+w.y+bs.y);
        x[2*s+h2]=*(u32*)&v;
      }
    }
  }
  u32 ad=stsm_addr(gate?buf3_sm:buf2_sm,row0,104,un*16,lane);
  if(ns==2) stsm4(ad,x[0],x[1],x[2],x[3]); else stsm2(ad,x[0],x[1]);
}

// ---- decoder (half2) rz epilogue ----
__device__ __forceinline__ void rz_epi_h2(int gate,int un,float d2[2][4],
    const __half* wih,const __half2* bsum2,const int* toks,
    u32 buf2_sm,u32 buf3_sm,int row0,int g,int tig,int lane){
  const __half2 hh5=__floats2half2_rn(0.5f,0.5f);
  int ns=(un<6)?2:1;
  u32 x[4]={0,0,0,0};
  #pragma unroll
  for(int s=0;s<2;s++){
    if(s<ns){
      int c=un*16+8*s+2*tig, gc=gate*100+c;
      __half2 bs=bsum2[gate*52+(c>>1)];
      #pragma unroll
      for(int h2=0;h2<2;h2++){
        int r=row0+g+8*h2;
        __half2 w=*(const __half2*)&wih[toks[r]*WIHST+gc];
        __half2 dd=__floats2half2_rn(d2[s][2*h2],d2[s][2*h2+1]);
        __half2 t=tanh_h2(__hmul2(__hadd2(__hadd2(dd,w),bs),hh5));
        __half2 v=__hfma2(t,hh5,hh5);
        x[2*s+h2]=*(u32*)&v;
      }
    }
  }
  u32 ad=stsm_addr(gate?buf3_sm:buf2_sm,row0,104,un*16,lane);
  if(ns==2) stsm4(ad,x[0],x[1],x[2],x[3]); else stsm2(ad,x[0],x[1]);
}

// encoder pass A: rz + optional ha; n-gate into nacc regs
__device__ __forceinline__ void enc_passA2(u32 fcA_sm,int row0,int acol,u32 whh_sm,u32 aw_sm,
    const __half* wih,const float* bsum,const int* toks,
    u32 buf2_sm,u32 buf3_sm,int tprev,int blk0,int wlocal,int lane,bool do_ha,
    float nacc[2][2][4]){
  int g=lane>>2,tig=lane&3;
  u32 Af[7][4]; ldA7(Af,fcA_sm,row0,acol,lane);
  int nunits=do_ha?21:14;
  for(int u=wlocal;u<nunits;u+=4){
    float d2[2][4]={{0,0,0,0},{0,0,0,0}};
    if(u<14){
      int gate=u/7, un=u-7*gate;
      unit_mma(Af,whh_sm+(u32)(gate*GSZ*2),WST,un,d2,lane);
      rz_epi(gate,un,d2,wih,bsum,toks,buf2_sm,buf3_sm,row0,g,tig,lane);
    }else{
      int un=u-14;
      unit_mma(Af,aw_sm,WST,un,d2,lane);
      int ns=(un<6)?2:1;
      #pragma unroll
      for(int s=0;s<ns;s++){
        int c=un*16+8*s+2*tig;
        #pragma unroll
        for(int h2=0;h2<2;h2++){
          int r=row0+g+8*h2;
          int bb=blk0+(r>>2);
          *(__half2*)&g_HA[((size_t)(bb*J+(r&3))*TIN+tprev)*HP+c]=__floats2half2_rn(d2[s][2*h2],d2[s][2*h2+1]);
        }
      }
    }
  }
  #pragma unroll
  for(int i=0;i<2;i++){
    int un=wlocal+4*i;
    if(un<7) unit_mma(Af,whh_sm+(u32)(2*GSZ*2),WST,un,nacc[i],lane);
  }
}

// encoder n epilogue: hm f32 master + fp16 mirror (stsm) + g_H fp16
__device__ __forceinline__ void gru_n_epi_enc(float nacc[2][2][4],int row0,
    const __half* wih,const float* bih,const float* bhh,const int* toks,
    const __half* buf2,const __half* buf3,float* hm,u32 fcA_sm,int wcol,
    int t,int blk0,int wlocal,int lane){
  int g=lane>>2,tig=lane&3;
  #pragma unroll
  for(int i=0;i<2;i++){
    int un=wlocal+4*i;
    if(un<7){
      int ns=(un<6)?2:1;
      u32 x[4]={0,0,0,0};
      #pragma unroll
      for(int s=0;s<2;s++){
        if(s<ns){
          int c=un*16+8*s+2*tig, gc=200+c;
          float2 bi=*(const float2*)&bih[gc], bh=*(const float2*)&bhh[gc];
          #pragma unroll
          for(int h2=0;h2<2;h2++){
            int r=row0+g+8*h2;
            float2 w=__half22float2(*(const __half2*)&wih[toks[r]*WIHST+gc]);
            float2 rr=__half22float2(*(const __half2*)&buf2[r*104+c]);
            float2 zz=__half22float2(*(const __half2*)&buf3[r*104+c]);
            __half2 nh=tanh2f(w.x+bi.x+rr.x*(nacc[i][s][2*h2]+bh.x),
                              w.y+bi.y+rr.y*(nacc[i][s][2*h2+1]+bh.y));
            float2 nn=__half22float2(nh);
            float2 ho=*(const float2*)&hm[r*104+c];
            float2 hn; hn.x=(1.f-zz.x)*nn.x+zz.x*ho.x; hn.y=(1.f-zz.y)*nn.y+zz.y*ho.y;
            *(float2*)&hm[r*104+c]=hn;
            __half2 hh=__floats2half2_rn(hn.x,hn.y);
            x[2*s+h2]=*(u32*)&hh;
            int bb=blk0+(r>>2);
            *(__half2*)&g_H[((size_t)(bb*J+(r&3))*TIN+t)*HP+c]=hh;
          }
        }
      }
      u32 ad=stsm_addr(fcA_sm,row0,FCA,wcol+un*16,lane);
      if(ns==2) stsm4(ad,x[0],x[1],x[2],x[3]); else stsm2(ad,x[0],x[1]);
    }
  }
}

// decoder n epilogue: full half2 math; old state from fp16 c-mirror, write P-mirror
__device__ __forceinline__ void gru_n_epi_dec(float nacc[2][2][4],int row0,
    const __half* wih,const __half2* bin2,const __half2* bhn2,const int* toks,
    const __half* buf2,const __half* buf3,const __half* fcA,u32 fcA_sm,
    int wlocal,int lane){
  int g=lane>>2,tig=lane&3;
  #pragma unroll
  for(int i=0;i<2;i++){
    int un=wlocal+4*i;
    if(un<7){
      int ns=(un<6)?2:1;
      u32 x[4]={0,0,0,0};
      #pragma unroll
      for(int s=0;s<2;s++){
        if(s<ns){
          int c=un*16+8*s+2*tig, gc=200+c;
          __half2 bi=bin2[c>>1], bh=bhn2[c>>1];
          #pragma unroll
          for(int h2=0;h2<2;h2++){
            int r=row0+g+8*h2;
            __half2 w=*(const __half2*)&wih[toks[r]*WIHST+gc];
            __half2 rr=*(const __half2*)&buf2[r*104+c];
            __half2 zz=*(const __half2*)&buf3[r*104+c];
            __half2 dd=__floats2half2_rn(nacc[i][s][2*h2],nacc[i][s][2*h2+1]);
            __half2 nh=tanh_h2(__hfma2(rr,__hadd2(dd,bh),__hadd2(w,bi)));
            __half2 ho=*(const __half2*)&fcA[r*FCA+112+c];
            __half2 hh=__hfma2(zz,__hsub2(ho,nh),nh);
            x[2*s+h2]=*(u32*)&hh;
          }
        }
      }
      u32 ad=stsm_addr(fcA_sm,row0,FCA,un*16,lane);
      if(ns==2) stsm4(ad,x[0],x[1],x[2],x[3]); else stsm2(ad,x[0],x[1]);
    }
  }
}

// decoder pass A: rz (half2) + fc (half2); n-gate into nacc
__device__ __forceinline__ void dec_passA2(u32 fcA_sm,int row0,u32 whh_sm,u32 wb2_sm,
    const __half* wih,const __half2* bsum2,const __half2* wbb2,const int* toks,
    u32 buf1_sm,u32 buf2_sm,u32 buf3_sm,int wlocal,int lane,float nacc[2][2][4]){
  int g=lane>>2,tig=lane&3;
  u32 Af1[7][4]; ldA7(Af1,fcA_sm,row0,112,lane);
  for(int u=wlocal;u<21;u+=4){
    float d2[2][4]={{0,0,0,0},{0,0,0,0}};
    if(u<14){
      int gate=u/7, un=u-7*gate;
      unit_mma(Af1,whh_sm+(u32)(gate*GSZ*2),WST,un,d2,lane);
      rz_epi_h2(gate,un,d2,wih,bsum2,toks,buf2_sm,buf3_sm,row0,g,tig,lane);
    }else{
      int un=u-14;
      unit_mma(Af1,wb2_sm+(u32)(112*2),WWBST,un,d2,lane);
      u32 Af0[7][4]; ldA7(Af0,fcA_sm,row0,0,lane);
      unit_mma(Af0,wb2_sm,WWBST,un,d2,lane);
      int ns=(un<6)?2:1;
      u32 x[4]={0,0,0,0};
      #pragma unroll
      for(int s=0;s<2;s++){
        if(s<ns){
          int c=un*16+8*s+2*tig;
          __half2 wb=wbb2[c>>1];
          #pragma unroll
          for(int h2=0;h2<2;h2++){
            __half2 dd=__floats2half2_rn(d2[s][2*h2],d2[s][2*h2+1]);
            __half2 v=tanh_h2(__hadd2(dd,wb));
            x[2*s+h2]=*(u32*)&v;
          }
        }
      }
      u32 ad=stsm_addr(buf1_sm,row0,104,un*16,lane);
      if(ns==2) stsm4(ad,x[0],x[1],x[2],x[3]); else stsm2(ad,x[0],x[1]);
    }
  }
  #pragma unroll
  for(int i=0;i<2;i++){
    int un=wlocal+4*i;
    if(un<7) unit_mma(Af1,whh_sm+(u32)(2*GSZ*2),WST,un,nacc[i],lane);
  }
}

__global__ void __launch_bounds__(NTHREADS,1)
fused_kernel(const int* __restrict__ inputs, const int* __restrict__ target,
             const float* __restrict__ eWih, const float* __restrict__ eWhh,
             const float* __restrict__ ebih, const float* __restrict__ ebhh,
             const float* __restrict__ dWih, const float* __restrict__ dWhh,
             const float* __restrict__ dbih, const float* __restrict__ dbhh,
             const float* __restrict__ Ww,  const float* __restrict__ Wb,
             const float* __restrict__ Vw,  const float* __restrict__ Vb,
             const float* __restrict__ Aw,  float* __restrict__ out)
{
    extern __shared__ char smx[];
    __half* whh =(__half*)(smx+OFF_WHH);
    __half* wb2 =(__half*)(smx+OFF_WB2);
    __half* wih =(__half*)(smx+OFF_WIH);
    float*  vwf =(float*)(smx+OFF_VW);
    float*  bih =(float*)(smx+OFF_BIH);
    float*  bhh =(float*)(smx+OFF_BHH);
    float*  bsum=(float*)(smx+OFF_BSUM);
    float*  wbb =(float*)(smx+OFF_WBB);
    float*  vbb =(float*)(smx+OFF_VB);
    __half* fcA =(__half*)(smx+OFF_FCAB);
    float*  hm  =(float*)(smx+OFF_HM);
    __half* buf1=(__half*)(smx+OFF_BUF1);
    __half* buf2=(__half*)(smx+OFF_BUF2);
    __half* buf3=(__half*)(smx+OFF_BUF3);
    float*  scb =(float*)(smx+OFF_SC);
    int*    toks=(int*)(smx+OFF_TOK);
    __half2* bsum2=(__half2*)(smx+OFF_T2);     // [2][52]
    __half2* bin2 = bsum2+104;
    __half2* bhn2 = bin2+52;
    __half2* wbb2 = bhn2+52;

    const u32 fcA_sm=smaddr(fcA), whh_sm=smaddr(whh), wb2_sm=smaddr(wb2);
    const u32 buf1_sm=smaddr(buf1), buf2_sm=smaddr(buf2), buf3_sm=smaddr(buf3);
    const int tid=threadIdx.x, warp=tid>>5, lane=tid&31;
    const int wg=warp>>2, wlocal=warp&3, row0=wg*16;
    const int blk0=blockIdx.x*NWARP;
    const int b=blk0+warp;
    const int e0=2*lane, e1=64+2*lane;
    const bool m1=(lane<18);

    for(int i=tid;i<3*GSZ;i+=NTHREADS){
        int gate=i/GSZ, rem=i-gate*GSZ, n=rem/WST, k=rem-n*WST;
        whh[i]=(n<100&&k<100)?__float2half(eWhh[(gate*100+n)*100+k]):__half(0.f);
    }
    for(int i=tid;i<104*WST;i+=NTHREADS){
        int f=i/WST,e=i-f*WST;
        wb2[i]=(f<100&&e<100)?__float2half(Aw[e*100+f]):__half(0.f);
    }
    for(int i=tid;i<11*WIHST;i+=NTHREADS){
        int v=i/WIHST,gg=i-v*WIHST;
        wih[i]=(gg<300)?__float2half(eWih[gg*11+v]):__half(0.f);
    }
    for(int i=tid;i<304;i+=NTHREADS){
        float a=(i<300)?ebih[i]:0.f, c=(i<300)?ebhh[i]:0.f;
        bih[i]=a; bhh[i]=c; bsum[i]=a+c;
    }
    for(int i=tid;i<MROWS*FCA/2;i+=NTHREADS) ((u32*)fcA)[i]=0u;
    for(int i=tid;i<MROWS*104;i+=NTHREADS) hm[i]=0.f;
    int* toks2=(int*)scb;
    for(int i=tid;i<TIN*MROWS;i+=NTHREADS){
        int t=i/MROWS, r=i-t*MROWS;
        int bb=blk0+(r>>2);
        toks2[i]=inputs[((r&3)*TIN+t)*BATCH+bb];
    }
    __syncthreads();

    for(int t=0;t<TIN;t++){
        int rcol=(t&1)?112:0, wcol=112-rcol;
        float nacc[2][2][4]={{{0,0,0,0},{0,0,0,0}},{{0,0,0,0},{0,0,0,0}}};
        enc_passA2(fcA_sm,row0,rcol,whh_sm,wb2_sm,wih,bsum,&toks2[t*MROWS],
                   buf2_sm,buf3_sm,t-1,blk0,wlocal,lane,t>0,nacc);
        BARWG();
        gru_n_epi_enc(nacc,row0,wih,bih,bhh,&toks2[t*MROWS],buf2,buf3,hm,fcA_sm,wcol,t,blk0,wlocal,lane);
        BARWG();
    }
    {   // final HA(9): h(9) mirror at col 0
        int g=lane>>2,tig=lane&3;
        u32 Af[7][4]; ldA7(Af,fcA_sm,row0,0,lane);
        for(int un=wlocal;un<7;un+=4){
            float d2[2][4]={{0,0,0,0},{0,0,0,0}};
            unit_mma(Af,wb2_sm,WST,un,d2,lane);
            int ns=(un<6)?2:1;
            #pragma unroll
            for(int s=0;s<ns;s++){
                int c=un*16+8*s+2*tig;
                #pragma unroll
                for(int h2=0;h2<2;h2++){
                    int r=row0+g+8*h2;
                    int bb=blk0+(r>>2);
                    *(__half2*)&g_HA[((size_t)(bb*J+(r&3))*TIN+(TIN-1))*HP+c]=__floats2half2_rn(d2[s][2*h2],d2[s][2*h2+1]);
                }
            }
        }
    }
    __syncthreads();

    for(int i=tid;i<3*GSZ;i+=NTHREADS){
        int gate=i/GSZ, rem=i-gate*GSZ, n=rem/WST, k=rem-n*WST;
        whh[i]=(n<100&&k<100)?__float2half(dWhh[(gate*100+n)*100+k]):__half(0.f);
    }
    for(int i=tid;i<104*WWBST;i+=NTHREADS){
        int e=i/WWBST, kk=i-e*WWBST;
        float v=0.f;
        if(e<100){ if(kk<100) v=Ww[e*200+kk]; else if(kk>=112&&kk<212) v=Ww[e*200+kk-12]; }
        wb2[i]=__float2half(v);
    }
    for(int i=tid;i<11*WIHST;i+=NTHREADS){
        int v=i/WIHST,gg=i-v*WIHST;
        wih[i]=(gg<300)?__float2half(dWih[gg*11+v]):__half(0.f);
    }
    for(int i=tid;i<304;i+=NTHREADS){
        float a=(i<300)?dbih[i]:0.f, c=(i<300)?dbhh[i]:0.f;
        bih[i]=a; bhh[i]=c; bsum[i]=a+c;
    }
    for(int i=tid;i<11*104;i+=NTHREADS){int v=i/104,e=i-v*104; vwf[i]=(e<100)?Vw[v*100+e]:0.f;}
    for(int i=tid;i<104;i+=NTHREADS) wbb[i]=(i<100)?Wb[i]:0.f;
    for(int i=tid;i<16;i+=NTHREADS) vbb[i]=(i<VDIM)?Vb[i]:0.f;
    for(int i=tid;i<MROWS*112;i+=NTHREADS){int r=i/112,c=i-r*112; fcA[r*FCA+112+c]=fcA[r*FCA+c];}
    if(tid<MROWS) toks[tid]=VDIM-1;
    __syncthreads();
    // half2 bias tables (needs bsum/bih/bhh/wbb finalized)
    for(int i=tid;i<52;i+=NTHREADS){
        int c=2*i;
        bsum2[i]   =__floats2half2_rn(bsum[c],bsum[c+1]);
        bsum2[52+i]=__floats2half2_rn(bsum[100+c],bsum[100+c+1]);
        bin2[i]=__floats2half2_rn(bih[200+c],bih[200+c+1]);
        bhn2[i]=__floats2half2_rn(bhh[200+c],bhh[200+c+1]);
        wbb2[i]=__floats2half2_rn(wbb[c],wbb[c+1]);
    }
    __syncthreads();

    {   // init P0 = GRU(SOS, h_last); h_last mirror in region1
        float nacc[2][2][4]={{{0,0,0,0},{0,0,0,0}},{{0,0,0,0},{0,0,0,0}}};
        enc_passA2(fcA_sm,row0,112,whh_sm,wb2_sm,wih,bsum,toks,buf2_sm,buf3_sm,0,blk0,wlocal,lane,false,nacc);
        BARWG();
        gru_n_epi_dec(nacc,row0,wih,bin2,bhn2,toks,buf2,buf3,fcA,fcA_sm,wlocal,lane);
        BARWG();
    }

    float score=0.f;
    float* sc=&scb[warp*40];
    for(int t=0;t<TOUT;t++){
        {   // scores = HA . P
            int j=lane/10, tt=lane-10*j;
            const int4* hap=(const int4*)&g_HA[((size_t)(b*J+j)*TIN+tt)*HP];
            const int4* pj =(const int4*)&fcA[(warp*J+j)*FCA];
            float accs=0.f;
            #pragma unroll 13
            for(int q=0;q<13;q++){
                int4 hv=hap[q], pv4=pj[q];
                float2 h0=__half22float2(*(__half2*)&hv.x), p0=__half22float2(*(__half2*)&pv4.x);
                float2 h1=__half22float2(*(__half2*)&hv.y), p1=__half22float2(*(__half2*)&pv4.y);
                float2 h2=__half22float2(*(__half2*)&hv.z), p2=__half22float2(*(__half2*)&pv4.z);
                float2 h3=__half22float2(*(__half2*)&hv.w), p3=__half22float2(*(__half2*)&pv4.w);
                accs=fmaf(h0.x,p0.x,accs); accs=fmaf(h0.y,p0.y,accs);
                accs=fmaf(h1.x,p1.x,accs); accs=fmaf(h1.y,p1.y,accs);
                accs=fmaf(h2.x,p2.x,accs); accs=fmaf(h2.y,p2.y,accs);
                accs=fmaf(h3.x,p3.x,accs); accs=fmaf(h3.y,p3.y,accs);
            }
            sc[lane]=accs;
            if(lane<8){
                int t2=32+lane, j2=t2/10, tt2=t2-10*j2;
                const int4* hap2=(const int4*)&g_HA[((size_t)(b*J+j2)*TIN+tt2)*HP];
                const int4* pj2 =(const int4*)&fcA[(warp*J+j2)*FCA];
                float a2=0.f;
                #pragma unroll 13
                for(int q=0;q<13;q++){
                    int4 hv=hap2[q], pv4=pj2[q];
                    float2 h0=__half22float2(*(__half2*)&hv.x), p0=__half22float2(*(__half2*)&pv4.x);
                    float2 h1=__half22float2(*(__half2*)&hv.y), p1=__half22float2(*(__half2*)&pv4.y);
                    float2 h2=__half22float2(*(__half2*)&hv.z), p2=__half22float2(*(__half2*)&pv4.z);
                    float2 h3=__half22float2(*(__half2*)&hv.w), p3=__half22float2(*(__half2*)&pv4.w);
                    a2=fmaf(h0.x,p0.x,a2); a2=fmaf(h0.y,p0.y,a2);
                    a2=fmaf(h1.x,p1.x,a2); a2=fmaf(h1.y,p1.y,a2);
                    a2=fmaf(h2.x,p2.x,a2); a2=fmaf(h2.y,p2.y,a2);
                    a2=fmaf(h3.x,p3.x,a2); a2=fmaf(h3.y,p3.y,a2);
                }
                sc[t2]=a2;
            }
        }
        __syncwarp();
        if(lane<J){
            float mx=-1e30f;
            #pragma unroll
            for(int tt=0;tt<TIN;tt++) mx=fmaxf(mx,sc[lane*10+tt]);
            float s=0.f;
            #pragma unroll
            for(int tt=0;tt<TIN;tt++) s+=__expf(sc[lane*10+tt]-mx);
            float lg=__logf(s)+mx;
            #pragma unroll
            for(int tt=0;tt<TIN;tt++) sc[lane*10+tt]-=lg;
        }
        __syncwarp();
        {   // c = logs . H  (52 tasks over 32 lanes; fp16 H, 8 cols each)
            #pragma unroll
            for(int pass=0;pass<2;pass++){
                int task = pass? 32+lane : lane;
                if(pass && lane>=20) break;
                int j=task/13, q=task-13*j;
                const int4* hb=(const int4*)&g_H[((size_t)(b*J+j)*TIN)*HP];
                float a0=0,a1=0,a2=0,a3=0,a4=0,a5=0,a6=0,a7=0;
                #pragma unroll
                for(int tt=0;tt<TIN;tt++){
                    float lg=sc[j*10+tt];
                    int4 hv=hb[tt*13+q];
                    float2 f0=__half22float2(*(__half2*)&hv.x);
                    float2 f1=__half22float2(*(__half2*)&hv.y);
                    float2 f2=__half22float2(*(__half2*)&hv.z);
                    float2 f3=__half22float2(*(__half2*)&hv.w);
                    a0=fmaf(lg,f0.x,a0); a1=fmaf(lg,f0.y,a1);
                    a2=fmaf(lg,f1.x,a2); a3=fmaf(lg,f1.y,a3);
                    a4=fmaf(lg,f2.x,a4); a5=fmaf(lg,f2.y,a5);
                    a6=fmaf(lg,f3.x,a6); a7=fmaf(lg,f3.y,a7);
                }
                int r=warp*J+j;
                __half2 p0=__floats2half2_rn(a0,a1), p1=__floats2half2_rn(a2,a3);
                __half2 p2=__floats2half2_rn(a4,a5), p3=__floats2half2_rn(a6,a7);
                uint4 pk; pk.x=*(u32*)&p0; pk.y=*(u32*)&p1; pk.z=*(u32*)&p2; pk.w=*(u32*)&p3;
                *(uint4*)&fcA[r*FCA+112+8*q]=pk;
            }
        }
        if(lane<J) toks[warp*J+lane]=target[t*BATCH+b];
        BARWG();
        float nacc[2][2][4]={{{0,0,0,0},{0,0,0,0}},{{0,0,0,0},{0,0,0,0}}};
        dec_passA2(fcA_sm,row0,whh_sm,wb2_sm,wih,bsum2,wbb2,toks,buf1_sm,buf2_sm,buf3_sm,wlocal,lane,nacc);
        BARWG();
        {   // logits (half2 max)
            __half2 mA2=__floats2half2_rn(-60000.f,-60000.f), mB2=mA2;
            #pragma unroll
            for(int j=0;j<J;j++){
                int r=warp*J+j;
                mA2=__hmax2(mA2,*(const __half2*)&buf1[r*104+e0]);
                if(m1) mB2=__hmax2(mB2,*(const __half2*)&buf1[r*104+e1]);
            }
            float2 mA=__half22float2(mA2);
            float2 mB=m1?__half22float2(mB2):make_float2(0.f,0.f);
            float pv[VDIM];
            #pragma unroll
            for(int v=0;v<VDIM;v++){
                const float* vr=&vwf[v*104];
                float p=vr[e0]*mA.x+vr[e0+1]*mA.y;
                if(m1){p=fmaf(vr[e1],mB.x,p); p=fmaf(vr[e1+1],mB.y,p);}
                pv[v]=p;
            }
            #pragma unroll
            for(int off=16;off>=1;off>>=1){
                #pragma unroll
                for(int v=0;v<VDIM;v++) pv[v]+=__shfl_xor_sync(0xffffffffu,pv[v],off);
            }
            int tok=target[t*BATCH+b];
            float mx=-1e30f;
            #pragma unroll
            for(int v=0;v<VDIM;v++){pv[v]+=vbb[v]; mx=fmaxf(mx,pv[v]);}
            float ss=0.f;
            #pragma unroll
            for(int v=0;v<VDIM;v++) ss+=__expf(pv[v]-mx);
            score+=pv[tok]-mx-__logf(ss);
        }
        gru_n_epi_dec(nacc,row0,wih,bin2,bhn2,toks,buf2,buf3,fcA,fcA_sm,wlocal,lane);
        BARWG();
    }
    if(lane==0) out[b]=score;
}

extern "C" void kernel_launch(void* const* d_in, const int* in_sizes, int n_in,
                              void* d_out, int out_size)
{
    cudaFuncSetAttribute(fused_kernel, cudaFuncAttributeMaxDynamicSharedMemorySize, SMEM_BYTES);
    int grid=(BATCH+NWARP-1)/NWARP;
    fused_kernel<<<grid, NTHREADS, SMEM_BYTES>>>(
        (const int*)d_in[0], (const int*)d_in[1],
        (const float*)d_in[2], (const float*)d_in[3], (const float*)d_in[4], (const float*)d_in[5],
        (const float*)d_in[6], (const float*)d_in[7], (const float*)d_in[8], (const float*)d_in[9],
        (const float*)d_in[10], (const float*)d_in[11], (const float*)d_in[12], (const float*)d_in[13],
        (const float*)d_in[14], (float*)d_out);
}

// round 15
// speedup vs baseline: 3.6409x; 1.0058x over previous
#include <cuda_runtime.h>
#include <cuda_fp16.h>
#include <cstdint>

#define J 4
#define BATCH 8192
#define TIN 10
#define TOUT 10
#define VDIM 11
#define NWARP 16
#define NTHREADS 512
#define MROWS 64
typedef unsigned long long u64;
typedef uint32_t u32;

#define FCA 232
#define WST 104
#define GSZ (104*104)
#define WWBST 232
#define WIHST 304
#define HP 104

#define OFF_WHH   0
#define OFF_WB2   64896
#define OFF_WIH   113152
#define OFF_VW    119840
#define OFF_BIH   124416
#define OFF_BHH   125632
#define OFF_BSUM  126848
#define OFF_WBB   128064
#define OFF_VB    128480
#define OFF_FCAB  128544
#define OFF_HM    158240
#define OFF_BUF1  184864
#define OFF_BUF2  198176
#define OFF_BUF3  211488
#define OFF_SC    224800
#define OFF_TOK   227360
#define OFF_T2    227616
#define SMEM_BYTES 228656

__device__ __half g_H [(size_t)J*BATCH*TIN*HP];
__device__ __half g_HA[(size_t)J*BATCH*TIN*HP];

__device__ __forceinline__ u32 smaddr(const void* p){ u32 a; asm("{.reg .u64 t; cvta.to.shared.u64 t, %1; cvt.u32.u64 %0, t;}":"=r"(a):"l"(p)); return a; }
__device__ __forceinline__ void fma2(u64 &d, u64 a, u64 b){
    asm("fma.rn.f32x2 %0, %1, %2, %0;" : "+l"(d) : "l"(a), "l"(b));
}
__device__ __forceinline__ u64 dup2(float x){ u64 r; asm("mov.b64 %0, {%1, %1};" : "=l"(r) : "f"(x)); return r; }
__device__ __forceinline__ float2 unpack2(u64 v){ float2 f; asm("mov.b64 {%0, %1}, %2;" : "=f"(f.x), "=f"(f.y) : "l"(v)); return f; }
__device__ __forceinline__ u64 h2f2(u32 h){   // half2 -> packed f32x2
    float2 f=__half22float2(*(__half2*)&h);
    u64 r; asm("mov.b64 %0, {%1, %2};" : "=l"(r) : "f"(f.x), "f"(f.y)); return r;
}
__device__ __forceinline__ __half2 tanh_h2(__half2 x){
  __half2 r; asm("tanh.approx.f16x2 %0, %1;":"=r"(*(u32*)&r):"r"(*(u32*)&x)); return r;
}
__device__ __forceinline__ __half2 sigm_h2(float a, float b){
  __half2 t=tanh_h2(__floats2half2_rn(0.5f*a,0.5f*b));
  const __half2 hh=__floats2half2_rn(0.5f,0.5f);
  return __hfma2(t,hh,hh);
}
__device__ __forceinline__ __half2 tanh2f(float a, float b){
  return tanh_h2(__floats2half2_rn(a,b));
}
__device__ __forceinline__ void ldsm4(u32&a0,u32&a1,u32&a2,u32&a3,u32 ad){
  asm volatile("ldmatrix.sync.aligned.m8n8.x4.shared.b16 {%0,%1,%2,%3},[%4];":"=r"(a0),"=r"(a1),"=r"(a2),"=r"(a3):"r"(ad));
}
__device__ __forceinline__ void ldsm2(u32&b0,u32&b1,u32 ad){
  asm volatile("ldmatrix.sync.aligned.m8n8.x2.shared.b16 {%0,%1},[%2];":"=r"(b0),"=r"(b1):"r"(ad));
}
__device__ __forceinline__ void stsm4(u32 ad,u32 x0,u32 x1,u32 x2,u32 x3){
  asm volatile("stmatrix.sync.aligned.m8n8.x4.shared.b16 [%0],{%1,%2,%3,%4};"::"r"(ad),"r"(x0),"r"(x1),"r"(x2),"r"(x3):"memory");
}
__device__ __forceinline__ void stsm2(u32 ad,u32 x0,u32 x1){
  asm volatile("stmatrix.sync.aligned.m8n8.x2.shared.b16 [%0],{%1,%2};"::"r"(ad),"r"(x0),"r"(x1):"memory");
}
__device__ __forceinline__ void mma_(float d[4], const u32 a[4], u32 b0,u32 b1){
  asm("mma.sync.aligned.m16n8k16.row.col.f32.f16.f16.f32 {%0,%1,%2,%3},{%4,%5,%6,%7},{%8,%9},{%0,%1,%2,%3};"
   :"+f"(d[0]),"+f"(d[1]),"+f"(d[2]),"+f"(d[3]):"r"(a[0]),"r"(a[1]),"r"(a[2]),"r"(a[3]),"r"(b0),"r"(b1));
}
#define BARWG() asm volatile("bar.sync %0, 128;"::"r"(wg+1):"memory")

__device__ __forceinline__ void ldA7(u32 Af[7][4], u32 fcA_sm, int row0, int acol, int lane){
  int arow=row0+(lane&7)+((lane&8)?8:0);
  u32 base=fcA_sm+(u32)((arow*FCA+acol+((lane&16)?8:0))*2);
  #pragma unroll
  for(int kt=0;kt<7;kt++) ldsm4(Af[kt][0],Af[kt][1],Af[kt][2],Af[kt][3],base+kt*32u);
}

__device__ __forceinline__ void unit_mma(const u32 Af[7][4], u32 bbase, int bst,
                                         int un, float d2[2][4], int lane){
  if(un<6){
    int row=un*16+(lane&7)+((lane&16)?8:0);
    u32 ba=bbase+(u32)((row*bst+((lane&8)?8:0))*2);
    #pragma unroll
    for(int kt=0;kt<7;kt++){
      u32 b0,b1,b2,b3; ldsm4(b0,b1,b2,b3,ba+kt*32u);
      mma_(d2[0],Af[kt],b0,b1); mma_(d2[1],Af[kt],b2,b3);
    }
  }else{
    int l16=lane&15;
    u32 ba=bbase+(u32)(((96+(l16&7))*bst+((l16&8)?8:0))*2);
    #pragma unroll
    for(int kt=0;kt<7;kt++){ u32 b0,b1; ldsm2(b0,b1,ba+kt*32u); mma_(d2[0],Af[kt],b0,b1); }
  }
}

__device__ __forceinline__ u32 stsm_addr(u32 base_sm,int row0,int stride,int c0,int lane){
  int row=row0+(lane&15), col=c0+((lane>>4)<<3);
  return base_sm + (u32)((row*stride+col)*2);
}

// ---- encoder (f32) rz epilogue ----
__device__ __forceinline__ void rz_epi(int gate,int un,float d2[2][4],
    const __half* wih,const float* bsum,const int* toks,
    u32 buf2_sm,u32 buf3_sm,int row0,int g,int tig,int lane){
  int ns=(un<6)?2:1;
  u32 x[4]={0,0,0,0};
  #pragma unroll
  for(int s=0;s<2;s++){
    if(s<ns){
      int c=un*16+8*s+2*tig, gc=gate*100+c;
      float2 bs=*(const float2*)&bsum[gc];
      #pragma unroll
      for(int h2=0;h2<2;h2++){
        int r=row0+g+8*h2;
        float2 w=__half22float2(*(const __half2*)&wih[toks[r]*WIHST+gc]);
        __half2 v=sigm_h2(d2[s][2*h2]+w.x+bs.x, d2[s][2*h2+1]+w.y+bs.y);
        x[2*s+h2]=*(u32*)&v;
      }
    }
  }
  u32 ad=stsm_addr(gate?buf3_sm:buf2_sm,row0,104,un*16,lane);
  if(ns==2) stsm4(ad,x[0],x[1],x[2],x[3]); else stsm2(ad,x[0],x[1]);
}

// ---- decoder (half2) rz epilogue ----
__device__ __forceinline__ void rz_epi_h2(int gate,int un,float d2[2][4],
    const __half* wih,const __half2* bsum2,const int* toks,
    u32 buf2_sm,u32 buf3_sm,int row0,int g,int tig,int lane){
  const __half2 hh5=__floats2half2_rn(0.5f,0.5f);
  int ns=(un<6)?2:1;
  u32 x[4]={0,0,0,0};
  #pragma unroll
  for(int s=0;s<2;s++){
    if(s<ns){
      int c=un*16+8*s+2*tig, gc=gate*100+c;
      __half2 bs=bsum2[gate*52+(c>>1)];
      #pragma unroll
      for(int h2=0;h2<2;h2++){
        int r=row0+g+8*h2;
        __half2 w=*(const __half2*)&wih[toks[r]*WIHST+gc];
        __half2 dd=__floats2half2_rn(d2[s][2*h2],d2[s][2*h2+1]);
        __half2 t=tanh_h2(__hmul2(__hadd2(__hadd2(dd,w),bs),hh5));
        __half2 v=__hfma2(t,hh5,hh5);
        x[2*s+h2]=*(u32*)&v;
      }
    }
  }
  u32 ad=stsm_addr(gate?buf3_sm:buf2_sm,row0,104,un*16,lane);
  if(ns==2) stsm4(ad,x[0],x[1],x[2],x[3]); else stsm2(ad,x[0],x[1]);
}

// encoder pass A: rz + optional ha; n-gate into nacc regs
__device__ __forceinline__ void enc_passA2(u32 fcA_sm,int row0,int acol,u32 whh_sm,u32 aw_sm,
    const __half* wih,const float* bsum,const int* toks,
    u32 buf2_sm,u32 buf3_sm,int tprev,int blk0,int wlocal,int lane,bool do_ha,
    float nacc[2][2][4]){
  int g=lane>>2,tig=lane&3;
  u32 Af[7][4]; ldA7(Af,fcA_sm,row0,acol,lane);
  int nunits=do_ha?21:14;
  for(int u=wlocal;u<nunits;u+=4){
    float d2[2][4]={{0,0,0,0},{0,0,0,0}};
    if(u<14){
      int gate=u/7, un=u-7*gate;
      unit_mma(Af,whh_sm+(u32)(gate*GSZ*2),WST,un,d2,lane);
      rz_epi(gate,un,d2,wih,bsum,toks,buf2_sm,buf3_sm,row0,g,tig,lane);
    }else{
      int un=u-14;
      unit_mma(Af,aw_sm,WST,un,d2,lane);
      int ns=(un<6)?2:1;
      #pragma unroll
      for(int s=0;s<ns;s++){
        int c=un*16+8*s+2*tig;
        #pragma unroll
        for(int h2=0;h2<2;h2++){
          int r=row0+g+8*h2;
          int bb=blk0+(r>>2);
          *(__half2*)&g_HA[((size_t)(bb*J+(r&3))*TIN+tprev)*HP+c]=__floats2half2_rn(d2[s][2*h2],d2[s][2*h2+1]);
        }
      }
    }
  }
  #pragma unroll
  for(int i=0;i<2;i++){
    int un=wlocal+4*i;
    if(un<7) unit_mma(Af,whh_sm+(u32)(2*GSZ*2),WST,un,nacc[i],lane);
  }
}

// encoder n epilogue
__device__ __forceinline__ void gru_n_epi_enc(float nacc[2][2][4],int row0,
    const __half* wih,const float* bih,const float* bhh,const int* toks,
    const __half* buf2,const __half* buf3,float* hm,u32 fcA_sm,int wcol,
    int t,int blk0,int wlocal,int lane){
  int g=lane>>2,tig=lane&3;
  #pragma unroll
  for(int i=0;i<2;i++){
    int un=wlocal+4*i;
    if(un<7){
      int ns=(un<6)?2:1;
      u32 x[4]={0,0,0,0};
      #pragma unroll
      for(int s=0;s<2;s++){
        if(s<ns){
          int c=un*16+8*s+2*tig, gc=200+c;
          float2 bi=*(const float2*)&bih[gc], bh=*(const float2*)&bhh[gc];
          #pragma unroll
          for(int h2=0;h2<2;h2++){
            int r=row0+g+8*h2;
            float2 w=__half22float2(*(const __half2*)&wih[toks[r]*WIHST+gc]);
            float2 rr=__half22float2(*(const __half2*)&buf2[r*104+c]);
            float2 zz=__half22float2(*(const __half2*)&buf3[r*104+c]);
            __half2 nh=tanh2f(w.x+bi.x+rr.x*(nacc[i][s][2*h2]+bh.x),
                              w.y+bi.y+rr.y*(nacc[i][s][2*h2+1]+bh.y));
            float2 nn=__half22float2(nh);
            float2 ho=*(const float2*)&hm[r*104+c];
            float2 hn; hn.x=(1.f-zz.x)*nn.x+zz.x*ho.x; hn.y=(1.f-zz.y)*nn.y+zz.y*ho.y;
            *(float2*)&hm[r*104+c]=hn;
            __half2 hh=__floats2half2_rn(hn.x,hn.y);
            x[2*s+h2]=*(u32*)&hh;
            int bb=blk0+(r>>2);
            *(__half2*)&g_H[((size_t)(bb*J+(r&3))*TIN+t)*HP+c]=hh;
          }
        }
      }
      u32 ad=stsm_addr(fcA_sm,row0,FCA,wcol+un*16,lane);
      if(ns==2) stsm4(ad,x[0],x[1],x[2],x[3]); else stsm2(ad,x[0],x[1]);
    }
  }
}

// decoder n epilogue: half2
__device__ __forceinline__ void gru_n_epi_dec(float nacc[2][2][4],int row0,
    const __half* wih,const __half2* bin2,const __half2* bhn2,const int* toks,
    const __half* buf2,const __half* buf3,const __half* fcA,u32 fcA_sm,
    int wlocal,int lane){
  int g=lane>>2,tig=lane&3;
  #pragma unroll
  for(int i=0;i<2;i++){
    int un=wlocal+4*i;
    if(un<7){
      int ns=(un<6)?2:1;
      u32 x[4]={0,0,0,0};
      #pragma unroll
      for(int s=0;s<2;s++){
        if(s<ns){
          int c=un*16+8*s+2*tig, gc=200+c;
          __half2 bi=bin2[c>>1], bh=bhn2[c>>1];
          #pragma unroll
          for(int h2=0;h2<2;h2++){
            int r=row0+g+8*h2;
            __half2 w=*(const __half2*)&wih[toks[r]*WIHST+gc];
            __half2 rr=*(const __half2*)&buf2[r*104+c];
            __half2 zz=*(const __half2*)&buf3[r*104+c];
            __half2 dd=__floats2half2_rn(nacc[i][s][2*h2],nacc[i][s][2*h2+1]);
            __half2 nh=tanh_h2(__hfma2(rr,__hadd2(dd,bh),__hadd2(w,bi)));
            __half2 ho=*(const __half2*)&fcA[r*FCA+112+c];
            __half2 hh=__hfma2(zz,__hsub2(ho,nh),nh);
            x[2*s+h2]=*(u32*)&hh;
          }
        }
      }
      u32 ad=stsm_addr(fcA_sm,row0,FCA,un*16,lane);
      if(ns==2) stsm4(ad,x[0],x[1],x[2],x[3]); else stsm2(ad,x[0],x[1]);
    }
  }
}

// decoder pass A: rz loop (Af1 only) then fc loop (Af0 hoisted) ; n-gate into nacc
__device__ __forceinline__ void dec_passA2(u32 fcA_sm,int row0,u32 whh_sm,u32 wb2_sm,
    const __half* wih,const __half2* bsum2,const __half2* wbb2,const int* toks,
    u32 buf1_sm,u32 buf2_sm,u32 buf3_sm,int wlocal,int lane,float nacc[2][2][4]){
  int g=lane>>2,tig=lane&3;
  u32 Af1[7][4]; ldA7(Af1,fcA_sm,row0,112,lane);
  for(int u=wlocal;u<14;u+=4){
    float d2[2][4]={{0,0,0,0},{0,0,0,0}};
    int gate=u/7, un=u-7*gate;
    unit_mma(Af1,whh_sm+(u32)(gate*GSZ*2),WST,un,d2,lane);
    rz_epi_h2(gate,un,d2,wih,bsum2,toks,buf2_sm,buf3_sm,row0,g,tig,lane);
  }
  {
    u32 Af0[7][4]; ldA7(Af0,fcA_sm,row0,0,lane);
    for(int un=((14+3-wlocal)&3)+wlocal>=4?wlocal:wlocal, uu=0; uu<2; uu++){
      int ufc = wlocal+4*uu + 14 - 14;   // fc units: u=14+..20 -> un = u-14 covers wlocal-aligned
      (void)un;
      int ufc_u = 14 + wlocal + 4*uu;
      if(ufc_u>20) break;
      int unf = ufc_u-14;
      float d2[2][4]={{0,0,0,0},{0,0,0,0}};
      unit_mma(Af1,wb2_sm+(u32)(112*2),WWBST,unf,d2,lane);
      unit_mma(Af0,wb2_sm,WWBST,unf,d2,lane);
      int ns=(unf<6)?2:1;
      u32 x[4]={0,0,0,0};
      #pragma unroll
      for(int s=0;s<2;s++){
        if(s<ns){
          int c=unf*16+8*s+2*tig;
          __half2 wb=wbb2[c>>1];
          #pragma unroll
          for(int h2=0;h2<2;h2++){
            __half2 dd=__floats2half2_rn(d2[s][2*h2],d2[s][2*h2+1]);
            __half2 v=tanh_h2(__hadd2(dd,wb));
            x[2*s+h2]=*(u32*)&v;
          }
        }
      }
      u32 ad=stsm_addr(buf1_sm,row0,104,unf*16,lane);
      if(ns==2) stsm4(ad,x[0],x[1],x[2],x[3]); else stsm2(ad,x[0],x[1]);
    }
  }
  #pragma unroll
  for(int i=0;i<2;i++){
    int un=wlocal+4*i;
    if(un<7) unit_mma(Af1,whh_sm+(u32)(2*GSZ*2),WST,un,nacc[i],lane);
  }
}

__global__ void __launch_bounds__(NTHREADS,1)
fused_kernel(const int* __restrict__ inputs, const int* __restrict__ target,
             const float* __restrict__ eWih, const float* __restrict__ eWhh,
             const float* __restrict__ ebih, const float* __restrict__ ebhh,
             const float* __restrict__ dWih, const float* __restrict__ dWhh,
             const float* __restrict__ dbih, const float* __restrict__ dbhh,
             const float* __restrict__ Ww,  const float* __restrict__ Wb,
             const float* __restrict__ Vw,  const float* __restrict__ Vb,
             const float* __restrict__ Aw,  float* __restrict__ out)
{
    extern __shared__ char smx[];
    __half* whh =(__half*)(smx+OFF_WHH);
    __half* wb2 =(__half*)(smx+OFF_WB2);
    __half* wih =(__half*)(smx+OFF_WIH);
    float*  vwf =(float*)(smx+OFF_VW);
    float*  bih =(float*)(smx+OFF_BIH);
    float*  bhh =(float*)(smx+OFF_BHH);
    float*  bsum=(float*)(smx+OFF_BSUM);
    float*  wbb =(float*)(smx+OFF_WBB);
    float*  vbb =(float*)(smx+OFF_VB);
    __half* fcA =(__half*)(smx+OFF_FCAB);
    float*  hm  =(float*)(smx+OFF_HM);
    __half* buf1=(__half*)(smx+OFF_BUF1);
    __half* buf2=(__half*)(smx+OFF_BUF2);
    __half* buf3=(__half*)(smx+OFF_BUF3);
    float*  scb =(float*)(smx+OFF_SC);
    int*    toks=(int*)(smx+OFF_TOK);
    __half2* bsum2=(__half2*)(smx+OFF_T2);
    __half2* bin2 = bsum2+104;
    __half2* bhn2 = bin2+52;
    __half2* wbb2 = bhn2+52;

    const u32 fcA_sm=smaddr(fcA), whh_sm=smaddr(whh), wb2_sm=smaddr(wb2);
    const u32 buf1_sm=smaddr(buf1), buf2_sm=smaddr(buf2), buf3_sm=smaddr(buf3);
    const int tid=threadIdx.x, warp=tid>>5, lane=tid&31;
    const int wg=warp>>2, wlocal=warp&3, row0=wg*16;
    const int blk0=blockIdx.x*NWARP;
    const int b=blk0+warp;
    const int e0=2*lane, e1=64+2*lane;
    const bool m1=(lane<18);

    for(int i=tid;i<3*GSZ;i+=NTHREADS){
        int gate=i/GSZ, rem=i-gate*GSZ, n=rem/WST, k=rem-n*WST;
        whh[i]=(n<100&&k<100)?__float2half(eWhh[(gate*100+n)*100+k]):__half(0.f);
    }
    for(int i=tid;i<104*WST;i+=NTHREADS){
        int f=i/WST,e=i-f*WST;
        wb2[i]=(f<100&&e<100)?__float2half(Aw[e*100+f]):__half(0.f);
    }
    for(int i=tid;i<11*WIHST;i+=NTHREADS){
        int v=i/WIHST,gg=i-v*WIHST;
        wih[i]=(gg<300)?__float2half(eWih[gg*11+v]):__half(0.f);
    }
    for(int i=tid;i<304;i+=NTHREADS){
        float a=(i<300)?ebih[i]:0.f, c=(i<300)?ebhh[i]:0.f;
        bih[i]=a; bhh[i]=c; bsum[i]=a+c;
    }
    for(int i=tid;i<MROWS*FCA/2;i+=NTHREADS) ((u32*)fcA)[i]=0u;
    for(int i=tid;i<MROWS*104;i+=NTHREADS) hm[i]=0.f;
    int* toks2=(int*)scb;
    for(int i=tid;i<TIN*MROWS;i+=NTHREADS){
        int t=i/MROWS, r=i-t*MROWS;
        int bb=blk0+(r>>2);
        toks2[i]=inputs[((r&3)*TIN+t)*BATCH+bb];
    }
    __syncthreads();

    for(int t=0;t<TIN;t++){
        int rcol=(t&1)?112:0, wcol=112-rcol;
        float nacc[2][2][4]={{{0,0,0,0},{0,0,0,0}},{{0,0,0,0},{0,0,0,0}}};
        enc_passA2(fcA_sm,row0,rcol,whh_sm,wb2_sm,wih,bsum,&toks2[t*MROWS],
                   buf2_sm,buf3_sm,t-1,blk0,wlocal,lane,t>0,nacc);
        BARWG();
        gru_n_epi_enc(nacc,row0,wih,bih,bhh,&toks2[t*MROWS],buf2,buf3,hm,fcA_sm,wcol,t,blk0,wlocal,lane);
        BARWG();
    }
    {   // final HA(9)
        int g=lane>>2,tig=lane&3;
        u32 Af[7][4]; ldA7(Af,fcA_sm,row0,0,lane);
        for(int un=wlocal;un<7;un+=4){
            float d2[2][4]={{0,0,0,0},{0,0,0,0}};
            unit_mma(Af,wb2_sm,WST,un,d2,lane);
            int ns=(un<6)?2:1;
            #pragma unroll
            for(int s=0;s<ns;s++){
                int c=un*16+8*s+2*tig;
                #pragma unroll
                for(int h2=0;h2<2;h2++){
                    int r=row0+g+8*h2;
                    int bb=blk0+(r>>2);
                    *(__half2*)&g_HA[((size_t)(bb*J+(r&3))*TIN+(TIN-1))*HP+c]=__floats2half2_rn(d2[s][2*h2],d2[s][2*h2+1]);
                }
            }
        }
    }
    __syncthreads();

    for(int i=tid;i<3*GSZ;i+=NTHREADS){
        int gate=i/GSZ, rem=i-gate*GSZ, n=rem/WST, k=rem-n*WST;
        whh[i]=(n<100&&k<100)?__float2half(dWhh[(gate*100+n)*100+k]):__half(0.f);
    }
    for(int i=tid;i<104*WWBST;i+=NTHREADS){
        int e=i/WWBST, kk=i-e*WWBST;
        float v=0.f;
        if(e<100){ if(kk<100) v=Ww[e*200+kk]; else if(kk>=112&&kk<212) v=Ww[e*200+kk-12]; }
        wb2[i]=__float2half(v);
    }
    for(int i=tid;i<11*WIHST;i+=NTHREADS){
        int v=i/WIHST,gg=i-v*WIHST;
        wih[i]=(gg<300)?__float2half(dWih[gg*11+v]):__half(0.f);
    }
    for(int i=tid;i<304;i+=NTHREADS){
        float a=(i<300)?dbih[i]:0.f, c=(i<300)?dbhh[i]:0.f;
        bih[i]=a; bhh[i]=c; bsum[i]=a+c;
    }
    for(int i=tid;i<11*104;i+=NTHREADS){int v=i/104,e=i-v*104; vwf[i]=(e<100)?Vw[v*100+e]:0.f;}
    for(int i=tid;i<104;i+=NTHREADS) wbb[i]=(i<100)?Wb[i]:0.f;
    for(int i=tid;i<16;i+=NTHREADS) vbb[i]=(i<VDIM)?Vb[i]:0.f;
    for(int i=tid;i<MROWS*112;i+=NTHREADS){int r=i/112,c=i-r*112; fcA[r*FCA+112+c]=fcA[r*FCA+c];}
    if(tid<MROWS) toks[tid]=VDIM-1;
    __syncthreads();
    for(int i=tid;i<52;i+=NTHREADS){
        int c=2*i;
        bsum2[i]   =__floats2half2_rn(bsum[c],bsum[c+1]);
        bsum2[52+i]=__floats2half2_rn(bsum[100+c],bsum[100+c+1]);
        bin2[i]=__floats2half2_rn(bih[200+c],bih[200+c+1]);
        bhn2[i]=__floats2half2_rn(bhh[200+c],bhh[200+c+1]);
        wbb2[i]=__floats2half2_rn(wbb[c],wbb[c+1]);
    }
    __syncthreads();

    {   // init P0
        float nacc[2][2][4]={{{0,0,0,0},{0,0,0,0}},{{0,0,0,0},{0,0,0,0}}};
        enc_passA2(fcA_sm,row0,112,whh_sm,wb2_sm,wih,bsum,toks,buf2_sm,buf3_sm,0,blk0,wlocal,lane,false,nacc);
        BARWG();
        gru_n_epi_dec(nacc,row0,wih,bin2,bhn2,toks,buf2,buf3,fcA,fcA_sm,wlocal,lane);
        BARWG();
    }

    float score=0.f;
    float* sc=&scb[warp*40];
    for(int t=0;t<TOUT;t++){
        {   // scores = HA . P  (packed f32x2)
            int j=lane/10, tt=lane-10*j;
            const uint4* hap=(const uint4*)&g_HA[((size_t)(b*J+j)*TIN+tt)*HP];
            const uint4* pj =(const uint4*)&fcA[(warp*J+j)*FCA];
            u64 acc=0ull;
            #pragma unroll 13
            for(int q=0;q<13;q++){
                uint4 hv=hap[q], pv4=pj[q];
                fma2(acc,h2f2(hv.x),h2f2(pv4.x));
                fma2(acc,h2f2(hv.y),h2f2(pv4.y));
                fma2(acc,h2f2(hv.z),h2f2(pv4.z));
                fma2(acc,h2f2(hv.w),h2f2(pv4.w));
            }
            float2 fz=unpack2(acc); sc[lane]=fz.x+fz.y;
            if(lane<8){
                int t2=32+lane, j2=t2/10, tt2=t2-10*j2;
                const uint4* hap2=(const uint4*)&g_HA[((size_t)(b*J+j2)*TIN+tt2)*HP];
                const uint4* pj2 =(const uint4*)&fcA[(warp*J+j2)*FCA];
                u64 a2=0ull;
                #pragma unroll 13
                for(int q=0;q<13;q++){
                    uint4 hv=hap2[q], pv4=pj2[q];
                    fma2(a2,h2f2(hv.x),h2f2(pv4.x));
                    fma2(a2,h2f2(hv.y),h2f2(pv4.y));
                    fma2(a2,h2f2(hv.z),h2f2(pv4.z));
                    fma2(a2,h2f2(hv.w),h2f2(pv4.w));
                }
                float2 f2z=unpack2(a2); sc[t2]=f2z.x+f2z.y;
            }
        }
        __syncwarp();
        if(lane<J){
            float mx=-1e30f;
            #pragma unroll
            for(int tt=0;tt<TIN;tt++) mx=fmaxf(mx,sc[lane*10+tt]);
            float s=0.f;
            #pragma unroll
            for(int tt=0;tt<TIN;tt++) s+=__expf(sc[lane*10+tt]-mx);
            float lg=__logf(s)+mx;
            #pragma unroll
            for(int tt=0;tt<TIN;tt++) sc[lane*10+tt]-=lg;
        }
        __syncwarp();
        {   // c = logs . H  (packed f32x2; 52 tasks)
            #pragma unroll
            for(int pass=0;pass<2;pass++){
                int task = pass? 32+lane : lane;
                if(pass && lane>=20) break;
                int j=task/13, q=task-13*j;
                const uint4* hb=(const uint4*)&g_H[((size_t)(b*J+j)*TIN)*HP];
                u64 A0=0ull,A1=0ull,A2=0ull,A3=0ull;
                #pragma unroll
                for(int tt=0;tt<TIN;tt++){
                    u64 lg2=dup2(sc[j*10+tt]);
                    uint4 hv=hb[tt*13+q];
                    fma2(A0,h2f2(hv.x),lg2);
                    fma2(A1,h2f2(hv.y),lg2);
                    fma2(A2,h2f2(hv.z),lg2);
                    fma2(A3,h2f2(hv.w),lg2);
                }
                int r=warp*J+j;
                float2 f0=unpack2(A0),f1=unpack2(A1),f2=unpack2(A2),f3=unpack2(A3);
                __half2 p0=__floats2half2_rn(f0.x,f0.y), p1=__floats2half2_rn(f1.x,f1.y);
                __half2 p2=__floats2half2_rn(f2.x,f2.y), p3=__floats2half2_rn(f3.x,f3.y);
                uint4 pk; pk.x=*(u32*)&p0; pk.y=*(u32*)&p1; pk.z=*(u32*)&p2; pk.w=*(u32*)&p3;
                *(uint4*)&fcA[r*FCA+112+8*q]=pk;
            }
        }
        if(lane<J) toks[warp*J+lane]=target[t*BATCH+b];
        BARWG();
        float nacc[2][2][4]={{{0,0,0,0},{0,0,0,0}},{{0,0,0,0},{0,0,0,0}}};
        dec_passA2(fcA_sm,row0,whh_sm,wb2_sm,wih,bsum2,wbb2,toks,buf1_sm,buf2_sm,buf3_sm,wlocal,lane,nacc);
        BARWG();
        {   // logits
            __half2 mA2=__floats2half2_rn(-60000.f,-60000.f), mB2=mA2;
            #pragma unroll
            for(int j=0;j<J;j++){
                int r=warp*J+j;
                mA2=__hmax2(mA2,*(const __half2*)&buf1[r*104+e0]);
                if(m1) mB2=__hmax2(mB2,*(const __half2*)&buf1[r*104+e1]);
            }
            float2 mA=__half22float2(mA2);
            float2 mB=m1?__half22float2(mB2):make_float2(0.f,0.f);
            float pv[VDIM];
            #pragma unroll
            for(int v=0;v<VDIM;v++){
                const float* vr=&vwf[v*104];
                float p=vr[e0]*mA.x+vr[e0+1]*mA.y;
                if(m1){p=fmaf(vr[e1],mB.x,p); p=fmaf(vr[e1+1],mB.y,p);}
                pv[v]=p;
            }
            #pragma unroll
            for(int off=16;off>=1;off>>=1){
                #pragma unroll
                for(int v=0;v<VDIM;v++) pv[v]+=__shfl_xor_sync(0xffffffffu,pv[v],off);
            }
            int tok=target[t*BATCH+b];
            float mx=-1e30f;
            #pragma unroll
            for(int v=0;v<VDIM;v++){pv[v]+=vbb[v]; mx=fmaxf(mx,pv[v]);}
            float ss=0.f;
            #pragma unroll
            for(int v=0;v<VDIM;v++) ss+=__expf(pv[v]-mx);
            score+=pv[tok]-mx-__logf(ss);
        }
        gru_n_epi_dec(nacc,row0,wih,bin2,bhn2,toks,buf2,buf3,fcA,fcA_sm,wlocal,lane);
        BARWG();
    }
    if(lane==0) out[b]=score;
}

extern "C" void kernel_launch(void* const* d_in, const int* in_sizes, int n_in,
                              void* d_out, int out_size)
{
    cudaFuncSetAttribute(fused_kernel, cudaFuncAttributeMaxDynamicSharedMemorySize, SMEM_BYTES);
    int grid=(BATCH+NWARP-1)/NWARP;
    fused_kernel<<<grid, NTHREADS, SMEM_BYTES>>>(
        (const int*)d_in[0], (const int*)d_in[1],
        (const float*)d_in[2], (const float*)d_in[3], (const float*)d_in[4], (const float*)d_in[5],
        (const float*)d_in[6], (const float*)d_in[7], (const float*)d_in[8], (const float*)d_in[9],
        (const float*)d_in[10], (const float*)d_in[11], (const float*)d_in[12], (const float*)d_in[13],
        (const float*)d_in[14], (float*)d_out);
}